// round 1
// baseline (speedup 1.0000x reference)
#include <cuda_runtime.h>
#include <math.h>

// ---------------------------------------------------------------------------
// SeqGraphRepNetwork on GB300 — packed (no padding) formulation, all fp32.
//
// Pipeline:
//  K1 prep:    v_src = att_W^T a_src, v_dst = att_W^T a_dst; prefix starts[]
//  K2 logits:  per-node p_src/p_dst, per-edge qe (warp dot-products)
//  K3 gcn+ln1: 2-way softmax GCN aggregate -> Hu; LayerNorm -> Qin
//  G  gemms:   q=Qin@Wq^T, k=Hu@Wk^T, v=Hu@Wv^T   (MODE 0)
//  K5 attn:    per (session,head) masked softmax attention -> ctx
//  G  gemm:    out2 = LN2(ctx@Wo^T + bo + Qin)      (MODE 2)
//  G  gemm:    h = relu(out2@W1^T + b1)             (MODE 1)
//  G  gemm:    out3 = h@W2^T + b2 + out2            (MODE 3)
//  K7 pool:    S_u[b] = mean over valid tokens
// ---------------------------------------------------------------------------

#define NMAX   163840      // 1024 * 160 upper bound on packed nodes
#define LMAX   160
#define BMAXS  1024

// -------- device scratch (no allocations allowed in kernel_launch) --------
__device__ float d_vsrc[128];
__device__ float d_vdst[128];
__device__ int   d_starts[BMAXS + 1];
__device__ float d_psrc[NMAX];
__device__ float d_pdst[NMAX];
__device__ float d_qe[NMAX];
__device__ float g_buf0[(size_t)NMAX * 128];  // Hu, later ctx
__device__ float g_buf1[(size_t)NMAX * 128];  // Qin (LN1 output)
__device__ float g_buf2[(size_t)NMAX * 128];  // q proj, later out3
__device__ float g_buf3[(size_t)NMAX * 128];  // k proj, later out2
__device__ float g_buf4[(size_t)NMAX * 128];  // v proj, later ffn hidden

// ---------------------------------------------------------------------------
// K1: v_src/v_dst vectors + session start offsets
// ---------------------------------------------------------------------------
__global__ void prep_kernel(const float* __restrict__ attW,
                            const float* __restrict__ a_src,
                            const float* __restrict__ a_dst,
                            const int*   __restrict__ lengths, int B)
{
    int d = threadIdx.x;
    float vs = 0.f, vd = 0.f;
    #pragma unroll 4
    for (int k = 0; k < 128; ++k) {
        float w = attW[k * 128 + d];
        vs += a_src[k] * w;
        vd += a_dst[k] * w;
    }
    d_vsrc[d] = vs;
    d_vdst[d] = vd;
    if (d == 0) {
        int s = 0;
        for (int b = 0; b < B; ++b) { d_starts[b] = s; s += lengths[b]; }
        d_starts[B] = s;
    }
}

// ---------------------------------------------------------------------------
// K2: per-node p_src/p_dst and per-edge qe  (one warp per item)
// ---------------------------------------------------------------------------
__global__ void logits_kernel(const float* __restrict__ POI,
                              const float* __restrict__ dde,
                              const int*   __restrict__ sess_idx,
                              const int*   __restrict__ edge_dist,
                              int N, int E)
{
    int gwarp = (blockIdx.x * blockDim.x + threadIdx.x) >> 5;
    int lane  = threadIdx.x & 31;
    if (gwarp < N) {
        const float4* row = (const float4*)(POI + (size_t)sess_idx[gwarp] * 128);
        float4 x = row[lane];
        float4 a = ((const float4*)d_vsrc)[lane];
        float4 b = ((const float4*)d_vdst)[lane];
        float p1 = x.x*a.x + x.y*a.y + x.z*a.z + x.w*a.w;
        float p2 = x.x*b.x + x.y*b.y + x.z*b.z + x.w*b.w;
        #pragma unroll
        for (int o = 16; o; o >>= 1) {
            p1 += __shfl_xor_sync(0xffffffffu, p1, o);
            p2 += __shfl_xor_sync(0xffffffffu, p2, o);
        }
        if (lane == 0) { d_psrc[gwarp] = p1; d_pdst[gwarp] = p2; }
    } else if (gwarp < N + E) {
        int e = gwarp - N;
        const float4* row = (const float4*)(dde + (size_t)edge_dist[e] * 128);
        float4 x = row[lane];
        float4 a = ((const float4*)d_vsrc)[lane];
        float q = x.x*a.x + x.y*a.y + x.z*a.z + x.w*a.w;
        #pragma unroll
        for (int o = 16; o; o >>= 1) q += __shfl_xor_sync(0xffffffffu, q, o);
        if (lane == 0) d_qe[e] = q;
    }
}

// ---------------------------------------------------------------------------
// K3: GCN 2-message softmax aggregation + LayerNorm1.  Block = one node.
// ---------------------------------------------------------------------------
__global__ void gcn_ln1_kernel(const float* __restrict__ POI,
                               const int*   __restrict__ sess_idx,
                               const int*   __restrict__ batch_ids,
                               const int*   __restrict__ node_pos,
                               const int*   __restrict__ lengths,
                               const float* __restrict__ g1,
                               const float* __restrict__ b1)
{
    int n = blockIdx.x;
    int d = threadIdx.x;
    int b = batch_ids[n];
    int p = node_pos[n];
    int l = lengths[b];
    bool h1 = (p > 0);          // fwd message from n-1
    bool h2 = (p < l - 1);      // bwd message from n+1
    float L1 = h1 ? (d_psrc[n] + d_qe[n - 1 - b]) : -1e30f;
    float L2 = h2 ? d_pdst[n] : -1e30f;
    float m  = fmaxf(L1, L2);
    float e1 = h1 ? expf(L1 - m) : 0.f;
    float e2 = h2 ? expf(L2 - m) : 0.f;
    float inv = 1.f / (e1 + e2 + 1e-16f);
    float a1 = e1 * inv, a2 = e2 * inv;
    float hu = 0.f;
    if (h1) hu += a1 * POI[(size_t)sess_idx[n - 1] * 128 + d];
    if (h2) hu += a2 * POI[(size_t)sess_idx[n + 1] * 128 + d];
    g_buf0[(size_t)n * 128 + d] = hu;

    // LayerNorm over the 128 block threads
    __shared__ float red[8];
    float s1 = hu, s2 = hu * hu;
    #pragma unroll
    for (int o = 16; o; o >>= 1) {
        s1 += __shfl_xor_sync(0xffffffffu, s1, o);
        s2 += __shfl_xor_sync(0xffffffffu, s2, o);
    }
    int w = d >> 5;
    if ((d & 31) == 0) { red[w] = s1; red[4 + w] = s2; }
    __syncthreads();
    s1 = red[0] + red[1] + red[2] + red[3];
    s2 = red[4] + red[5] + red[6] + red[7];
    float mu   = s1 * (1.f / 128.f);
    float var  = fmaxf(s2 * (1.f / 128.f) - mu * mu, 0.f);
    float rstd = rsqrtf(var + 1e-8f);
    g_buf1[(size_t)n * 128 + d] = (hu - mu) * rstd * g1[d] + b1[d];
}

// ---------------------------------------------------------------------------
// Generic [N,128]x[128,128]^T GEMM with fused epilogues.
//  MODE 0: +bias            MODE 1: +bias, relu
//  MODE 2: +bias +res, LN   MODE 3: +bias +res
// Block: 256 threads, 64 rows x full 128 cols. W held transposed in smem.
// ---------------------------------------------------------------------------
template<int MODE>
__global__ void __launch_bounds__(256)
gemm128_kernel(const float* __restrict__ A, const float* __restrict__ W,
               const float* __restrict__ bias, const float* __restrict__ res,
               const float* __restrict__ lng, const float* __restrict__ lnb,
               float* __restrict__ out, int nrows)
{
    extern __shared__ float sm[];
    float* Ws = sm;               // [128][128], Ws[c*128 + j] = W[j][c]
    float* As = sm + 128 * 128;   // [64][128]
    int tid  = threadIdx.x;
    int row0 = blockIdx.x * 64;

    for (int i = tid; i < 128 * 32; i += 256) {
        int j  = i >> 5;
        int c  = (i & 31) << 2;
        float4 w = ((const float4*)W)[i];
        Ws[(c + 0) * 128 + j] = w.x;
        Ws[(c + 1) * 128 + j] = w.y;
        Ws[(c + 2) * 128 + j] = w.z;
        Ws[(c + 3) * 128 + j] = w.w;
    }
    for (int i = tid; i < 64 * 32; i += 256) {
        int r = i >> 5, c4 = i & 31;
        int gr = row0 + r;
        float4 a = (gr < nrows) ? ((const float4*)(A + (size_t)gr * 128))[c4]
                                : make_float4(0.f, 0.f, 0.f, 0.f);
        ((float4*)(As + r * 128))[c4] = a;
    }
    __syncthreads();

    const int tx = tid & 31;   // 4 output cols: tx*4..tx*4+3
    const int ty = tid >> 5;   // warp id, 8 rows: ty*8..ty*8+7
    float acc[8][4];
    #pragma unroll
    for (int r = 0; r < 8; ++r)
        acc[r][0] = acc[r][1] = acc[r][2] = acc[r][3] = 0.f;

    const float* Arow = As + ty * 8 * 128;
    #pragma unroll 4
    for (int k = 0; k < 128; ++k) {
        float4 bv = ((const float4*)(Ws + k * 128))[tx];
        #pragma unroll
        for (int r = 0; r < 8; ++r) {
            float a = Arow[r * 128 + k];
            acc[r][0] += a * bv.x;
            acc[r][1] += a * bv.y;
            acc[r][2] += a * bv.z;
            acc[r][3] += a * bv.w;
        }
    }

    float4 bb = ((const float4*)bias)[tx];
    float4 gg = make_float4(0,0,0,0), be = make_float4(0,0,0,0);
    if (MODE == 2) { gg = ((const float4*)lng)[tx]; be = ((const float4*)lnb)[tx]; }

    #pragma unroll
    for (int r = 0; r < 8; ++r) {
        int gr = row0 + ty * 8 + r;
        if (gr < nrows) {
            float v0 = acc[r][0] + bb.x;
            float v1 = acc[r][1] + bb.y;
            float v2 = acc[r][2] + bb.z;
            float v3 = acc[r][3] + bb.w;
            if (MODE == 1) {
                v0 = fmaxf(v0, 0.f); v1 = fmaxf(v1, 0.f);
                v2 = fmaxf(v2, 0.f); v3 = fmaxf(v3, 0.f);
            }
            if (MODE == 2 || MODE == 3) {
                float4 rv = ((const float4*)(res + (size_t)gr * 128))[tx];
                v0 += rv.x; v1 += rv.y; v2 += rv.z; v3 += rv.w;
            }
            if (MODE == 2) {
                float s1 = v0 + v1 + v2 + v3;
                float s2 = v0*v0 + v1*v1 + v2*v2 + v3*v3;
                #pragma unroll
                for (int o = 16; o; o >>= 1) {
                    s1 += __shfl_xor_sync(0xffffffffu, s1, o);
                    s2 += __shfl_xor_sync(0xffffffffu, s2, o);
                }
                float mu   = s1 * (1.f / 128.f);
                float var  = fmaxf(s2 * (1.f / 128.f) - mu * mu, 0.f);
                float rstd = rsqrtf(var + 1e-8f);
                v0 = (v0 - mu) * rstd * gg.x + be.x;
                v1 = (v1 - mu) * rstd * gg.y + be.y;
                v2 = (v2 - mu) * rstd * gg.z + be.z;
                v3 = (v3 - mu) * rstd * gg.w + be.w;
            }
            ((float4*)(out + (size_t)gr * 128))[tx] = make_float4(v0, v1, v2, v3);
        }
    }
}

// ---------------------------------------------------------------------------
// K5: attention per (session, head). 8 warps, warp-per-query.
// smem: q[L][32], kT[32][L], v[L][32], w[8][L] — all conflict-free layouts.
// ---------------------------------------------------------------------------
__global__ void __launch_bounds__(256)
attn_kernel(const float* __restrict__ qp, const float* __restrict__ kp,
            const float* __restrict__ vp, float* __restrict__ ctx,
            const int* __restrict__ lengths)
{
    int b = blockIdx.x;
    int h = blockIdx.y;
    int n0 = d_starts[b];
    int l  = lengths[b];
    extern __shared__ float sm[];
    float* sq  = sm;                    // [LMAX][32]
    float* skT = sm + LMAX * 32;        // [32][LMAX]
    float* sv  = skT + 32 * LMAX;       // [LMAX][32]
    float* sw  = sv + LMAX * 32;        // [8][LMAX]
    int tid = threadIdx.x;
    int hc  = h * 32;

    for (int i = tid; i < l * 32; i += 256) {
        int s = i >> 5, c = i & 31;
        size_t gi = (size_t)(n0 + s) * 128 + hc + c;
        float kvl = kp[gi];
        sq[i] = qp[gi];
        skT[c * LMAX + s] = kvl;
        sv[i] = vp[gi];
    }
    __syncthreads();

    int wid  = tid >> 5;
    int lane = tid & 31;
    const float scale = 0.17677669529663687f;   // 1/sqrt(32)
    int ng = (l + 31) >> 5;

    for (int t = wid; t < l; t += 8) {
        float qreg[32];
        #pragma unroll
        for (int c = 0; c < 32; ++c) qreg[c] = sq[t * 32 + c];

        float sc[5];
        float m = -1e30f;
        for (int g = 0; g < ng; ++g) {
            float a = 0.f;
            const float* kcol = skT + (g << 5) + lane;
            #pragma unroll
            for (int c = 0; c < 32; ++c) a += qreg[c] * kcol[c * LMAX];
            a *= scale;
            if (((g << 5) + lane) >= l) a = -1e30f;
            sc[g] = a;
            m = fmaxf(m, a);
        }
        #pragma unroll
        for (int o = 16; o; o >>= 1)
            m = fmaxf(m, __shfl_xor_sync(0xffffffffu, m, o));

        float dsum = 0.f;
        for (int g = 0; g < ng; ++g) {
            int s = (g << 5) + lane;
            float e = (s < l) ? __expf(sc[g] - m) : 0.f;
            sc[g] = e;
            dsum += e;
        }
        #pragma unroll
        for (int o = 16; o; o >>= 1)
            dsum += __shfl_xor_sync(0xffffffffu, dsum, o);

        for (int g = 0; g < ng; ++g) {
            int s = (g << 5) + lane;
            if (s < l) sw[wid * LMAX + s] = sc[g];
        }
        __syncwarp();

        float inv = 1.f / dsum;
        float cv = 0.f;
        const float* wrow = sw + wid * LMAX;
        #pragma unroll 4
        for (int s = 0; s < l; ++s) cv += wrow[s] * sv[(s << 5) + lane];
        ctx[(size_t)(n0 + t) * 128 + hc + lane] = cv * inv;
        __syncwarp();   // protect sw before next query overwrites it
    }
}

// ---------------------------------------------------------------------------
// K7: masked mean pool -> S_u[b][d]
// ---------------------------------------------------------------------------
__global__ void pool_kernel(const float* __restrict__ x,
                            const int* __restrict__ lengths,
                            float* __restrict__ out)
{
    int b = blockIdx.x, d = threadIdx.x;
    int n0 = d_starts[b], l = lengths[b];
    float s = 0.f;
    #pragma unroll 4
    for (int p = 0; p < l; ++p) s += x[(size_t)(n0 + p) * 128 + d];
    out[b * 128 + d] = s / (float)l;
}

// ---------------------------------------------------------------------------
extern "C" void kernel_launch(void* const* d_in, const int* in_sizes, int n_in,
                              void* d_out, int out_size)
{
    const float* POI    = (const float*)d_in[0];
    const float* dde    = (const float*)d_in[1];
    const float* attW   = (const float*)d_in[2];
    const float* a_src  = (const float*)d_in[3];
    const float* a_dst  = (const float*)d_in[4];
    const float* in_w   = (const float*)d_in[5];
    const float* in_b   = (const float*)d_in[6];
    const float* out_w  = (const float*)d_in[7];
    const float* out_b  = (const float*)d_in[8];
    const float* ln1g   = (const float*)d_in[9];
    const float* ln1b   = (const float*)d_in[10];
    const float* ln2g   = (const float*)d_in[11];
    const float* ln2b   = (const float*)d_in[12];
    const float* fw1    = (const float*)d_in[13];
    const float* fb1    = (const float*)d_in[14];
    const float* fw2    = (const float*)d_in[15];
    const float* fb2    = (const float*)d_in[16];
    const int* sess_idx  = (const int*)d_in[17];
    const int* edge_dist = (const int*)d_in[18];
    // d_in[19] = edge_index (unused; structure derived analytically)
    const int* batch_ids = (const int*)d_in[20];
    const int* node_pos  = (const int*)d_in[21];
    const int* lengths   = (const int*)d_in[22];
    int N = in_sizes[17];
    int E = in_sizes[18];
    int B = in_sizes[22];
    float* outp = (float*)d_out;

    float *b0, *b1, *b2, *b3, *b4;
    cudaGetSymbolAddress((void**)&b0, g_buf0);
    cudaGetSymbolAddress((void**)&b1, g_buf1);
    cudaGetSymbolAddress((void**)&b2, g_buf2);
    cudaGetSymbolAddress((void**)&b3, g_buf3);
    cudaGetSymbolAddress((void**)&b4, g_buf4);

    const int gemm_smem = (128 * 128 + 64 * 128) * (int)sizeof(float);   // 96 KB
    const int attn_smem = (LMAX * 32 * 3 + 8 * LMAX) * (int)sizeof(float); // 65 KB
    cudaFuncSetAttribute(gemm128_kernel<0>, cudaFuncAttributeMaxDynamicSharedMemorySize, gemm_smem);
    cudaFuncSetAttribute(gemm128_kernel<1>, cudaFuncAttributeMaxDynamicSharedMemorySize, gemm_smem);
    cudaFuncSetAttribute(gemm128_kernel<2>, cudaFuncAttributeMaxDynamicSharedMemorySize, gemm_smem);
    cudaFuncSetAttribute(gemm128_kernel<3>, cudaFuncAttributeMaxDynamicSharedMemorySize, gemm_smem);
    cudaFuncSetAttribute(attn_kernel, cudaFuncAttributeMaxDynamicSharedMemorySize, attn_smem);

    prep_kernel<<<1, 128>>>(attW, a_src, a_dst, lengths, B);

    int items = N + E;
    logits_kernel<<<(items + 7) / 8, 256>>>(POI, dde, sess_idx, edge_dist, N, E);

    gcn_ln1_kernel<<<N, 128>>>(POI, sess_idx, batch_ids, node_pos, lengths, ln1g, ln1b);

    int gblocks = (N + 63) / 64;
    // q = Qin @ Wq^T ; k = Hu @ Wk^T ; v = Hu @ Wv^T
    gemm128_kernel<0><<<gblocks, 256, gemm_smem>>>(b1, in_w,             in_b,       nullptr, nullptr, nullptr, b2, N);
    gemm128_kernel<0><<<gblocks, 256, gemm_smem>>>(b0, in_w + 128 * 128, in_b + 128, nullptr, nullptr, nullptr, b3, N);
    gemm128_kernel<0><<<gblocks, 256, gemm_smem>>>(b0, in_w + 256 * 128, in_b + 256, nullptr, nullptr, nullptr, b4, N);

    dim3 ag(B, 4);
    attn_kernel<<<ag, 256, attn_smem>>>(b2, b3, b4, b0, lengths);

    // out2 = LN2(ctx@Wo^T + bo + Qin)
    gemm128_kernel<2><<<gblocks, 256, gemm_smem>>>(b0, out_w, out_b, b1, ln2g, ln2b, b3, N);
    // h = relu(out2@W1^T + b1)
    gemm128_kernel<1><<<gblocks, 256, gemm_smem>>>(b3, fw1, fb1, nullptr, nullptr, nullptr, b4, N);
    // out3 = h@W2^T + b2 + out2
    gemm128_kernel<3><<<gblocks, 256, gemm_smem>>>(b4, fw2, fb2, b3, nullptr, nullptr, b2, N);

    pool_kernel<<<B, 128>>>(b2, lengths, outp);
}

// round 3
// speedup vs baseline: 1.3561x; 1.3561x over previous
#include <cuda_runtime.h>
#include <math.h>

// ---------------------------------------------------------------------------
// SeqGraphRepNetwork on GB300 — packed formulation, fp32.
// R2: 8x8 register-tiled GEMM (FMA-bound), 8-query-per-warp attention.
// ---------------------------------------------------------------------------

#define NMAX   163840
#define LMAX   160
#define SKP    161          // padded skT row stride (160 % 32 == 0 -> conflicts)
#define BMAXS  1024

__device__ float d_vsrc[128];
__device__ float d_vdst[128];
__device__ int   d_starts[BMAXS + 1];
__device__ float d_psrc[NMAX];
__device__ float d_pdst[NMAX];
__device__ float d_qe[NMAX];
__device__ float d_wt[6 * 128 * 128];        // transposed weights [k][c]
__device__ float g_buf0[(size_t)NMAX * 128]; // Hu, later ctx
__device__ float g_buf1[(size_t)NMAX * 128]; // Qin (LN1 output)
__device__ float g_buf2[(size_t)NMAX * 128]; // q proj, later out3
__device__ float g_buf3[(size_t)NMAX * 128]; // k proj, later out2
__device__ float g_buf4[(size_t)NMAX * 128]; // v proj, later ffn hidden

// ---------------------------------------------------------------------------
// K0: transpose the six 128x128 weight matrices -> d_wt[m][k][c] = W_m[c][k]
// ---------------------------------------------------------------------------
__global__ void wtrans_kernel(const float* __restrict__ in_w,
                              const float* __restrict__ out_w,
                              const float* __restrict__ fw1,
                              const float* __restrict__ fw2)
{
    int m = blockIdx.x;
    const float* src = (m < 3) ? (in_w + m * 16384)
                     : (m == 3 ? out_w : (m == 4 ? fw1 : fw2));
    float* dst = d_wt + (size_t)m * 16384;
    __shared__ float t[32][33];
    int x = threadIdx.x & 31;      // 32
    int y0 = threadIdx.x >> 5;     // 8
    for (int bi = 0; bi < 4; ++bi)
        for (int bj = 0; bj < 4; ++bj) {
            #pragma unroll
            for (int p = 0; p < 4; ++p) {
                int y = y0 + p * 8;
                t[y][x] = src[(bi * 32 + y) * 128 + bj * 32 + x];
            }
            __syncthreads();
            #pragma unroll
            for (int p = 0; p < 4; ++p) {
                int y = y0 + p * 8;
                dst[(bj * 32 + y) * 128 + bi * 32 + x] = t[x][y];
            }
            __syncthreads();
        }
}

// ---------------------------------------------------------------------------
// K1: v_src/v_dst vectors + session start offsets
// ---------------------------------------------------------------------------
__global__ void prep_kernel(const float* __restrict__ attW,
                            const float* __restrict__ a_src,
                            const float* __restrict__ a_dst,
                            const int*   __restrict__ lengths, int B)
{
    int d = threadIdx.x;
    float vs = 0.f, vd = 0.f;
    #pragma unroll 4
    for (int k = 0; k < 128; ++k) {
        float w = attW[k * 128 + d];
        vs += a_src[k] * w;
        vd += a_dst[k] * w;
    }
    d_vsrc[d] = vs;
    d_vdst[d] = vd;
    if (d == 0) {
        int s = 0;
        for (int b = 0; b < B; ++b) { d_starts[b] = s; s += lengths[b]; }
        d_starts[B] = s;
    }
}

// ---------------------------------------------------------------------------
// K2: per-node p_src/p_dst and per-edge qe  (one warp per item)
// ---------------------------------------------------------------------------
__global__ void logits_kernel(const float* __restrict__ POI,
                              const float* __restrict__ dde,
                              const int*   __restrict__ sess_idx,
                              const int*   __restrict__ edge_dist,
                              int N, int E)
{
    int gwarp = (blockIdx.x * blockDim.x + threadIdx.x) >> 5;
    int lane  = threadIdx.x & 31;
    if (gwarp < N) {
        const float4* row = (const float4*)(POI + (size_t)sess_idx[gwarp] * 128);
        float4 x = row[lane];
        float4 a = ((const float4*)d_vsrc)[lane];
        float4 b = ((const float4*)d_vdst)[lane];
        float p1 = x.x*a.x + x.y*a.y + x.z*a.z + x.w*a.w;
        float p2 = x.x*b.x + x.y*b.y + x.z*b.z + x.w*b.w;
        #pragma unroll
        for (int o = 16; o; o >>= 1) {
            p1 += __shfl_xor_sync(0xffffffffu, p1, o);
            p2 += __shfl_xor_sync(0xffffffffu, p2, o);
        }
        if (lane == 0) { d_psrc[gwarp] = p1; d_pdst[gwarp] = p2; }
    } else if (gwarp < N + E) {
        int e = gwarp - N;
        const float4* row = (const float4*)(dde + (size_t)edge_dist[e] * 128);
        float4 x = row[lane];
        float4 a = ((const float4*)d_vsrc)[lane];
        float q = x.x*a.x + x.y*a.y + x.z*a.z + x.w*a.w;
        #pragma unroll
        for (int o = 16; o; o >>= 1) q += __shfl_xor_sync(0xffffffffu, q, o);
        if (lane == 0) d_qe[e] = q;
    }
}

// ---------------------------------------------------------------------------
// K3: GCN 2-message softmax aggregation + LayerNorm1.  Block = one node.
// ---------------------------------------------------------------------------
__global__ void gcn_ln1_kernel(const float* __restrict__ POI,
                               const int*   __restrict__ sess_idx,
                               const int*   __restrict__ batch_ids,
                               const int*   __restrict__ node_pos,
                               const int*   __restrict__ lengths,
                               const float* __restrict__ g1,
                               const float* __restrict__ b1)
{
    int n = blockIdx.x;
    int d = threadIdx.x;
    int b = batch_ids[n];
    int p = node_pos[n];
    int l = lengths[b];
    bool h1 = (p > 0);
    bool h2 = (p < l - 1);
    float L1 = h1 ? (d_psrc[n] + d_qe[n - 1 - b]) : -1e30f;
    float L2 = h2 ? d_pdst[n] : -1e30f;
    float m  = fmaxf(L1, L2);
    float e1 = h1 ? expf(L1 - m) : 0.f;
    float e2 = h2 ? expf(L2 - m) : 0.f;
    float inv = 1.f / (e1 + e2 + 1e-16f);
    float a1 = e1 * inv, a2 = e2 * inv;
    float hu = 0.f;
    if (h1) hu += a1 * POI[(size_t)sess_idx[n - 1] * 128 + d];
    if (h2) hu += a2 * POI[(size_t)sess_idx[n + 1] * 128 + d];
    g_buf0[(size_t)n * 128 + d] = hu;

    __shared__ float red[8];
    float s1 = hu, s2 = hu * hu;
    #pragma unroll
    for (int o = 16; o; o >>= 1) {
        s1 += __shfl_xor_sync(0xffffffffu, s1, o);
        s2 += __shfl_xor_sync(0xffffffffu, s2, o);
    }
    int w = d >> 5;
    if ((d & 31) == 0) { red[w] = s1; red[4 + w] = s2; }
    __syncthreads();
    s1 = red[0] + red[1] + red[2] + red[3];
    s2 = red[4] + red[5] + red[6] + red[7];
    float mu   = s1 * (1.f / 128.f);
    float var  = fmaxf(s2 * (1.f / 128.f) - mu * mu, 0.f);
    float rstd = rsqrtf(var + 1e-8f);
    g_buf1[(size_t)n * 128 + d] = (hu - mu) * rstd * g1[d] + b1[d];
}

// ---------------------------------------------------------------------------
// GEMM: out[r][c] = sum_k A[r][k] * Wt[k][c]  (+ fused epilogues)
//  MODE 0: +bias   MODE 1: +bias,relu   MODE 2: +bias+res,LN   MODE 3: +bias+res
// 256 threads, 128x128 tile, 8x8 per thread. Wt is pre-transposed.
// ---------------------------------------------------------------------------
template<int MODE>
__global__ void __launch_bounds__(256, 1)
gemm128_kernel(const float* __restrict__ A, const float* __restrict__ Wt,
               const float* __restrict__ bias, const float* __restrict__ res,
               const float* __restrict__ lng, const float* __restrict__ lnb,
               float* __restrict__ out, int nrows)
{
    extern __shared__ float sm[];
    float* As = sm;               // [128][128] natural (row, k)
    float* Ws = sm + 128 * 128;   // [128][128] (k, c)
    int tid  = threadIdx.x;
    int row0 = blockIdx.x * 128;

    const float4* A4  = (const float4*)A;
    const float4* Wt4 = (const float4*)Wt;
    for (int i = tid; i < 4096; i += 256) {
        int r = i >> 5;
        int gr = row0 + r;
        ((float4*)As)[i] = (gr < nrows) ? A4[(size_t)gr * 32 + (i & 31)]
                                        : make_float4(0.f, 0.f, 0.f, 0.f);
        ((float4*)Ws)[i] = Wt4[i];
    }
    __syncthreads();

    int tx = tid & 15;     // col group: cols tx*8 .. tx*8+7
    int ty = tid >> 4;     // row group: rows ty*8 .. ty*8+7
    float acc[8][8];
    #pragma unroll
    for (int r = 0; r < 8; ++r)
        #pragma unroll
        for (int c = 0; c < 8; ++c) acc[r][c] = 0.f;

    const float* Ap = As + ty * 8 * 128;
    const float* Wp = Ws + tx * 8;

    #pragma unroll 8
    for (int k = 0; k < 128; ++k) {
        float a[8];
        #pragma unroll
        for (int j = 0; j < 8; ++j) a[j] = Ap[j * 128 + k];
        float4 w0 = *(const float4*)(Wp + k * 128);
        float4 w1 = *(const float4*)(Wp + k * 128 + 4);
        #pragma unroll
        for (int r = 0; r < 8; ++r) {
            acc[r][0] += a[r] * w0.x;
            acc[r][1] += a[r] * w0.y;
            acc[r][2] += a[r] * w0.z;
            acc[r][3] += a[r] * w0.w;
            acc[r][4] += a[r] * w1.x;
            acc[r][5] += a[r] * w1.y;
            acc[r][6] += a[r] * w1.z;
            acc[r][7] += a[r] * w1.w;
        }
    }

    float4 bb0 = ((const float4*)bias)[tx * 2];
    float4 bb1 = ((const float4*)bias)[tx * 2 + 1];
    float4 gg0 = make_float4(0,0,0,0), gg1 = gg0, be0 = gg0, be1 = gg0;
    if (MODE == 2) {
        gg0 = ((const float4*)lng)[tx * 2]; gg1 = ((const float4*)lng)[tx * 2 + 1];
        be0 = ((const float4*)lnb)[tx * 2]; be1 = ((const float4*)lnb)[tx * 2 + 1];
    }

    #pragma unroll
    for (int r = 0; r < 8; ++r) {
        int gr = row0 + ty * 8 + r;
        if (gr >= nrows) continue;
        float v[8];
        v[0] = acc[r][0] + bb0.x; v[1] = acc[r][1] + bb0.y;
        v[2] = acc[r][2] + bb0.z; v[3] = acc[r][3] + bb0.w;
        v[4] = acc[r][4] + bb1.x; v[5] = acc[r][5] + bb1.y;
        v[6] = acc[r][6] + bb1.z; v[7] = acc[r][7] + bb1.w;
        if (MODE == 1) {
            #pragma unroll
            for (int c = 0; c < 8; ++c) v[c] = fmaxf(v[c], 0.f);
        }
        if (MODE == 2 || MODE == 3) {
            float4 r0 = ((const float4*)(res + (size_t)gr * 128))[tx * 2];
            float4 r1 = ((const float4*)(res + (size_t)gr * 128))[tx * 2 + 1];
            v[0] += r0.x; v[1] += r0.y; v[2] += r0.z; v[3] += r0.w;
            v[4] += r1.x; v[5] += r1.y; v[6] += r1.z; v[7] += r1.w;
        }
        if (MODE == 2) {
            float s1 = 0.f, s2 = 0.f;
            #pragma unroll
            for (int c = 0; c < 8; ++c) { s1 += v[c]; s2 += v[c] * v[c]; }
            #pragma unroll
            for (int o = 8; o; o >>= 1) {
                s1 += __shfl_xor_sync(0xffffffffu, s1, o, 16);
                s2 += __shfl_xor_sync(0xffffffffu, s2, o, 16);
            }
            float mu   = s1 * (1.f / 128.f);
            float var  = fmaxf(s2 * (1.f / 128.f) - mu * mu, 0.f);
            float rstd = rsqrtf(var + 1e-8f);
            v[0] = (v[0]-mu)*rstd*gg0.x + be0.x; v[1] = (v[1]-mu)*rstd*gg0.y + be0.y;
            v[2] = (v[2]-mu)*rstd*gg0.z + be0.z; v[3] = (v[3]-mu)*rstd*gg0.w + be0.w;
            v[4] = (v[4]-mu)*rstd*gg1.x + be1.x; v[5] = (v[5]-mu)*rstd*gg1.y + be1.y;
            v[6] = (v[6]-mu)*rstd*gg1.z + be1.z; v[7] = (v[7]-mu)*rstd*gg1.w + be1.w;
        }
        float4* o4 = (float4*)(out + (size_t)gr * 128);
        o4[tx * 2]     = make_float4(v[0], v[1], v[2], v[3]);
        o4[tx * 2 + 1] = make_float4(v[4], v[5], v[6], v[7]);
    }
}

// ---------------------------------------------------------------------------
// K5: attention per (session, head). 8 warps; each warp handles 8 queries at
// a time, so k columns and v rows are read from smem once per 8 queries.
// Probabilities stay in registers; ctx uses shfl broadcast (no smem w-pass).
// ---------------------------------------------------------------------------
__global__ void __launch_bounds__(256)
attn_kernel(const float* __restrict__ qp, const float* __restrict__ kp,
            const float* __restrict__ vp, float* __restrict__ ctx,
            const int* __restrict__ lengths)
{
    int b = blockIdx.x;
    int h = blockIdx.y;
    int n0 = d_starts[b];
    int l  = lengths[b];
    extern __shared__ float sm[];
    float* sq  = sm;                 // [LMAX][32]
    float* skT = sm + LMAX * 32;     // [32][SKP]
    float* sv  = skT + 32 * SKP;     // [LMAX][32]
    int tid = threadIdx.x;
    int hc  = h * 32;

    for (int i = tid; i < l * 32; i += 256) {
        int s = i >> 5, c = i & 31;
        size_t gi = (size_t)(n0 + s) * 128 + hc + c;
        sq[i] = qp[gi];
        skT[c * SKP + s] = kp[gi];
        sv[i] = vp[gi];
    }
    int nchunk = (l + 7) >> 3;
    for (int i = l * 32 + tid; i < nchunk * 256; i += 256) sq[i] = 0.f;
    __syncthreads();

    int wid  = tid >> 5;
    int lane = tid & 31;
    const float scale = 0.17677669529663687f;   // 1/sqrt(32)
    int ng = (l + 31) >> 5;

    for (int ch = wid; ch < nchunk; ch += 8) {
        int t0 = ch * 8;
        float acc[8][5];
        #pragma unroll
        for (int j = 0; j < 8; ++j)
            #pragma unroll
            for (int g = 0; g < 5; ++g) acc[j][g] = 0.f;

        for (int c = 0; c < 32; ++c) {
            float kx[5];
            #pragma unroll
            for (int g = 0; g < 5; ++g)
                kx[g] = (g < ng) ? skT[c * SKP + (g << 5) + lane] : 0.f;
            #pragma unroll
            for (int j = 0; j < 8; ++j) {
                float qv = sq[(t0 + j) * 32 + c];
                #pragma unroll
                for (int g = 0; g < 5; ++g) acc[j][g] += qv * kx[g];
            }
        }

        float inv[8];
        #pragma unroll
        for (int j = 0; j < 8; ++j) {
            float m = -1e30f;
            #pragma unroll
            for (int g = 0; g < 5; ++g) {
                int s = (g << 5) + lane;
                float a = (g < ng && s < l) ? acc[j][g] * scale : -1e30f;
                acc[j][g] = a;
                m = fmaxf(m, a);
            }
            #pragma unroll
            for (int o = 16; o; o >>= 1)
                m = fmaxf(m, __shfl_xor_sync(0xffffffffu, m, o));
            float dsum = 0.f;
            #pragma unroll
            for (int g = 0; g < 5; ++g) {
                int s = (g << 5) + lane;
                float e = (g < ng && s < l) ? __expf(acc[j][g] - m) : 0.f;
                acc[j][g] = e;
                dsum += e;
            }
            #pragma unroll
            for (int o = 16; o; o >>= 1)
                dsum += __shfl_xor_sync(0xffffffffu, dsum, o);
            inv[j] = 1.f / dsum;
        }

        float cv[8];
        #pragma unroll
        for (int j = 0; j < 8; ++j) cv[j] = 0.f;
        for (int g = 0; g < ng; ++g) {
            int smax = l - (g << 5);
            if (smax > 32) smax = 32;
            for (int sl = 0; sl < smax; ++sl) {
                float vx = sv[(((g << 5) + sl) << 5) + lane];
                #pragma unroll
                for (int j = 0; j < 8; ++j)
                    cv[j] += __shfl_sync(0xffffffffu, acc[j][g], sl) * vx;
            }
        }
        #pragma unroll
        for (int j = 0; j < 8; ++j)
            if (t0 + j < l)
                ctx[(size_t)(n0 + t0 + j) * 128 + hc + lane] = cv[j] * inv[j];
    }
}

// ---------------------------------------------------------------------------
// K7: masked mean pool -> S_u[b][d]
// ---------------------------------------------------------------------------
__global__ void pool_kernel(const float* __restrict__ x,
                            const int* __restrict__ lengths,
                            float* __restrict__ out)
{
    int b = blockIdx.x, d = threadIdx.x;
    int n0 = d_starts[b], l = lengths[b];
    float s = 0.f;
    #pragma unroll 4
    for (int p = 0; p < l; ++p) s += x[(size_t)(n0 + p) * 128 + d];
    out[b * 128 + d] = s / (float)l;
}

// ---------------------------------------------------------------------------
extern "C" void kernel_launch(void* const* d_in, const int* in_sizes, int n_in,
                              void* d_out, int out_size)
{
    const float* POI    = (const float*)d_in[0];
    const float* dde    = (const float*)d_in[1];
    const float* attW   = (const float*)d_in[2];
    const float* a_src  = (const float*)d_in[3];
    const float* a_dst  = (const float*)d_in[4];
    const float* in_w   = (const float*)d_in[5];
    const float* in_b   = (const float*)d_in[6];
    const float* out_w  = (const float*)d_in[7];
    const float* out_b  = (const float*)d_in[8];
    const float* ln1g   = (const float*)d_in[9];
    const float* ln1b   = (const float*)d_in[10];
    const float* ln2g   = (const float*)d_in[11];
    const float* ln2b   = (const float*)d_in[12];
    const float* fw1    = (const float*)d_in[13];
    const float* fb1    = (const float*)d_in[14];
    const float* fw2    = (const float*)d_in[15];
    const float* fb2    = (const float*)d_in[16];
    const int* sess_idx  = (const int*)d_in[17];
    const int* edge_dist = (const int*)d_in[18];
    const int* batch_ids = (const int*)d_in[20];
    const int* node_pos  = (const int*)d_in[21];
    const int* lengths   = (const int*)d_in[22];
    int N = in_sizes[17];
    int E = in_sizes[18];
    int B = in_sizes[22];
    float* outp = (float*)d_out;

    float *b0, *b1, *b2, *b3, *b4, *wt;
    cudaGetSymbolAddress((void**)&b0, g_buf0);
    cudaGetSymbolAddress((void**)&b1, g_buf1);
    cudaGetSymbolAddress((void**)&b2, g_buf2);
    cudaGetSymbolAddress((void**)&b3, g_buf3);
    cudaGetSymbolAddress((void**)&b4, g_buf4);
    cudaGetSymbolAddress((void**)&wt, d_wt);

    const int gemm_smem = 2 * 128 * 128 * (int)sizeof(float);               // 128 KB
    const int attn_smem = (LMAX * 32 * 2 + 32 * SKP) * (int)sizeof(float);  // ~61 KB
    cudaFuncSetAttribute(gemm128_kernel<0>, cudaFuncAttributeMaxDynamicSharedMemorySize, gemm_smem);
    cudaFuncSetAttribute(gemm128_kernel<1>, cudaFuncAttributeMaxDynamicSharedMemorySize, gemm_smem);
    cudaFuncSetAttribute(gemm128_kernel<2>, cudaFuncAttributeMaxDynamicSharedMemorySize, gemm_smem);
    cudaFuncSetAttribute(gemm128_kernel<3>, cudaFuncAttributeMaxDynamicSharedMemorySize, gemm_smem);
    cudaFuncSetAttribute(attn_kernel, cudaFuncAttributeMaxDynamicSharedMemorySize, attn_smem);

    wtrans_kernel<<<6, 256>>>(in_w, out_w, fw1, fw2);
    prep_kernel<<<1, 128>>>(attW, a_src, a_dst, lengths, B);

    int items = N + E;
    logits_kernel<<<(items + 7) / 8, 256>>>(POI, dde, sess_idx, edge_dist, N, E);
    gcn_ln1_kernel<<<N, 128>>>(POI, sess_idx, batch_ids, node_pos, lengths, ln1g, ln1b);

    int gblocks = (N + 127) / 128;
    gemm128_kernel<0><<<gblocks, 256, gemm_smem>>>(b1, wt,                 in_b,       nullptr, nullptr, nullptr, b2, N);
    gemm128_kernel<0><<<gblocks, 256, gemm_smem>>>(b0, wt + 16384,         in_b + 128, nullptr, nullptr, nullptr, b3, N);
    gemm128_kernel<0><<<gblocks, 256, gemm_smem>>>(b0, wt + 2 * 16384,     in_b + 256, nullptr, nullptr, nullptr, b4, N);

    dim3 ag(B, 4);
    attn_kernel<<<ag, 256, attn_smem>>>(b2, b3, b4, b0, lengths);

    gemm128_kernel<2><<<gblocks, 256, gemm_smem>>>(b0, wt + 3 * 16384, out_b, b1, ln2g, ln2b, b3, N);
    gemm128_kernel<1><<<gblocks, 256, gemm_smem>>>(b3, wt + 4 * 16384, fb1, nullptr, nullptr, nullptr, b4, N);
    gemm128_kernel<3><<<gblocks, 256, gemm_smem>>>(b4, wt + 5 * 16384, fb2, b3, nullptr, nullptr, b2, N);

    pool_kernel<<<B, 128>>>(b2, lengths, outp);
}

// round 4
// speedup vs baseline: 1.6560x; 1.2212x over previous
#include <cuda_runtime.h>
#include <cuda_bf16.h>
#include <math.h>

// ---------------------------------------------------------------------------
// SeqGraphRepNetwork on GB300 — packed formulation.
// R4: bf16-split (2-term, error-compensated) tensor-core GEMMs via
//     mma.sync.m16n8k16.bf16; warp-per-node GCN+LN1; parallel prefix scan.
// ---------------------------------------------------------------------------

#define NMAX   163840
#define LMAX   160
#define SKP    161
#define BMAXS  1024
#define PA     68            // padded row stride (32-bit words) for bf16x2 planes

__device__ float d_vsrc[128];
__device__ float d_vdst[128];
__device__ int   d_starts[BMAXS + 1];
__device__ float d_psrc[NMAX];
__device__ float d_pdst[NMAX];
__device__ float d_qe[NMAX];
__device__ float g_buf0[(size_t)NMAX * 128]; // Hu, later ctx
__device__ float g_buf1[(size_t)NMAX * 128]; // Qin (LN1 output)
__device__ float g_buf2[(size_t)NMAX * 128]; // q proj, later out3
__device__ float g_buf3[(size_t)NMAX * 128]; // k proj, later out2
__device__ float g_buf4[(size_t)NMAX * 128]; // v proj, later ffn hidden

// ---------------------------------------------------------------------------
// scan: session start offsets (parallel Hillis-Steele over one block)
// ---------------------------------------------------------------------------
__global__ void scan_kernel(const int* __restrict__ lengths, int B)
{
    __shared__ int s[BMAXS];
    int t = threadIdx.x;
    int v = (t < B) ? lengths[t] : 0;
    s[t] = v;
    __syncthreads();
    #pragma unroll
    for (int o = 1; o < BMAXS; o <<= 1) {
        int add = (t >= o) ? s[t - o] : 0;
        __syncthreads();
        s[t] += add;
        __syncthreads();
    }
    if (t < B) d_starts[t] = s[t] - v;
    if (t == B - 1) d_starts[B] = s[t];
}

// ---------------------------------------------------------------------------
// prep: v_src = att_W^T a_src, v_dst = att_W^T a_dst
// ---------------------------------------------------------------------------
__global__ void prep_kernel(const float* __restrict__ attW,
                            const float* __restrict__ a_src,
                            const float* __restrict__ a_dst)
{
    int d = threadIdx.x;
    float vs = 0.f, vd = 0.f;
    #pragma unroll 4
    for (int k = 0; k < 128; ++k) {
        float w = attW[k * 128 + d];
        vs += a_src[k] * w;
        vd += a_dst[k] * w;
    }
    d_vsrc[d] = vs;
    d_vdst[d] = vd;
}

// ---------------------------------------------------------------------------
// logits: per-node p_src/p_dst and per-edge qe  (one warp per item)
// ---------------------------------------------------------------------------
__global__ void logits_kernel(const float* __restrict__ POI,
                              const float* __restrict__ dde,
                              const int*   __restrict__ sess_idx,
                              const int*   __restrict__ edge_dist,
                              int N, int E)
{
    int gwarp = (blockIdx.x * blockDim.x + threadIdx.x) >> 5;
    int lane  = threadIdx.x & 31;
    if (gwarp < N) {
        const float4* row = (const float4*)(POI + (size_t)sess_idx[gwarp] * 128);
        float4 x = row[lane];
        float4 a = ((const float4*)d_vsrc)[lane];
        float4 b = ((const float4*)d_vdst)[lane];
        float p1 = x.x*a.x + x.y*a.y + x.z*a.z + x.w*a.w;
        float p2 = x.x*b.x + x.y*b.y + x.z*b.z + x.w*b.w;
        #pragma unroll
        for (int o = 16; o; o >>= 1) {
            p1 += __shfl_xor_sync(0xffffffffu, p1, o);
            p2 += __shfl_xor_sync(0xffffffffu, p2, o);
        }
        if (lane == 0) { d_psrc[gwarp] = p1; d_pdst[gwarp] = p2; }
    } else if (gwarp < N + E) {
        int e = gwarp - N;
        const float4* row = (const float4*)(dde + (size_t)edge_dist[e] * 128);
        float4 x = row[lane];
        float4 a = ((const float4*)d_vsrc)[lane];
        float q = x.x*a.x + x.y*a.y + x.z*a.z + x.w*a.w;
        #pragma unroll
        for (int o = 16; o; o >>= 1) q += __shfl_xor_sync(0xffffffffu, q, o);
        if (lane == 0) d_qe[e] = q;
    }
}

// ---------------------------------------------------------------------------
// GCN 2-message softmax aggregation + LayerNorm1.  One WARP per node.
// ---------------------------------------------------------------------------
__global__ void gcn_ln1_kernel(const float* __restrict__ POI,
                               const int*   __restrict__ sess_idx,
                               const int*   __restrict__ batch_ids,
                               const int*   __restrict__ node_pos,
                               const int*   __restrict__ lengths,
                               const float* __restrict__ g1,
                               const float* __restrict__ b1, int N)
{
    int n = blockIdx.x * 8 + (threadIdx.x >> 5);
    if (n >= N) return;
    int lane = threadIdx.x & 31;
    int b = batch_ids[n];
    int p = node_pos[n];
    int l = lengths[b];
    bool h1 = (p > 0);
    bool h2 = (p < l - 1);
    float L1 = h1 ? (d_psrc[n] + d_qe[n - 1 - b]) : -1e30f;
    float L2 = h2 ? d_pdst[n] : -1e30f;
    float m  = fmaxf(L1, L2);
    float e1 = h1 ? expf(L1 - m) : 0.f;
    float e2 = h2 ? expf(L2 - m) : 0.f;
    float inv = 1.f / (e1 + e2 + 1e-16f);
    float a1 = e1 * inv, a2 = e2 * inv;

    float4 hu = make_float4(0.f, 0.f, 0.f, 0.f);
    if (h1) {
        float4 x = ((const float4*)(POI + (size_t)sess_idx[n - 1] * 128))[lane];
        hu.x += a1 * x.x; hu.y += a1 * x.y; hu.z += a1 * x.z; hu.w += a1 * x.w;
    }
    if (h2) {
        float4 x = ((const float4*)(POI + (size_t)sess_idx[n + 1] * 128))[lane];
        hu.x += a2 * x.x; hu.y += a2 * x.y; hu.z += a2 * x.z; hu.w += a2 * x.w;
    }
    ((float4*)g_buf0)[(size_t)n * 32 + lane] = hu;

    float s1 = hu.x + hu.y + hu.z + hu.w;
    float s2 = hu.x*hu.x + hu.y*hu.y + hu.z*hu.z + hu.w*hu.w;
    #pragma unroll
    for (int o = 16; o; o >>= 1) {
        s1 += __shfl_xor_sync(0xffffffffu, s1, o);
        s2 += __shfl_xor_sync(0xffffffffu, s2, o);
    }
    float mu   = s1 * (1.f / 128.f);
    float var  = fmaxf(s2 * (1.f / 128.f) - mu * mu, 0.f);
    float rstd = rsqrtf(var + 1e-8f);
    float4 gg = ((const float4*)g1)[lane];
    float4 bb = ((const float4*)b1)[lane];
    float4 o4;
    o4.x = (hu.x - mu) * rstd * gg.x + bb.x;
    o4.y = (hu.y - mu) * rstd * gg.y + bb.y;
    o4.z = (hu.z - mu) * rstd * gg.z + bb.z;
    o4.w = (hu.w - mu) * rstd * gg.w + bb.w;
    ((float4*)g_buf1)[(size_t)n * 32 + lane] = o4;
}

// ---------------------------------------------------------------------------
// bf16 split helpers + mma wrapper
// ---------------------------------------------------------------------------
__device__ __forceinline__ void bsplit2(float a0, float a1,
                                        unsigned &hi, unsigned &lo)
{
    __nv_bfloat162 h = __float22bfloat162_rn(make_float2(a0, a1));
    float r0 = a0 - __low2float(h);
    float r1 = a1 - __high2float(h);
    __nv_bfloat162 l = __float22bfloat162_rn(make_float2(r0, r1));
    hi = *(unsigned*)&h;
    lo = *(unsigned*)&l;
}

#define MMA_BF16(d0,d1,d2,d3, a0,a1,a2,a3, b0,b1)                         \
    asm volatile("mma.sync.aligned.m16n8k16.row.col.f32.bf16.bf16.f32 "   \
                 "{%0,%1,%2,%3}, {%4,%5,%6,%7}, {%8,%9}, {%0,%1,%2,%3};"  \
                 : "+f"(d0), "+f"(d1), "+f"(d2), "+f"(d3)                 \
                 : "r"(a0), "r"(a1), "r"(a2), "r"(a3), "r"(b0), "r"(b1))

// ---------------------------------------------------------------------------
// Tensor-core GEMM: out[r][c] = sum_k A[r][k] * W[c][k]   (+ fused epilogues)
//  MODE 0: +bias   MODE 1: +bias,relu   MODE 2: +bias+res,LN   MODE 3: +bias+res
// 256 threads, 128x128 tile. Operands split hi/lo bf16; 3 MMA terms:
// Ah*Bh + Ah*Bl + Al*Bh  (drops Al*Bl ~ 2^-18 rel).
// Warp grid 2x4: warp tile 64 rows x 32 cols; frags 4x4 m16n8k16.
// ---------------------------------------------------------------------------
template<int MODE>
__global__ void __launch_bounds__(256, 1)
gemm_mma_kernel(const float* __restrict__ A, const float* __restrict__ W,
                const float* __restrict__ bias, const float* __restrict__ res,
                const float* __restrict__ lng, const float* __restrict__ lnb,
                float* __restrict__ out, int nrows)
{
    extern __shared__ unsigned smu[];
    unsigned* Ah = smu;                  // [128][PA]
    unsigned* Al = Ah + 128 * PA;
    unsigned* Bh = Al + 128 * PA;
    unsigned* Bl = Bh + 128 * PA;
    float*    Cs = (float*)smu;          // reuse Ah+Al: 128*132 floats fits 2*128*PA
    int tid  = threadIdx.x;
    int row0 = blockIdx.x * 128;

    // convert A (activations) and W (weights, natural [c][k]) to split bf16
    for (int i = tid; i < 4096; i += 256) {
        int r = i >> 5, q = i & 31;
        int gr = row0 + r;
        float4 a = (gr < nrows) ? ((const float4*)A)[(size_t)gr * 32 + q]
                                : make_float4(0.f, 0.f, 0.f, 0.f);
        unsigned h0, l0, h1, l1;
        bsplit2(a.x, a.y, h0, l0);
        bsplit2(a.z, a.w, h1, l1);
        Ah[r * PA + 2 * q]     = h0;  Ah[r * PA + 2 * q + 1] = h1;
        Al[r * PA + 2 * q]     = l0;  Al[r * PA + 2 * q + 1] = l1;
        float4 w = ((const float4*)W)[i];
        bsplit2(w.x, w.y, h0, l0);
        bsplit2(w.z, w.w, h1, l1);
        Bh[r * PA + 2 * q]     = h0;  Bh[r * PA + 2 * q + 1] = h1;
        Bl[r * PA + 2 * q]     = l0;  Bl[r * PA + 2 * q + 1] = l1;
    }
    __syncthreads();

    int lane = tid & 31, wid = tid >> 5;
    int g  = lane >> 2;          // 0..7
    int tq = lane & 3;           // 0..3
    int warpRow = (wid & 1) * 64;
    int warpCol = (wid >> 1) * 32;

    float d[4][4][4];
    #pragma unroll
    for (int i = 0; i < 4; ++i)
        #pragma unroll
        for (int j = 0; j < 4; ++j)
            d[i][j][0] = d[i][j][1] = d[i][j][2] = d[i][j][3] = 0.f;

    #pragma unroll
    for (int kk = 0; kk < 8; ++kk) {
        unsigned ah[4][4], al[4][4], bh[4][2], bl[4][2];
        #pragma unroll
        for (int i = 0; i < 4; ++i) {
            int base = (warpRow + i * 16 + g) * PA + kk * 8 + tq;
            ah[i][0] = Ah[base];            ah[i][1] = Ah[base + 8 * PA];
            ah[i][2] = Ah[base + 4];        ah[i][3] = Ah[base + 8 * PA + 4];
            al[i][0] = Al[base];            al[i][1] = Al[base + 8 * PA];
            al[i][2] = Al[base + 4];        al[i][3] = Al[base + 8 * PA + 4];
        }
        #pragma unroll
        for (int j = 0; j < 4; ++j) {
            int base = (warpCol + j * 8 + g) * PA + kk * 8 + tq;
            bh[j][0] = Bh[base];  bh[j][1] = Bh[base + 4];
            bl[j][0] = Bl[base];  bl[j][1] = Bl[base + 4];
        }
        #pragma unroll
        for (int i = 0; i < 4; ++i)
            #pragma unroll
            for (int j = 0; j < 4; ++j) {
                MMA_BF16(d[i][j][0], d[i][j][1], d[i][j][2], d[i][j][3],
                         ah[i][0], ah[i][1], ah[i][2], ah[i][3],
                         bh[j][0], bh[j][1]);
                MMA_BF16(d[i][j][0], d[i][j][1], d[i][j][2], d[i][j][3],
                         ah[i][0], ah[i][1], ah[i][2], ah[i][3],
                         bl[j][0], bl[j][1]);
                MMA_BF16(d[i][j][0], d[i][j][1], d[i][j][2], d[i][j][3],
                         al[i][0], al[i][1], al[i][2], al[i][3],
                         bh[j][0], bh[j][1]);
            }
    }
    __syncthreads();

    // stage accumulators to smem (stride 132 words)
    #pragma unroll
    for (int i = 0; i < 4; ++i) {
        int r0 = warpRow + i * 16 + g;
        #pragma unroll
        for (int j = 0; j < 4; ++j) {
            int c0 = warpCol + j * 8 + tq * 2;
            *(float2*)&Cs[r0 * 132 + c0]       = make_float2(d[i][j][0], d[i][j][1]);
            *(float2*)&Cs[(r0 + 8) * 132 + c0] = make_float2(d[i][j][2], d[i][j][3]);
        }
    }
    __syncthreads();

    // epilogue: warp per row (lane covers 4 cols)
    float4 bb = ((const float4*)bias)[lane];
    float4 gg = make_float4(0,0,0,0), be = gg;
    if (MODE == 2) {
        gg = ((const float4*)lng)[lane];
        be = ((const float4*)lnb)[lane];
    }
    for (int r = wid; r < 128; r += 8) {
        int gr = row0 + r;
        if (gr >= nrows) continue;
        float4 v = *(float4*)&Cs[r * 132 + lane * 4];
        v.x += bb.x; v.y += bb.y; v.z += bb.z; v.w += bb.w;
        if (MODE == 1) {
            v.x = fmaxf(v.x, 0.f); v.y = fmaxf(v.y, 0.f);
            v.z = fmaxf(v.z, 0.f); v.w = fmaxf(v.w, 0.f);
        }
        if (MODE == 2 || MODE == 3) {
            float4 rv = ((const float4*)(res + (size_t)gr * 128))[lane];
            v.x += rv.x; v.y += rv.y; v.z += rv.z; v.w += rv.w;
        }
        if (MODE == 2) {
            float s1 = v.x + v.y + v.z + v.w;
            float s2 = v.x*v.x + v.y*v.y + v.z*v.z + v.w*v.w;
            #pragma unroll
            for (int o = 16; o; o >>= 1) {
                s1 += __shfl_xor_sync(0xffffffffu, s1, o);
                s2 += __shfl_xor_sync(0xffffffffu, s2, o);
            }
            float mu   = s1 * (1.f / 128.f);
            float var  = fmaxf(s2 * (1.f / 128.f) - mu * mu, 0.f);
            float rstd = rsqrtf(var + 1e-8f);
            v.x = (v.x - mu) * rstd * gg.x + be.x;
            v.y = (v.y - mu) * rstd * gg.y + be.y;
            v.z = (v.z - mu) * rstd * gg.z + be.z;
            v.w = (v.w - mu) * rstd * gg.w + be.w;
        }
        ((float4*)(out + (size_t)gr * 128))[lane] = v;
    }
}

// ---------------------------------------------------------------------------
// attention per (session, head); 8 warps, 8 queries per warp pass.
// ---------------------------------------------------------------------------
__global__ void __launch_bounds__(256)
attn_kernel(const float* __restrict__ qp, const float* __restrict__ kp,
            const float* __restrict__ vp, float* __restrict__ ctx,
            const int* __restrict__ lengths)
{
    int b = blockIdx.x;
    int h = blockIdx.y;
    int n0 = d_starts[b];
    int l  = lengths[b];
    extern __shared__ float sm[];
    float* sq  = sm;                 // [LMAX][32]
    float* skT = sm + LMAX * 32;     // [32][SKP]
    float* sv  = skT + 32 * SKP;     // [LMAX][32]
    int tid = threadIdx.x;
    int hc  = h * 32;

    for (int i = tid; i < l * 32; i += 256) {
        int s = i >> 5, c = i & 31;
        size_t gi = (size_t)(n0 + s) * 128 + hc + c;
        sq[i] = qp[gi];
        skT[c * SKP + s] = kp[gi];
        sv[i] = vp[gi];
    }
    int nchunk = (l + 7) >> 3;
    for (int i = l * 32 + tid; i < nchunk * 256; i += 256) sq[i] = 0.f;
    __syncthreads();

    int wid  = tid >> 5;
    int lane = tid & 31;
    const float scale = 0.17677669529663687f;
    int ng = (l + 31) >> 5;

    for (int ch = wid; ch < nchunk; ch += 8) {
        int t0 = ch * 8;
        float acc[8][5];
        #pragma unroll
        for (int j = 0; j < 8; ++j)
            #pragma unroll
            for (int g = 0; g < 5; ++g) acc[j][g] = 0.f;

        for (int c = 0; c < 32; ++c) {
            float kx[5];
            #pragma unroll
            for (int g = 0; g < 5; ++g)
                kx[g] = (g < ng) ? skT[c * SKP + (g << 5) + lane] : 0.f;
            #pragma unroll
            for (int j = 0; j < 8; ++j) {
                float qv = sq[(t0 + j) * 32 + c];
                #pragma unroll
                for (int g = 0; g < 5; ++g) acc[j][g] += qv * kx[g];
            }
        }

        float inv[8];
        #pragma unroll
        for (int j = 0; j < 8; ++j) {
            float m = -1e30f;
            #pragma unroll
            for (int g = 0; g < 5; ++g) {
                int s = (g << 5) + lane;
                float a = (g < ng && s < l) ? acc[j][g] * scale : -1e30f;
                acc[j][g] = a;
                m = fmaxf(m, a);
            }
            #pragma unroll
            for (int o = 16; o; o >>= 1)
                m = fmaxf(m, __shfl_xor_sync(0xffffffffu, m, o));
            float dsum = 0.f;
            #pragma unroll
            for (int g = 0; g < 5; ++g) {
                int s = (g << 5) + lane;
                float e = (g < ng && s < l) ? __expf(acc[j][g] - m) : 0.f;
                acc[j][g] = e;
                dsum += e;
            }
            #pragma unroll
            for (int o = 16; o; o >>= 1)
                dsum += __shfl_xor_sync(0xffffffffu, dsum, o);
            inv[j] = 1.f / dsum;
        }

        float cv[8];
        #pragma unroll
        for (int j = 0; j < 8; ++j) cv[j] = 0.f;
        for (int g = 0; g < ng; ++g) {
            int smax = l - (g << 5);
            if (smax > 32) smax = 32;
            for (int sl = 0; sl < smax; ++sl) {
                float vx = sv[(((g << 5) + sl) << 5) + lane];
                #pragma unroll
                for (int j = 0; j < 8; ++j)
                    cv[j] += __shfl_sync(0xffffffffu, acc[j][g], sl) * vx;
            }
        }
        #pragma unroll
        for (int j = 0; j < 8; ++j)
            if (t0 + j < l)
                ctx[(size_t)(n0 + t0 + j) * 128 + hc + lane] = cv[j] * inv[j];
    }
}

// ---------------------------------------------------------------------------
// masked mean pool
// ---------------------------------------------------------------------------
__global__ void pool_kernel(const float* __restrict__ x,
                            const int* __restrict__ lengths,
                            float* __restrict__ out)
{
    int b = blockIdx.x, d = threadIdx.x;
    int n0 = d_starts[b], l = lengths[b];
    float s = 0.f;
    #pragma unroll 4
    for (int p = 0; p < l; ++p) s += x[(size_t)(n0 + p) * 128 + d];
    out[b * 128 + d] = s / (float)l;
}

// ---------------------------------------------------------------------------
extern "C" void kernel_launch(void* const* d_in, const int* in_sizes, int n_in,
                              void* d_out, int out_size)
{
    const float* POI    = (const float*)d_in[0];
    const float* dde    = (const float*)d_in[1];
    const float* attW   = (const float*)d_in[2];
    const float* a_src  = (const float*)d_in[3];
    const float* a_dst  = (const float*)d_in[4];
    const float* in_w   = (const float*)d_in[5];
    const float* in_b   = (const float*)d_in[6];
    const float* out_w  = (const float*)d_in[7];
    const float* out_b  = (const float*)d_in[8];
    const float* ln1g   = (const float*)d_in[9];
    const float* ln1b   = (const float*)d_in[10];
    const float* ln2g   = (const float*)d_in[11];
    const float* ln2b   = (const float*)d_in[12];
    const float* fw1    = (const float*)d_in[13];
    const float* fb1    = (const float*)d_in[14];
    const float* fw2    = (const float*)d_in[15];
    const float* fb2    = (const float*)d_in[16];
    const int* sess_idx  = (const int*)d_in[17];
    const int* edge_dist = (const int*)d_in[18];
    const int* batch_ids = (const int*)d_in[20];
    const int* node_pos  = (const int*)d_in[21];
    const int* lengths   = (const int*)d_in[22];
    int N = in_sizes[17];
    int E = in_sizes[18];
    int B = in_sizes[22];
    float* outp = (float*)d_out;

    float *b0, *b1, *b2, *b3, *b4;
    cudaGetSymbolAddress((void**)&b0, g_buf0);
    cudaGetSymbolAddress((void**)&b1, g_buf1);
    cudaGetSymbolAddress((void**)&b2, g_buf2);
    cudaGetSymbolAddress((void**)&b3, g_buf3);
    cudaGetSymbolAddress((void**)&b4, g_buf4);

    const int gemm_smem = 4 * 128 * PA * (int)sizeof(unsigned);             // ~136 KB
    const int attn_smem = (LMAX * 32 * 2 + 32 * SKP) * (int)sizeof(float);  // ~61 KB
    cudaFuncSetAttribute(gemm_mma_kernel<0>, cudaFuncAttributeMaxDynamicSharedMemorySize, gemm_smem);
    cudaFuncSetAttribute(gemm_mma_kernel<1>, cudaFuncAttributeMaxDynamicSharedMemorySize, gemm_smem);
    cudaFuncSetAttribute(gemm_mma_kernel<2>, cudaFuncAttributeMaxDynamicSharedMemorySize, gemm_smem);
    cudaFuncSetAttribute(gemm_mma_kernel<3>, cudaFuncAttributeMaxDynamicSharedMemorySize, gemm_smem);
    cudaFuncSetAttribute(attn_kernel, cudaFuncAttributeMaxDynamicSharedMemorySize, attn_smem);

    scan_kernel<<<1, BMAXS>>>(lengths, B);
    prep_kernel<<<1, 128>>>(attW, a_src, a_dst);

    int items = N + E;
    logits_kernel<<<(items + 7) / 8, 256>>>(POI, dde, sess_idx, edge_dist, N, E);
    gcn_ln1_kernel<<<(N + 7) / 8, 256>>>(POI, sess_idx, batch_ids, node_pos,
                                         lengths, ln1g, ln1b, N);

    int gblocks = (N + 127) / 128;
    gemm_mma_kernel<0><<<gblocks, 256, gemm_smem>>>(b1, in_w,             in_b,       nullptr, nullptr, nullptr, b2, N);
    gemm_mma_kernel<0><<<gblocks, 256, gemm_smem>>>(b0, in_w + 16384,     in_b + 128, nullptr, nullptr, nullptr, b3, N);
    gemm_mma_kernel<0><<<gblocks, 256, gemm_smem>>>(b0, in_w + 2 * 16384, in_b + 256, nullptr, nullptr, nullptr, b4, N);

    dim3 ag(B, 4);
    attn_kernel<<<ag, 256, attn_smem>>>(b2, b3, b4, b0, lengths);

    gemm_mma_kernel<2><<<gblocks, 256, gemm_smem>>>(b0, out_w, out_b, b1, ln2g, ln2b, b3, N);
    gemm_mma_kernel<1><<<gblocks, 256, gemm_smem>>>(b3, fw1, fb1, nullptr, nullptr, nullptr, b4, N);
    gemm_mma_kernel<3><<<gblocks, 256, gemm_smem>>>(b4, fw2, fb2, b3, nullptr, nullptr, b2, N);

    pool_kernel<<<B, 128>>>(b2, lengths, outp);
}

// round 5
// speedup vs baseline: 2.0244x; 1.2224x over previous
#include <cuda_runtime.h>
#include <cuda_bf16.h>
#include <math.h>

// ---------------------------------------------------------------------------
// SeqGraphRepNetwork on GB300 — packed formulation.
// R5: tensor-core attention (split-bf16 flash style, P kept in registers);
//     weight bf16-splits precomputed once; GEMM prologue halved.
// ---------------------------------------------------------------------------

#define NMAX   163840
#define LMAX   160
#define BMAXS  1024
#define PA     68            // gemm smem row stride (words)
#define QS     20            // attn Q/K smem row stride (words) - conflict free
#define VS     84            // attn V^T smem row stride (words)

__device__ float d_vsrc[128];
__device__ float d_vdst[128];
__device__ int   d_starts[BMAXS + 1];
__device__ float d_psrc[NMAX];
__device__ float d_pdst[NMAX];
__device__ float d_qe[NMAX];
__device__ unsigned d_wh[6 * 128 * PA];      // weight hi-plane, gemm layout
__device__ unsigned d_wl[6 * 128 * PA];      // weight lo-plane
__device__ float g_buf0[(size_t)NMAX * 128]; // Hu, later ctx
__device__ float g_buf1[(size_t)NMAX * 128]; // Qin (LN1 output)
__device__ float g_buf2[(size_t)NMAX * 128]; // q proj, later out3
__device__ float g_buf3[(size_t)NMAX * 128]; // k proj, later out2
__device__ float g_buf4[(size_t)NMAX * 128]; // v proj, later ffn hidden

// ---------------------------------------------------------------------------
__device__ __forceinline__ void bsplit2(float a0, float a1,
                                        unsigned &hi, unsigned &lo)
{
    __nv_bfloat162 h = __float22bfloat162_rn(make_float2(a0, a1));
    float r0 = a0 - __low2float(h);
    float r1 = a1 - __high2float(h);
    __nv_bfloat162 l = __float22bfloat162_rn(make_float2(r0, r1));
    hi = *(unsigned*)&h;
    lo = *(unsigned*)&l;
}

#define MMA_BF16(d0,d1,d2,d3, a0,a1,a2,a3, b0,b1)                         \
    asm volatile("mma.sync.aligned.m16n8k16.row.col.f32.bf16.bf16.f32 "   \
                 "{%0,%1,%2,%3}, {%4,%5,%6,%7}, {%8,%9}, {%0,%1,%2,%3};"  \
                 : "+f"(d0), "+f"(d1), "+f"(d2), "+f"(d3)                 \
                 : "r"(a0), "r"(a1), "r"(a2), "r"(a3), "r"(b0), "r"(b1))

// ---------------------------------------------------------------------------
// scan: session start offsets
// ---------------------------------------------------------------------------
__global__ void scan_kernel(const int* __restrict__ lengths, int B)
{
    __shared__ int s[BMAXS];
    int t = threadIdx.x;
    int v = (t < B) ? lengths[t] : 0;
    s[t] = v;
    __syncthreads();
    #pragma unroll
    for (int o = 1; o < BMAXS; o <<= 1) {
        int add = (t >= o) ? s[t - o] : 0;
        __syncthreads();
        s[t] += add;
        __syncthreads();
    }
    if (t < B) d_starts[t] = s[t] - v;
    if (t == B - 1) d_starts[B] = s[t];
}

// ---------------------------------------------------------------------------
// prep: v_src = att_W^T a_src, v_dst = att_W^T a_dst
// ---------------------------------------------------------------------------
__global__ void prep_kernel(const float* __restrict__ attW,
                            const float* __restrict__ a_src,
                            const float* __restrict__ a_dst)
{
    int d = threadIdx.x;
    float vs = 0.f, vd = 0.f;
    #pragma unroll 4
    for (int k = 0; k < 128; ++k) {
        float w = attW[k * 128 + d];
        vs += a_src[k] * w;
        vd += a_dst[k] * w;
    }
    d_vsrc[d] = vs;
    d_vdst[d] = vd;
}

// ---------------------------------------------------------------------------
// wsplit: precompute split-bf16 weight planes in gemm smem layout
// ---------------------------------------------------------------------------
__global__ void wsplit_kernel(const float* __restrict__ in_w,
                              const float* __restrict__ out_w,
                              const float* __restrict__ fw1,
                              const float* __restrict__ fw2)
{
    int m = blockIdx.x;
    const float* src = (m < 3) ? (in_w + m * 16384)
                     : (m == 3 ? out_w : (m == 4 ? fw1 : fw2));
    unsigned* wh = d_wh + m * 128 * PA;
    unsigned* wl = d_wl + m * 128 * PA;
    for (int i = threadIdx.x; i < 4096; i += 256) {
        int r = i >> 5, q = i & 31;
        float4 w = ((const float4*)src)[i];
        unsigned h0, l0, h1, l1;
        bsplit2(w.x, w.y, h0, l0);
        bsplit2(w.z, w.w, h1, l1);
        wh[r * PA + 2 * q]     = h0;  wh[r * PA + 2 * q + 1] = h1;
        wl[r * PA + 2 * q]     = l0;  wl[r * PA + 2 * q + 1] = l1;
    }
}

// ---------------------------------------------------------------------------
// logits: per-node p_src/p_dst and per-edge qe  (one warp per item)
// ---------------------------------------------------------------------------
__global__ void logits_kernel(const float* __restrict__ POI,
                              const float* __restrict__ dde,
                              const int*   __restrict__ sess_idx,
                              const int*   __restrict__ edge_dist,
                              int N, int E)
{
    int gwarp = (blockIdx.x * blockDim.x + threadIdx.x) >> 5;
    int lane  = threadIdx.x & 31;
    if (gwarp < N) {
        const float4* row = (const float4*)(POI + (size_t)sess_idx[gwarp] * 128);
        float4 x = row[lane];
        float4 a = ((const float4*)d_vsrc)[lane];
        float4 b = ((const float4*)d_vdst)[lane];
        float p1 = x.x*a.x + x.y*a.y + x.z*a.z + x.w*a.w;
        float p2 = x.x*b.x + x.y*b.y + x.z*b.z + x.w*b.w;
        #pragma unroll
        for (int o = 16; o; o >>= 1) {
            p1 += __shfl_xor_sync(0xffffffffu, p1, o);
            p2 += __shfl_xor_sync(0xffffffffu, p2, o);
        }
        if (lane == 0) { d_psrc[gwarp] = p1; d_pdst[gwarp] = p2; }
    } else if (gwarp < N + E) {
        int e = gwarp - N;
        const float4* row = (const float4*)(dde + (size_t)edge_dist[e] * 128);
        float4 x = row[lane];
        float4 a = ((const float4*)d_vsrc)[lane];
        float q = x.x*a.x + x.y*a.y + x.z*a.z + x.w*a.w;
        #pragma unroll
        for (int o = 16; o; o >>= 1) q += __shfl_xor_sync(0xffffffffu, q, o);
        if (lane == 0) d_qe[e] = q;
    }
}

// ---------------------------------------------------------------------------
// GCN 2-message softmax aggregation + LayerNorm1.  One warp per node.
// ---------------------------------------------------------------------------
__global__ void gcn_ln1_kernel(const float* __restrict__ POI,
                               const int*   __restrict__ sess_idx,
                               const int*   __restrict__ batch_ids,
                               const int*   __restrict__ node_pos,
                               const int*   __restrict__ lengths,
                               const float* __restrict__ g1,
                               const float* __restrict__ b1, int N)
{
    int n = blockIdx.x * 8 + (threadIdx.x >> 5);
    if (n >= N) return;
    int lane = threadIdx.x & 31;
    int b = batch_ids[n];
    int p = node_pos[n];
    int l = lengths[b];
    bool h1 = (p > 0);
    bool h2 = (p < l - 1);
    float L1 = h1 ? (d_psrc[n] + d_qe[n - 1 - b]) : -1e30f;
    float L2 = h2 ? d_pdst[n] : -1e30f;
    float m  = fmaxf(L1, L2);
    float e1 = h1 ? expf(L1 - m) : 0.f;
    float e2 = h2 ? expf(L2 - m) : 0.f;
    float inv = 1.f / (e1 + e2 + 1e-16f);
    float a1 = e1 * inv, a2 = e2 * inv;

    float4 hu = make_float4(0.f, 0.f, 0.f, 0.f);
    if (h1) {
        float4 x = ((const float4*)(POI + (size_t)sess_idx[n - 1] * 128))[lane];
        hu.x += a1 * x.x; hu.y += a1 * x.y; hu.z += a1 * x.z; hu.w += a1 * x.w;
    }
    if (h2) {
        float4 x = ((const float4*)(POI + (size_t)sess_idx[n + 1] * 128))[lane];
        hu.x += a2 * x.x; hu.y += a2 * x.y; hu.z += a2 * x.z; hu.w += a2 * x.w;
    }
    ((float4*)g_buf0)[(size_t)n * 32 + lane] = hu;

    float s1 = hu.x + hu.y + hu.z + hu.w;
    float s2 = hu.x*hu.x + hu.y*hu.y + hu.z*hu.z + hu.w*hu.w;
    #pragma unroll
    for (int o = 16; o; o >>= 1) {
        s1 += __shfl_xor_sync(0xffffffffu, s1, o);
        s2 += __shfl_xor_sync(0xffffffffu, s2, o);
    }
    float mu   = s1 * (1.f / 128.f);
    float var  = fmaxf(s2 * (1.f / 128.f) - mu * mu, 0.f);
    float rstd = rsqrtf(var + 1e-8f);
    float4 gg = ((const float4*)g1)[lane];
    float4 bb = ((const float4*)b1)[lane];
    float4 o4;
    o4.x = (hu.x - mu) * rstd * gg.x + bb.x;
    o4.y = (hu.y - mu) * rstd * gg.y + bb.y;
    o4.z = (hu.z - mu) * rstd * gg.z + bb.z;
    o4.w = (hu.w - mu) * rstd * gg.w + bb.w;
    ((float4*)g_buf1)[(size_t)n * 32 + lane] = o4;
}

// ---------------------------------------------------------------------------
// Tensor-core GEMM, weights pre-split.  Epilogues as before.
// ---------------------------------------------------------------------------
template<int MODE>
__global__ void __launch_bounds__(256, 1)
gemm_mma_kernel(const float* __restrict__ A,
                const unsigned* __restrict__ Wh, const unsigned* __restrict__ Wl,
                const float* __restrict__ bias, const float* __restrict__ res,
                const float* __restrict__ lng, const float* __restrict__ lnb,
                float* __restrict__ out, int nrows)
{
    extern __shared__ unsigned smu[];
    unsigned* Ah = smu;                  // [128][PA]
    unsigned* Al = Ah + 128 * PA;
    unsigned* Bh = Al + 128 * PA;
    unsigned* Bl = Bh + 128 * PA;
    float*    Cs = (float*)smu;          // reuse Ah+Al for epilogue staging
    int tid  = threadIdx.x;
    int row0 = blockIdx.x * 128;

    for (int i = tid; i < 4096; i += 256) {
        int r = i >> 5, q = i & 31;
        int gr = row0 + r;
        float4 a = (gr < nrows) ? ((const float4*)A)[(size_t)gr * 32 + q]
                                : make_float4(0.f, 0.f, 0.f, 0.f);
        unsigned h0, l0, h1, l1;
        bsplit2(a.x, a.y, h0, l0);
        bsplit2(a.z, a.w, h1, l1);
        Ah[r * PA + 2 * q]     = h0;  Ah[r * PA + 2 * q + 1] = h1;
        Al[r * PA + 2 * q]     = l0;  Al[r * PA + 2 * q + 1] = l1;
    }
    for (int i = tid; i < 2176; i += 256) {   // 128*PA/4 uint4 copies
        ((uint4*)Bh)[i] = ((const uint4*)Wh)[i];
        ((uint4*)Bl)[i] = ((const uint4*)Wl)[i];
    }
    __syncthreads();

    int lane = tid & 31, wid = tid >> 5;
    int g  = lane >> 2;
    int tq = lane & 3;
    int warpRow = (wid & 1) * 64;
    int warpCol = (wid >> 1) * 32;

    float d[4][4][4];
    #pragma unroll
    for (int i = 0; i < 4; ++i)
        #pragma unroll
        for (int j = 0; j < 4; ++j)
            d[i][j][0] = d[i][j][1] = d[i][j][2] = d[i][j][3] = 0.f;

    #pragma unroll
    for (int kk = 0; kk < 8; ++kk) {
        unsigned ah[4][4], al[4][4], bh[4][2], bl[4][2];
        #pragma unroll
        for (int i = 0; i < 4; ++i) {
            int base = (warpRow + i * 16 + g) * PA + kk * 8 + tq;
            ah[i][0] = Ah[base];            ah[i][1] = Ah[base + 8 * PA];
            ah[i][2] = Ah[base + 4];        ah[i][3] = Ah[base + 8 * PA + 4];
            al[i][0] = Al[base];            al[i][1] = Al[base + 8 * PA];
            al[i][2] = Al[base + 4];        al[i][3] = Al[base + 8 * PA + 4];
        }
        #pragma unroll
        for (int j = 0; j < 4; ++j) {
            int base = (warpCol + j * 8 + g) * PA + kk * 8 + tq;
            bh[j][0] = Bh[base];  bh[j][1] = Bh[base + 4];
            bl[j][0] = Bl[base];  bl[j][1] = Bl[base + 4];
        }
        #pragma unroll
        for (int i = 0; i < 4; ++i)
            #pragma unroll
            for (int j = 0; j < 4; ++j) {
                MMA_BF16(d[i][j][0], d[i][j][1], d[i][j][2], d[i][j][3],
                         ah[i][0], ah[i][1], ah[i][2], ah[i][3],
                         bh[j][0], bh[j][1]);
                MMA_BF16(d[i][j][0], d[i][j][1], d[i][j][2], d[i][j][3],
                         ah[i][0], ah[i][1], ah[i][2], ah[i][3],
                         bl[j][0], bl[j][1]);
                MMA_BF16(d[i][j][0], d[i][j][1], d[i][j][2], d[i][j][3],
                         al[i][0], al[i][1], al[i][2], al[i][3],
                         bh[j][0], bh[j][1]);
            }
    }
    __syncthreads();

    #pragma unroll
    for (int i = 0; i < 4; ++i) {
        int r0 = warpRow + i * 16 + g;
        #pragma unroll
        for (int j = 0; j < 4; ++j) {
            int c0 = warpCol + j * 8 + tq * 2;
            *(float2*)&Cs[r0 * 132 + c0]       = make_float2(d[i][j][0], d[i][j][1]);
            *(float2*)&Cs[(r0 + 8) * 132 + c0] = make_float2(d[i][j][2], d[i][j][3]);
        }
    }
    __syncthreads();

    float4 bb = ((const float4*)bias)[lane];
    float4 gg = make_float4(0,0,0,0), be = gg;
    if (MODE == 2) {
        gg = ((const float4*)lng)[lane];
        be = ((const float4*)lnb)[lane];
    }
    for (int r = wid; r < 128; r += 8) {
        int gr = row0 + r;
        if (gr >= nrows) continue;
        float4 v = *(float4*)&Cs[r * 132 + lane * 4];
        v.x += bb.x; v.y += bb.y; v.z += bb.z; v.w += bb.w;
        if (MODE == 1) {
            v.x = fmaxf(v.x, 0.f); v.y = fmaxf(v.y, 0.f);
            v.z = fmaxf(v.z, 0.f); v.w = fmaxf(v.w, 0.f);
        }
        if (MODE == 2 || MODE == 3) {
            float4 rv = ((const float4*)(res + (size_t)gr * 128))[lane];
            v.x += rv.x; v.y += rv.y; v.z += rv.z; v.w += rv.w;
        }
        if (MODE == 2) {
            float s1 = v.x + v.y + v.z + v.w;
            float s2 = v.x*v.x + v.y*v.y + v.z*v.z + v.w*v.w;
            #pragma unroll
            for (int o = 16; o; o >>= 1) {
                s1 += __shfl_xor_sync(0xffffffffu, s1, o);
                s2 += __shfl_xor_sync(0xffffffffu, s2, o);
            }
            float mu   = s1 * (1.f / 128.f);
            float var  = fmaxf(s2 * (1.f / 128.f) - mu * mu, 0.f);
            float rstd = rsqrtf(var + 1e-8f);
            v.x = (v.x - mu) * rstd * gg.x + be.x;
            v.y = (v.y - mu) * rstd * gg.y + be.y;
            v.z = (v.z - mu) * rstd * gg.z + be.z;
            v.w = (v.w - mu) * rstd * gg.w + be.w;
        }
        ((float4*)(out + (size_t)gr * 128))[lane] = v;
    }
}

// ---------------------------------------------------------------------------
// Tensor-core attention per (session, head).  4 warps; warp per 16-row tile.
// S = Q K^T (split-bf16, 3 terms), softmax in regs, ctx = P V with P
// fragments constructed in-register from the S accumulator layout.
// NCT = column tiles of 8 (12 for l<=96, 16 for l<=128, else 20).
// ---------------------------------------------------------------------------
template<int NCT>
__device__ __forceinline__ void attn_rowtile(
    const unsigned* Qh, const unsigned* Ql,
    const unsigned* Kh, const unsigned* Kl,
    const unsigned* Vh, const unsigned* Vl,
    float* __restrict__ ctx, int n0, int hc, int l, int i0, int g, int tq)
{
    const float scale = 0.17677669529663687f;   // 1/sqrt(32)
    unsigned qah[2][4], qal[2][4];
    #pragma unroll
    for (int kk = 0; kk < 2; ++kk) {
        int base = (i0 + g) * QS + kk * 8 + tq;
        qah[kk][0] = Qh[base];        qah[kk][1] = Qh[base + 8 * QS];
        qah[kk][2] = Qh[base + 4];    qah[kk][3] = Qh[base + 8 * QS + 4];
        qal[kk][0] = Ql[base];        qal[kk][1] = Ql[base + 8 * QS];
        qal[kk][2] = Ql[base + 4];    qal[kk][3] = Ql[base + 8 * QS + 4];
    }
    float sa[NCT][4];
    #pragma unroll
    for (int ct = 0; ct < NCT; ++ct)
        sa[ct][0] = sa[ct][1] = sa[ct][2] = sa[ct][3] = 0.f;

    #pragma unroll
    for (int ct = 0; ct < NCT; ++ct) {
        #pragma unroll
        for (int kk = 0; kk < 2; ++kk) {
            int base = (ct * 8 + g) * QS + kk * 8 + tq;
            unsigned bh0 = Kh[base], bh1 = Kh[base + 4];
            unsigned bl0 = Kl[base], bl1 = Kl[base + 4];
            MMA_BF16(sa[ct][0], sa[ct][1], sa[ct][2], sa[ct][3],
                     qah[kk][0], qah[kk][1], qah[kk][2], qah[kk][3], bh0, bh1);
            MMA_BF16(sa[ct][0], sa[ct][1], sa[ct][2], sa[ct][3],
                     qah[kk][0], qah[kk][1], qah[kk][2], qah[kk][3], bl0, bl1);
            MMA_BF16(sa[ct][0], sa[ct][1], sa[ct][2], sa[ct][3],
                     qal[kk][0], qal[kk][1], qal[kk][2], qal[kk][3], bh0, bh1);
        }
    }

    // masked softmax over rows g (regs 0,1) and g+8 (regs 2,3)
    float m0 = -1e30f, m1 = -1e30f;
    #pragma unroll
    for (int ct = 0; ct < NCT; ++ct) {
        int c0 = ct * 8 + 2 * tq;
        bool v0 = c0 < l, v1 = (c0 + 1) < l;
        sa[ct][0] = v0 ? sa[ct][0] * scale : -1e30f;
        sa[ct][1] = v1 ? sa[ct][1] * scale : -1e30f;
        sa[ct][2] = v0 ? sa[ct][2] * scale : -1e30f;
        sa[ct][3] = v1 ? sa[ct][3] * scale : -1e30f;
        m0 = fmaxf(m0, fmaxf(sa[ct][0], sa[ct][1]));
        m1 = fmaxf(m1, fmaxf(sa[ct][2], sa[ct][3]));
    }
    m0 = fmaxf(m0, __shfl_xor_sync(0xffffffffu, m0, 1));
    m0 = fmaxf(m0, __shfl_xor_sync(0xffffffffu, m0, 2));
    m1 = fmaxf(m1, __shfl_xor_sync(0xffffffffu, m1, 1));
    m1 = fmaxf(m1, __shfl_xor_sync(0xffffffffu, m1, 2));

    float sum0 = 0.f, sum1 = 0.f;
    #pragma unroll
    for (int ct = 0; ct < NCT; ++ct) {
        int c0 = ct * 8 + 2 * tq;
        float e0 = (c0 < l)     ? __expf(sa[ct][0] - m0) : 0.f;
        float e1 = (c0 + 1 < l) ? __expf(sa[ct][1] - m0) : 0.f;
        float e2 = (c0 < l)     ? __expf(sa[ct][2] - m1) : 0.f;
        float e3 = (c0 + 1 < l) ? __expf(sa[ct][3] - m1) : 0.f;
        sa[ct][0] = e0; sa[ct][1] = e1; sa[ct][2] = e2; sa[ct][3] = e3;
        sum0 += e0 + e1; sum1 += e2 + e3;
    }
    sum0 += __shfl_xor_sync(0xffffffffu, sum0, 1);
    sum0 += __shfl_xor_sync(0xffffffffu, sum0, 2);
    sum1 += __shfl_xor_sync(0xffffffffu, sum1, 1);
    sum1 += __shfl_xor_sync(0xffffffffu, sum1, 2);

    // ctx = P V  (P fragments from sa in-register)
    float ca[4][4];
    #pragma unroll
    for (int nt = 0; nt < 4; ++nt)
        ca[nt][0] = ca[nt][1] = ca[nt][2] = ca[nt][3] = 0.f;

    #pragma unroll
    for (int kk2 = 0; kk2 < NCT / 2; ++kk2) {
        unsigned pah[4], pal[4];
        bsplit2(sa[2*kk2][0],   sa[2*kk2][1],   pah[0], pal[0]);
        bsplit2(sa[2*kk2][2],   sa[2*kk2][3],   pah[1], pal[1]);
        bsplit2(sa[2*kk2+1][0], sa[2*kk2+1][1], pah[2], pal[2]);
        bsplit2(sa[2*kk2+1][2], sa[2*kk2+1][3], pah[3], pal[3]);
        #pragma unroll
        for (int nt = 0; nt < 4; ++nt) {
            int base = (nt * 8 + g) * VS + kk2 * 8 + tq;
            unsigned bh0 = Vh[base], bh1 = Vh[base + 4];
            unsigned bl0 = Vl[base], bl1 = Vl[base + 4];
            MMA_BF16(ca[nt][0], ca[nt][1], ca[nt][2], ca[nt][3],
                     pah[0], pah[1], pah[2], pah[3], bh0, bh1);
            MMA_BF16(ca[nt][0], ca[nt][1], ca[nt][2], ca[nt][3],
                     pah[0], pah[1], pah[2], pah[3], bl0, bl1);
            MMA_BF16(ca[nt][0], ca[nt][1], ca[nt][2], ca[nt][3],
                     pal[0], pal[1], pal[2], pal[3], bh0, bh1);
        }
    }

    float inv0 = 1.f / sum0;
    float inv1 = 1.f / sum1;
    int r0 = i0 + g, r1 = i0 + 8 + g;
    #pragma unroll
    for (int nt = 0; nt < 4; ++nt) {
        int dcol = nt * 8 + 2 * tq;
        if (r0 < l)
            *(float2*)(ctx + (size_t)(n0 + r0) * 128 + hc + dcol) =
                make_float2(ca[nt][0] * inv0, ca[nt][1] * inv0);
        if (r1 < l)
            *(float2*)(ctx + (size_t)(n0 + r1) * 128 + hc + dcol) =
                make_float2(ca[nt][2] * inv1, ca[nt][3] * inv1);
    }
}

__global__ void __launch_bounds__(128, 1)
attn_mma_kernel(const float* __restrict__ qp, const float* __restrict__ kp,
                const float* __restrict__ vp, float* __restrict__ ctx,
                const int* __restrict__ lengths)
{
    int b = blockIdx.x;
    int h = blockIdx.y;
    int n0 = d_starts[b];
    int l  = lengths[b];
    extern __shared__ unsigned sm[];
    unsigned* Qh = sm;                   // [160][QS]
    unsigned* Ql = Qh + 160 * QS;
    unsigned* Kh = Ql + 160 * QS;
    unsigned* Kl = Kh + 160 * QS;
    unsigned* Vh = Kl + 160 * QS;        // [32][VS]
    unsigned* Vl = Vh + 32 * VS;
    int tid = threadIdx.x;
    int hc  = h * 32;

    const int TOTW = 4 * 160 * QS + 2 * 32 * VS;   // 18176 words
    for (int i = tid; i < TOTW / 4; i += 128)
        ((uint4*)sm)[i] = make_uint4(0u, 0u, 0u, 0u);
    __syncthreads();

    for (int i = tid; i < l * 16; i += 128) {
        int s = i >> 4, cp = i & 15;
        size_t gi = (((size_t)(n0 + s) * 128 + hc) >> 1) + cp;
        float2 qv = ((const float2*)qp)[gi];
        unsigned hi, lo;
        bsplit2(qv.x, qv.y, hi, lo);
        Qh[s * QS + cp] = hi; Ql[s * QS + cp] = lo;
        float2 kv = ((const float2*)kp)[gi];
        bsplit2(kv.x, kv.y, hi, lo);
        Kh[s * QS + cp] = hi; Kl[s * QS + cp] = lo;
    }
    int njp = (l + 1) >> 1;
    for (int i = tid; i < njp * 32; i += 128) {
        int jp = i >> 5, d = i & 31;
        int j0 = 2 * jp;
        float v0 = vp[(size_t)(n0 + j0) * 128 + hc + d];
        float v1 = (j0 + 1 < l) ? vp[(size_t)(n0 + j0 + 1) * 128 + hc + d] : 0.f;
        unsigned hi, lo;
        bsplit2(v0, v1, hi, lo);
        Vh[d * VS + jp] = hi; Vl[d * VS + jp] = lo;
    }
    __syncthreads();

    int lane = tid & 31, wid = tid >> 5;
    int g = lane >> 2, tq = lane & 3;
    int nrt = (l + 15) >> 4;

    for (int rt = wid; rt < nrt; rt += 4) {
        int i0 = rt * 16;
        if (l <= 96)
            attn_rowtile<12>(Qh, Ql, Kh, Kl, Vh, Vl, ctx, n0, hc, l, i0, g, tq);
        else if (l <= 128)
            attn_rowtile<16>(Qh, Ql, Kh, Kl, Vh, Vl, ctx, n0, hc, l, i0, g, tq);
        else
            attn_rowtile<20>(Qh, Ql, Kh, Kl, Vh, Vl, ctx, n0, hc, l, i0, g, tq);
    }
}

// ---------------------------------------------------------------------------
// masked mean pool
// ---------------------------------------------------------------------------
__global__ void pool_kernel(const float* __restrict__ x,
                            const int* __restrict__ lengths,
                            float* __restrict__ out)
{
    int b = blockIdx.x, d = threadIdx.x;
    int n0 = d_starts[b], l = lengths[b];
    float s = 0.f;
    #pragma unroll 4
    for (int p = 0; p < l; ++p) s += x[(size_t)(n0 + p) * 128 + d];
    out[b * 128 + d] = s / (float)l;
}

// ---------------------------------------------------------------------------
extern "C" void kernel_launch(void* const* d_in, const int* in_sizes, int n_in,
                              void* d_out, int out_size)
{
    const float* POI    = (const float*)d_in[0];
    const float* dde    = (const float*)d_in[1];
    const float* attW   = (const float*)d_in[2];
    const float* a_src  = (const float*)d_in[3];
    const float* a_dst  = (const float*)d_in[4];
    const float* in_w   = (const float*)d_in[5];
    const float* in_b   = (const float*)d_in[6];
    const float* out_w  = (const float*)d_in[7];
    const float* out_b  = (const float*)d_in[8];
    const float* ln1g   = (const float*)d_in[9];
    const float* ln1b   = (const float*)d_in[10];
    const float* ln2g   = (const float*)d_in[11];
    const float* ln2b   = (const float*)d_in[12];
    const float* fw1    = (const float*)d_in[13];
    const float* fb1    = (const float*)d_in[14];
    const float* fw2    = (const float*)d_in[15];
    const float* fb2    = (const float*)d_in[16];
    const int* sess_idx  = (const int*)d_in[17];
    const int* edge_dist = (const int*)d_in[18];
    const int* batch_ids = (const int*)d_in[20];
    const int* node_pos  = (const int*)d_in[21];
    const int* lengths   = (const int*)d_in[22];
    int N = in_sizes[17];
    int E = in_sizes[18];
    int B = in_sizes[22];
    float* outp = (float*)d_out;

    float *b0, *b1, *b2, *b3, *b4;
    unsigned *wh, *wl;
    cudaGetSymbolAddress((void**)&b0, g_buf0);
    cudaGetSymbolAddress((void**)&b1, g_buf1);
    cudaGetSymbolAddress((void**)&b2, g_buf2);
    cudaGetSymbolAddress((void**)&b3, g_buf3);
    cudaGetSymbolAddress((void**)&b4, g_buf4);
    cudaGetSymbolAddress((void**)&wh, d_wh);
    cudaGetSymbolAddress((void**)&wl, d_wl);

    const int gemm_smem = 4 * 128 * PA * (int)sizeof(unsigned);                 // ~136 KB
    const int attn_smem = (4 * 160 * QS + 2 * 32 * VS) * (int)sizeof(unsigned); // ~72.7 KB
    cudaFuncSetAttribute(gemm_mma_kernel<0>, cudaFuncAttributeMaxDynamicSharedMemorySize, gemm_smem);
    cudaFuncSetAttribute(gemm_mma_kernel<1>, cudaFuncAttributeMaxDynamicSharedMemorySize, gemm_smem);
    cudaFuncSetAttribute(gemm_mma_kernel<2>, cudaFuncAttributeMaxDynamicSharedMemorySize, gemm_smem);
    cudaFuncSetAttribute(gemm_mma_kernel<3>, cudaFuncAttributeMaxDynamicSharedMemorySize, gemm_smem);
    cudaFuncSetAttribute(attn_mma_kernel, cudaFuncAttributeMaxDynamicSharedMemorySize, attn_smem);

    scan_kernel<<<1, BMAXS>>>(lengths, B);
    prep_kernel<<<1, 128>>>(attW, a_src, a_dst);
    wsplit_kernel<<<6, 256>>>(in_w, out_w, fw1, fw2);

    int items = N + E;
    logits_kernel<<<(items + 7) / 8, 256>>>(POI, dde, sess_idx, edge_dist, N, E);
    gcn_ln1_kernel<<<(N + 7) / 8, 256>>>(POI, sess_idx, batch_ids, node_pos,
                                         lengths, ln1g, ln1b, N);

    int gblocks = (N + 127) / 128;
    const int WP = 128 * PA;
    gemm_mma_kernel<0><<<gblocks, 256, gemm_smem>>>(b1, wh,           wl,           in_b,       nullptr, nullptr, nullptr, b2, N);
    gemm_mma_kernel<0><<<gblocks, 256, gemm_smem>>>(b0, wh + WP,      wl + WP,      in_b + 128, nullptr, nullptr, nullptr, b3, N);
    gemm_mma_kernel<0><<<gblocks, 256, gemm_smem>>>(b0, wh + 2 * WP,  wl + 2 * WP,  in_b + 256, nullptr, nullptr, nullptr, b4, N);

    dim3 ag(B, 4);
    attn_mma_kernel<<<ag, 128, attn_smem>>>(b2, b3, b4, b0, lengths);

    gemm_mma_kernel<2><<<gblocks, 256, gemm_smem>>>(b0, wh + 3 * WP, wl + 3 * WP, out_b, b1, ln2g, ln2b, b3, N);
    gemm_mma_kernel<1><<<gblocks, 256, gemm_smem>>>(b3, wh + 4 * WP, wl + 4 * WP, fb1, nullptr, nullptr, nullptr, b4, N);
    gemm_mma_kernel<3><<<gblocks, 256, gemm_smem>>>(b4, wh + 5 * WP, wl + 5 * WP, fb2, b3, nullptr, nullptr, b2, N);

    pool_kernel<<<B, 128>>>(b2, lengths, outp);
}

// round 6
// speedup vs baseline: 2.3608x; 1.1662x over previous
#include <cuda_runtime.h>
#include <cuda_bf16.h>
#include <math.h>

// ---------------------------------------------------------------------------
// SeqGraphRepNetwork on GB300 — packed formulation.
// R6: fused tail (out-proj+LN2+FFN1+FFN2+pool in one kernel, activations in
//     smem, pool via atomics); attention prologue zero-fill trimmed.
// ---------------------------------------------------------------------------

#define NMAX   163840
#define LMAX   160
#define BMAXS  1024
#define PA     68            // gemm smem row stride (words)
#define QS     20            // attn Q/K smem row stride (words)
#define VS     84            // attn V^T smem row stride (words)

__device__ float d_vsrc[128];
__device__ float d_vdst[128];
__device__ int   d_starts[BMAXS + 1];
__device__ float d_psrc[NMAX];
__device__ float d_pdst[NMAX];
__device__ float d_qe[NMAX];
__device__ unsigned d_wh[6 * 128 * PA];      // weight hi-plane, gemm layout
__device__ unsigned d_wl[6 * 128 * PA];      // weight lo-plane
__device__ float g_buf0[(size_t)NMAX * 128]; // Hu, later ctx
__device__ float g_buf1[(size_t)NMAX * 128]; // Qin (LN1 output)
__device__ float g_buf2[(size_t)NMAX * 128]; // q proj
__device__ float g_buf3[(size_t)NMAX * 128]; // k proj
__device__ float g_buf4[(size_t)NMAX * 128]; // v proj

// ---------------------------------------------------------------------------
__device__ __forceinline__ void bsplit2(float a0, float a1,
                                        unsigned &hi, unsigned &lo)
{
    __nv_bfloat162 h = __float22bfloat162_rn(make_float2(a0, a1));
    float r0 = a0 - __low2float(h);
    float r1 = a1 - __high2float(h);
    __nv_bfloat162 l = __float22bfloat162_rn(make_float2(r0, r1));
    hi = *(unsigned*)&h;
    lo = *(unsigned*)&l;
}

#define MMA_BF16(d0,d1,d2,d3, a0,a1,a2,a3, b0,b1)                         \
    asm volatile("mma.sync.aligned.m16n8k16.row.col.f32.bf16.bf16.f32 "   \
                 "{%0,%1,%2,%3}, {%4,%5,%6,%7}, {%8,%9}, {%0,%1,%2,%3};"  \
                 : "+f"(d0), "+f"(d1), "+f"(d2), "+f"(d3)                 \
                 : "r"(a0), "r"(a1), "r"(a2), "r"(a3), "r"(b0), "r"(b1))

// 128x128x128 block mma: A split planes [128][PA], B split planes [128][PA].
// 2x4 warp grid; 3-term error-compensated product.
__device__ __forceinline__ void mma_block128(
    const unsigned* __restrict__ Ah, const unsigned* __restrict__ Al,
    const unsigned* __restrict__ Bh, const unsigned* __restrict__ Bl,
    float d[4][4][4], int warpRow, int warpCol, int g, int tq)
{
    #pragma unroll
    for (int i = 0; i < 4; ++i)
        #pragma unroll
        for (int j = 0; j < 4; ++j)
            d[i][j][0] = d[i][j][1] = d[i][j][2] = d[i][j][3] = 0.f;

    #pragma unroll
    for (int kk = 0; kk < 8; ++kk) {
        unsigned ah[4][4], al[4][4], bh[4][2], bl[4][2];
        #pragma unroll
        for (int i = 0; i < 4; ++i) {
            int base = (warpRow + i * 16 + g) * PA + kk * 8 + tq;
            ah[i][0] = Ah[base];            ah[i][1] = Ah[base + 8 * PA];
            ah[i][2] = Ah[base + 4];        ah[i][3] = Ah[base + 8 * PA + 4];
            al[i][0] = Al[base];            al[i][1] = Al[base + 8 * PA];
            al[i][2] = Al[base + 4];        al[i][3] = Al[base + 8 * PA + 4];
        }
        #pragma unroll
        for (int j = 0; j < 4; ++j) {
            int base = (warpCol + j * 8 + g) * PA + kk * 8 + tq;
            bh[j][0] = Bh[base];  bh[j][1] = Bh[base + 4];
            bl[j][0] = Bl[base];  bl[j][1] = Bl[base + 4];
        }
        #pragma unroll
        for (int i = 0; i < 4; ++i)
            #pragma unroll
            for (int j = 0; j < 4; ++j) {
                MMA_BF16(d[i][j][0], d[i][j][1], d[i][j][2], d[i][j][3],
                         ah[i][0], ah[i][1], ah[i][2], ah[i][3],
                         bh[j][0], bh[j][1]);
                MMA_BF16(d[i][j][0], d[i][j][1], d[i][j][2], d[i][j][3],
                         ah[i][0], ah[i][1], ah[i][2], ah[i][3],
                         bl[j][0], bl[j][1]);
                MMA_BF16(d[i][j][0], d[i][j][1], d[i][j][2], d[i][j][3],
                         al[i][0], al[i][1], al[i][2], al[i][3],
                         bh[j][0], bh[j][1]);
            }
    }
}

// ---------------------------------------------------------------------------
__global__ void scan_kernel(const int* __restrict__ lengths, int B)
{
    __shared__ int s[BMAXS];
    int t = threadIdx.x;
    int v = (t < B) ? lengths[t] : 0;
    s[t] = v;
    __syncthreads();
    #pragma unroll
    for (int o = 1; o < BMAXS; o <<= 1) {
        int add = (t >= o) ? s[t - o] : 0;
        __syncthreads();
        s[t] += add;
        __syncthreads();
    }
    if (t < B) d_starts[t] = s[t] - v;
    if (t == B - 1) d_starts[B] = s[t];
}

__global__ void prep_kernel(const float* __restrict__ attW,
                            const float* __restrict__ a_src,
                            const float* __restrict__ a_dst)
{
    int d = threadIdx.x;
    float vs = 0.f, vd = 0.f;
    #pragma unroll 4
    for (int k = 0; k < 128; ++k) {
        float w = attW[k * 128 + d];
        vs += a_src[k] * w;
        vd += a_dst[k] * w;
    }
    d_vsrc[d] = vs;
    d_vdst[d] = vd;
}

__global__ void wsplit_kernel(const float* __restrict__ in_w,
                              const float* __restrict__ out_w,
                              const float* __restrict__ fw1,
                              const float* __restrict__ fw2)
{
    int m = blockIdx.x;
    const float* src = (m < 3) ? (in_w + m * 16384)
                     : (m == 3 ? out_w : (m == 4 ? fw1 : fw2));
    unsigned* wh = d_wh + m * 128 * PA;
    unsigned* wl = d_wl + m * 128 * PA;
    for (int i = threadIdx.x; i < 4096; i += 256) {
        int r = i >> 5, q = i & 31;
        float4 w = ((const float4*)src)[i];
        unsigned h0, l0, h1, l1;
        bsplit2(w.x, w.y, h0, l0);
        bsplit2(w.z, w.w, h1, l1);
        wh[r * PA + 2 * q]     = h0;  wh[r * PA + 2 * q + 1] = h1;
        wl[r * PA + 2 * q]     = l0;  wl[r * PA + 2 * q + 1] = l1;
    }
}

__global__ void zero_out_kernel(float* __restrict__ out, int n)
{
    int i = blockIdx.x * blockDim.x + threadIdx.x;
    if (i < n) out[i] = 0.f;
}

// ---------------------------------------------------------------------------
__global__ void logits_kernel(const float* __restrict__ POI,
                              const float* __restrict__ dde,
                              const int*   __restrict__ sess_idx,
                              const int*   __restrict__ edge_dist,
                              int N, int E)
{
    int gwarp = (blockIdx.x * blockDim.x + threadIdx.x) >> 5;
    int lane  = threadIdx.x & 31;
    if (gwarp < N) {
        const float4* row = (const float4*)(POI + (size_t)sess_idx[gwarp] * 128);
        float4 x = row[lane];
        float4 a = ((const float4*)d_vsrc)[lane];
        float4 b = ((const float4*)d_vdst)[lane];
        float p1 = x.x*a.x + x.y*a.y + x.z*a.z + x.w*a.w;
        float p2 = x.x*b.x + x.y*b.y + x.z*b.z + x.w*b.w;
        #pragma unroll
        for (int o = 16; o; o >>= 1) {
            p1 += __shfl_xor_sync(0xffffffffu, p1, o);
            p2 += __shfl_xor_sync(0xffffffffu, p2, o);
        }
        if (lane == 0) { d_psrc[gwarp] = p1; d_pdst[gwarp] = p2; }
    } else if (gwarp < N + E) {
        int e = gwarp - N;
        const float4* row = (const float4*)(dde + (size_t)edge_dist[e] * 128);
        float4 x = row[lane];
        float4 a = ((const float4*)d_vsrc)[lane];
        float q = x.x*a.x + x.y*a.y + x.z*a.z + x.w*a.w;
        #pragma unroll
        for (int o = 16; o; o >>= 1) q += __shfl_xor_sync(0xffffffffu, q, o);
        if (lane == 0) d_qe[e] = q;
    }
}

__global__ void gcn_ln1_kernel(const float* __restrict__ POI,
                               const int*   __restrict__ sess_idx,
                               const int*   __restrict__ batch_ids,
                               const int*   __restrict__ node_pos,
                               const int*   __restrict__ lengths,
                               const float* __restrict__ g1,
                               const float* __restrict__ b1, int N)
{
    int n = blockIdx.x * 8 + (threadIdx.x >> 5);
    if (n >= N) return;
    int lane = threadIdx.x & 31;
    int b = batch_ids[n];
    int p = node_pos[n];
    int l = lengths[b];
    bool h1 = (p > 0);
    bool h2 = (p < l - 1);
    float L1 = h1 ? (d_psrc[n] + d_qe[n - 1 - b]) : -1e30f;
    float L2 = h2 ? d_pdst[n] : -1e30f;
    float m  = fmaxf(L1, L2);
    float e1 = h1 ? expf(L1 - m) : 0.f;
    float e2 = h2 ? expf(L2 - m) : 0.f;
    float inv = 1.f / (e1 + e2 + 1e-16f);
    float a1 = e1 * inv, a2 = e2 * inv;

    float4 hu = make_float4(0.f, 0.f, 0.f, 0.f);
    if (h1) {
        float4 x = ((const float4*)(POI + (size_t)sess_idx[n - 1] * 128))[lane];
        hu.x += a1 * x.x; hu.y += a1 * x.y; hu.z += a1 * x.z; hu.w += a1 * x.w;
    }
    if (h2) {
        float4 x = ((const float4*)(POI + (size_t)sess_idx[n + 1] * 128))[lane];
        hu.x += a2 * x.x; hu.y += a2 * x.y; hu.z += a2 * x.z; hu.w += a2 * x.w;
    }
    ((float4*)g_buf0)[(size_t)n * 32 + lane] = hu;

    float s1 = hu.x + hu.y + hu.z + hu.w;
    float s2 = hu.x*hu.x + hu.y*hu.y + hu.z*hu.z + hu.w*hu.w;
    #pragma unroll
    for (int o = 16; o; o >>= 1) {
        s1 += __shfl_xor_sync(0xffffffffu, s1, o);
        s2 += __shfl_xor_sync(0xffffffffu, s2, o);
    }
    float mu   = s1 * (1.f / 128.f);
    float var  = fmaxf(s2 * (1.f / 128.f) - mu * mu, 0.f);
    float rstd = rsqrtf(var + 1e-8f);
    float4 gg = ((const float4*)g1)[lane];
    float4 bb = ((const float4*)b1)[lane];
    float4 o4;
    o4.x = (hu.x - mu) * rstd * gg.x + bb.x;
    o4.y = (hu.y - mu) * rstd * gg.y + bb.y;
    o4.z = (hu.z - mu) * rstd * gg.z + bb.z;
    o4.w = (hu.w - mu) * rstd * gg.w + bb.w;
    ((float4*)g_buf1)[(size_t)n * 32 + lane] = o4;
}

// ---------------------------------------------------------------------------
// QKV projection GEMM (bias only epilogue)
// ---------------------------------------------------------------------------
__global__ void __launch_bounds__(256, 1)
gemm_qkv_kernel(const float* __restrict__ A,
                const unsigned* __restrict__ Wh, const unsigned* __restrict__ Wl,
                const float* __restrict__ bias,
                float* __restrict__ out, int nrows)
{
    extern __shared__ unsigned smu[];
    unsigned* Ah = smu;
    unsigned* Al = Ah + 128 * PA;
    unsigned* Bh = Al + 128 * PA;
    unsigned* Bl = Bh + 128 * PA;
    float*    Cs = (float*)smu;          // reuse Ah+Al for epilogue staging
    int tid  = threadIdx.x;
    int row0 = blockIdx.x * 128;

    for (int i = tid; i < 4096; i += 256) {
        int r = i >> 5, q = i & 31;
        int gr = row0 + r;
        float4 a = (gr < nrows) ? ((const float4*)A)[(size_t)gr * 32 + q]
                                : make_float4(0.f, 0.f, 0.f, 0.f);
        unsigned h0, l0, h1, l1;
        bsplit2(a.x, a.y, h0, l0);
        bsplit2(a.z, a.w, h1, l1);
        Ah[r * PA + 2 * q]     = h0;  Ah[r * PA + 2 * q + 1] = h1;
        Al[r * PA + 2 * q]     = l0;  Al[r * PA + 2 * q + 1] = l1;
    }
    for (int i = tid; i < 2176; i += 256) {
        ((uint4*)Bh)[i] = ((const uint4*)Wh)[i];
        ((uint4*)Bl)[i] = ((const uint4*)Wl)[i];
    }
    __syncthreads();

    int lane = tid & 31, wid = tid >> 5;
    int g  = lane >> 2, tq = lane & 3;
    int warpRow = (wid & 1) * 64;
    int warpCol = (wid >> 1) * 32;

    float d[4][4][4];
    mma_block128(Ah, Al, Bh, Bl, d, warpRow, warpCol, g, tq);
    __syncthreads();

    #pragma unroll
    for (int i = 0; i < 4; ++i) {
        int r0 = warpRow + i * 16 + g;
        #pragma unroll
        for (int j = 0; j < 4; ++j) {
            int c0 = warpCol + j * 8 + tq * 2;
            *(float2*)&Cs[r0 * 132 + c0]       = make_float2(d[i][j][0], d[i][j][1]);
            *(float2*)&Cs[(r0 + 8) * 132 + c0] = make_float2(d[i][j][2], d[i][j][3]);
        }
    }
    __syncthreads();

    float4 bb = ((const float4*)bias)[lane];
    for (int r = wid; r < 128; r += 8) {
        int gr = row0 + r;
        if (gr >= nrows) continue;
        float4 v = *(float4*)&Cs[r * 132 + lane * 4];
        v.x += bb.x; v.y += bb.y; v.z += bb.z; v.w += bb.w;
        ((float4*)(out + (size_t)gr * 128))[lane] = v;
    }
}

// ---------------------------------------------------------------------------
// Fused tail: out2 = LN2(ctx@Wo^T + bo + Qin); h = relu(out2@W1^T + b1);
// out3 = h@W2^T + b2 + out2; S_u += out3 / l  (atomic pool).
// smem: A split planes (69.6K) + W split planes (69.6K) + O fp32 (67.6K).
// ---------------------------------------------------------------------------
__global__ void __launch_bounds__(256, 1)
tail_kernel(const float* __restrict__ ctx, const float* __restrict__ Qin,
            const unsigned* __restrict__ Wh3, const unsigned* __restrict__ Wl3,
            const float* __restrict__ out_b, const float* __restrict__ fb1,
            const float* __restrict__ fb2,
            const float* __restrict__ lng, const float* __restrict__ lnb,
            const int* __restrict__ batch_ids, const int* __restrict__ lengths,
            float* __restrict__ pool_out, int nrows)
{
    extern __shared__ unsigned smu[];
    unsigned* Ah = smu;                       // [128][PA]
    unsigned* Al = Ah + 128 * PA;
    unsigned* Bh = Al + 128 * PA;
    unsigned* Bl = Bh + 128 * PA;
    float*    O  = (float*)(Bl + 128 * PA);   // [128][132] fp32 out2 / staging
    int tid  = threadIdx.x;
    int row0 = blockIdx.x * 128;
    int lane = tid & 31, wid = tid >> 5;
    int g  = lane >> 2, tq = lane & 3;
    int warpRow = (wid & 1) * 64;
    int warpCol = (wid >> 1) * 32;
    const int WP = 128 * PA;

    // ---- stage 0: split ctx, load Wo
    for (int i = tid; i < 4096; i += 256) {
        int r = i >> 5, q = i & 31;
        int gr = row0 + r;
        float4 a = (gr < nrows) ? ((const float4*)ctx)[(size_t)gr * 32 + q]
                                : make_float4(0.f, 0.f, 0.f, 0.f);
        unsigned h0, l0, h1, l1;
        bsplit2(a.x, a.y, h0, l0);
        bsplit2(a.z, a.w, h1, l1);
        Ah[r * PA + 2 * q]     = h0;  Ah[r * PA + 2 * q + 1] = h1;
        Al[r * PA + 2 * q]     = l0;  Al[r * PA + 2 * q + 1] = l1;
    }
    for (int i = tid; i < 2176; i += 256) {
        ((uint4*)Bh)[i] = ((const uint4*)Wh3)[i];
        ((uint4*)Bl)[i] = ((const uint4*)Wl3)[i];
    }
    __syncthreads();

    float d[4][4][4];
    mma_block128(Ah, Al, Bh, Bl, d, warpRow, warpCol, g, tq);
    __syncthreads();   // all reads of Ah/Al (ctx) done

    // stage frags to O
    #pragma unroll
    for (int i = 0; i < 4; ++i) {
        int r0 = warpRow + i * 16 + g;
        #pragma unroll
        for (int j = 0; j < 4; ++j) {
            int c0 = warpCol + j * 8 + tq * 2;
            *(float2*)&O[r0 * 132 + c0]       = make_float2(d[i][j][0], d[i][j][1]);
            *(float2*)&O[(r0 + 8) * 132 + c0] = make_float2(d[i][j][2], d[i][j][3]);
        }
    }
    __syncthreads();

    // LN pass: +bo +Qin -> LN2 -> O (fp32) and split into A planes
    {
        float4 bo = ((const float4*)out_b)[lane];
        float4 gg = ((const float4*)lng)[lane];
        float4 be = ((const float4*)lnb)[lane];
        for (int r = wid; r < 128; r += 8) {
            int gr = row0 + r;
            float4 v = *(float4*)&O[r * 132 + lane * 4];
            float4 qv = (gr < nrows) ? ((const float4*)(Qin + (size_t)gr * 128))[lane]
                                     : make_float4(0.f, 0.f, 0.f, 0.f);
            v.x += bo.x + qv.x; v.y += bo.y + qv.y;
            v.z += bo.z + qv.z; v.w += bo.w + qv.w;
            float s1 = v.x + v.y + v.z + v.w;
            float s2 = v.x*v.x + v.y*v.y + v.z*v.z + v.w*v.w;
            #pragma unroll
            for (int o = 16; o; o >>= 1) {
                s1 += __shfl_xor_sync(0xffffffffu, s1, o);
                s2 += __shfl_xor_sync(0xffffffffu, s2, o);
            }
            float mu   = s1 * (1.f / 128.f);
            float var  = fmaxf(s2 * (1.f / 128.f) - mu * mu, 0.f);
            float rstd = rsqrtf(var + 1e-8f);
            v.x = (v.x - mu) * rstd * gg.x + be.x;
            v.y = (v.y - mu) * rstd * gg.y + be.y;
            v.z = (v.z - mu) * rstd * gg.z + be.z;
            v.w = (v.w - mu) * rstd * gg.w + be.w;
            *(float4*)&O[r * 132 + lane * 4] = v;
            unsigned h0, l0, h1, l1;
            bsplit2(v.x, v.y, h0, l0);
            bsplit2(v.z, v.w, h1, l1);
            Ah[r * PA + lane * 2]     = h0;  Ah[r * PA + lane * 2 + 1] = h1;
            Al[r * PA + lane * 2]     = l0;  Al[r * PA + lane * 2 + 1] = l1;
        }
    }
    __syncthreads();

    // ---- stage 1: FFN1 (relu)
    for (int i = tid; i < 2176; i += 256) {
        ((uint4*)Bh)[i] = ((const uint4*)(Wh3 + WP))[i];
        ((uint4*)Bl)[i] = ((const uint4*)(Wl3 + WP))[i];
    }
    __syncthreads();
    mma_block128(Ah, Al, Bh, Bl, d, warpRow, warpCol, g, tq);
    __syncthreads();   // done reading out2 split planes

    // h = relu(acc + b1) -> split directly into A planes (row/col owned)
    #pragma unroll
    for (int i = 0; i < 4; ++i) {
        #pragma unroll
        for (int j = 0; j < 4; ++j) {
            int c0 = warpCol + j * 8 + tq * 2;
            float bx = fb1[c0], by = fb1[c0 + 1];
            int r0 = warpRow + i * 16 + g;
            float v0 = fmaxf(d[i][j][0] + bx, 0.f);
            float v1 = fmaxf(d[i][j][1] + by, 0.f);
            float v2 = fmaxf(d[i][j][2] + bx, 0.f);
            float v3 = fmaxf(d[i][j][3] + by, 0.f);
            unsigned h0, l0, h1, l1;
            bsplit2(v0, v1, h0, l0);
            bsplit2(v2, v3, h1, l1);
            int w0 = r0 * PA + (c0 >> 1);
            int w1 = (r0 + 8) * PA + (c0 >> 1);
            Ah[w0] = h0;  Al[w0] = l0;
            Ah[w1] = h1;  Al[w1] = l1;
        }
    }
    __syncthreads();

    // ---- stage 2: FFN2 + residual + pooled atomic accumulation
    for (int i = tid; i < 2176; i += 256) {
        ((uint4*)Bh)[i] = ((const uint4*)(Wh3 + 2 * WP))[i];
        ((uint4*)Bl)[i] = ((const uint4*)(Wl3 + 2 * WP))[i];
    }
    __syncthreads();
    mma_block128(Ah, Al, Bh, Bl, d, warpRow, warpCol, g, tq);

    #pragma unroll
    for (int i = 0; i < 4; ++i) {
        #pragma unroll
        for (int half = 0; half < 2; ++half) {
            int r0 = warpRow + i * 16 + g + half * 8;
            int gr = row0 + r0;
            if (gr >= nrows) continue;
            int bsess = batch_ids[gr];
            float invl = 1.f / (float)lengths[bsess];
            float* outrow = pool_out + (size_t)bsess * 128;
            #pragma unroll
            for (int j = 0; j < 4; ++j) {
                int c0 = warpCol + j * 8 + tq * 2;
                float v0 = d[i][j][2 * half]     + fb2[c0]     + O[r0 * 132 + c0];
                float v1 = d[i][j][2 * half + 1] + fb2[c0 + 1] + O[r0 * 132 + c0 + 1];
                atomicAdd(outrow + c0,     v0 * invl);
                atomicAdd(outrow + c0 + 1, v1 * invl);
            }
        }
    }
}

// ---------------------------------------------------------------------------
// Tensor-core attention per (session, head).
// ---------------------------------------------------------------------------
template<int NCT>
__device__ __forceinline__ void attn_rowtile(
    const unsigned* Qh, const unsigned* Ql,
    const unsigned* Kh, const unsigned* Kl,
    const unsigned* Vh, const unsigned* Vl,
    float* __restrict__ ctx, int n0, int hc, int l, int i0, int g, int tq)
{
    const float scale = 0.17677669529663687f;   // 1/sqrt(32)
    unsigned qah[2][4], qal[2][4];
    #pragma unroll
    for (int kk = 0; kk < 2; ++kk) {
        int base = (i0 + g) * QS + kk * 8 + tq;
        qah[kk][0] = Qh[base];        qah[kk][1] = Qh[base + 8 * QS];
        qah[kk][2] = Qh[base + 4];    qah[kk][3] = Qh[base + 8 * QS + 4];
        qal[kk][0] = Ql[base];        qal[kk][1] = Ql[base + 8 * QS];
        qal[kk][2] = Ql[base + 4];    qal[kk][3] = Ql[base + 8 * QS + 4];
    }
    float sa[NCT][4];
    #pragma unroll
    for (int ct = 0; ct < NCT; ++ct)
        sa[ct][0] = sa[ct][1] = sa[ct][2] = sa[ct][3] = 0.f;

    #pragma unroll
    for (int ct = 0; ct < NCT; ++ct) {
        #pragma unroll
        for (int kk = 0; kk < 2; ++kk) {
            int base = (ct * 8 + g) * QS + kk * 8 + tq;
            unsigned bh0 = Kh[base], bh1 = Kh[base + 4];
            unsigned bl0 = Kl[base], bl1 = Kl[base + 4];
            MMA_BF16(sa[ct][0], sa[ct][1], sa[ct][2], sa[ct][3],
                     qah[kk][0], qah[kk][1], qah[kk][2], qah[kk][3], bh0, bh1);
            MMA_BF16(sa[ct][0], sa[ct][1], sa[ct][2], sa[ct][3],
                     qah[kk][0], qah[kk][1], qah[kk][2], qah[kk][3], bl0, bl1);
            MMA_BF16(sa[ct][0], sa[ct][1], sa[ct][2], sa[ct][3],
                     qal[kk][0], qal[kk][1], qal[kk][2], qal[kk][3], bh0, bh1);
        }
    }

    float m0 = -1e30f, m1 = -1e30f;
    #pragma unroll
    for (int ct = 0; ct < NCT; ++ct) {
        int c0 = ct * 8 + 2 * tq;
        bool v0 = c0 < l, v1 = (c0 + 1) < l;
        sa[ct][0] = v0 ? sa[ct][0] * scale : -1e30f;
        sa[ct][1] = v1 ? sa[ct][1] * scale : -1e30f;
        sa[ct][2] = v0 ? sa[ct][2] * scale : -1e30f;
        sa[ct][3] = v1 ? sa[ct][3] * scale : -1e30f;
        m0 = fmaxf(m0, fmaxf(sa[ct][0], sa[ct][1]));
        m1 = fmaxf(m1, fmaxf(sa[ct][2], sa[ct][3]));
    }
    m0 = fmaxf(m0, __shfl_xor_sync(0xffffffffu, m0, 1));
    m0 = fmaxf(m0, __shfl_xor_sync(0xffffffffu, m0, 2));
    m1 = fmaxf(m1, __shfl_xor_sync(0xffffffffu, m1, 1));
    m1 = fmaxf(m1, __shfl_xor_sync(0xffffffffu, m1, 2));

    float sum0 = 0.f, sum1 = 0.f;
    #pragma unroll
    for (int ct = 0; ct < NCT; ++ct) {
        int c0 = ct * 8 + 2 * tq;
        float e0 = (c0 < l)     ? __expf(sa[ct][0] - m0) : 0.f;
        float e1 = (c0 + 1 < l) ? __expf(sa[ct][1] - m0) : 0.f;
        float e2 = (c0 < l)     ? __expf(sa[ct][2] - m1) : 0.f;
        float e3 = (c0 + 1 < l) ? __expf(sa[ct][3] - m1) : 0.f;
        sa[ct][0] = e0; sa[ct][1] = e1; sa[ct][2] = e2; sa[ct][3] = e3;
        sum0 += e0 + e1; sum1 += e2 + e3;
    }
    sum0 += __shfl_xor_sync(0xffffffffu, sum0, 1);
    sum0 += __shfl_xor_sync(0xffffffffu, sum0, 2);
    sum1 += __shfl_xor_sync(0xffffffffu, sum1, 1);
    sum1 += __shfl_xor_sync(0xffffffffu, sum1, 2);

    float ca[4][4];
    #pragma unroll
    for (int nt = 0; nt < 4; ++nt)
        ca[nt][0] = ca[nt][1] = ca[nt][2] = ca[nt][3] = 0.f;

    #pragma unroll
    for (int kk2 = 0; kk2 < NCT / 2; ++kk2) {
        unsigned pah[4], pal[4];
        bsplit2(sa[2*kk2][0],   sa[2*kk2][1],   pah[0], pal[0]);
        bsplit2(sa[2*kk2][2],   sa[2*kk2][3],   pah[1], pal[1]);
        bsplit2(sa[2*kk2+1][0], sa[2*kk2+1][1], pah[2], pal[2]);
        bsplit2(sa[2*kk2+1][2], sa[2*kk2+1][3], pah[3], pal[3]);
        #pragma unroll
        for (int nt = 0; nt < 4; ++nt) {
            int base = (nt * 8 + g) * VS + kk2 * 8 + tq;
            unsigned bh0 = Vh[base], bh1 = Vh[base + 4];
            unsigned bl0 = Vl[base], bl1 = Vl[base + 4];
            MMA_BF16(ca[nt][0], ca[nt][1], ca[nt][2], ca[nt][3],
                     pah[0], pah[1], pah[2], pah[3], bh0, bh1);
            MMA_BF16(ca[nt][0], ca[nt][1], ca[nt][2], ca[nt][3],
                     pah[0], pah[1], pah[2], pah[3], bl0, bl1);
            MMA_BF16(ca[nt][0], ca[nt][1], ca[nt][2], ca[nt][3],
                     pal[0], pal[1], pal[2], pal[3], bh0, bh1);
        }
    }

    float inv0 = 1.f / sum0;
    float inv1 = 1.f / sum1;
    int r0 = i0 + g, r1 = i0 + 8 + g;
    #pragma unroll
    for (int nt = 0; nt < 4; ++nt) {
        int dcol = nt * 8 + 2 * tq;
        if (r0 < l)
            *(float2*)(ctx + (size_t)(n0 + r0) * 128 + hc + dcol) =
                make_float2(ca[nt][0] * inv0, ca[nt][1] * inv0);
        if (r1 < l)
            *(float2*)(ctx + (size_t)(n0 + r1) * 128 + hc + dcol) =
                make_float2(ca[nt][2] * inv1, ca[nt][3] * inv1);
    }
}

__global__ void __launch_bounds__(128, 1)
attn_mma_kernel(const float* __restrict__ qp, const float* __restrict__ kp,
                const float* __restrict__ vp, float* __restrict__ ctx,
                const int* __restrict__ lengths)
{
    int b = blockIdx.x;
    int h = blockIdx.y;
    int n0 = d_starts[b];
    int l  = lengths[b];
    extern __shared__ unsigned sm[];
    unsigned* Qh = sm;                   // [160][QS]
    unsigned* Ql = Qh + 160 * QS;
    unsigned* Kh = Ql + 160 * QS;
    unsigned* Kl = Kh + 160 * QS;
    unsigned* Vh = Kl + 160 * QS;        // [32][VS]
    unsigned* Vl = Vh + 32 * VS;
    int tid = threadIdx.x;
    int hc  = h * 32;

    // load + split Q, K (rows < l only; garbage beyond l is masked/row-local)
    for (int i = tid; i < l * 16; i += 128) {
        int s = i >> 4, cp = i & 15;
        size_t gi = (((size_t)(n0 + s) * 128 + hc) >> 1) + cp;
        float2 qv = ((const float2*)qp)[gi];
        unsigned hi, lo;
        bsplit2(qv.x, qv.y, hi, lo);
        Qh[s * QS + cp] = hi; Ql[s * QS + cp] = lo;
        float2 kv = ((const float2*)kp)[gi];
        bsplit2(kv.x, kv.y, hi, lo);
        Kh[s * QS + cp] = hi; Kl[s * QS + cp] = lo;
    }
    // V^T packed pairs along sequence
    int njp = (l + 1) >> 1;
    for (int i = tid; i < njp * 32; i += 128) {
        int jp = i >> 5, d = i & 31;
        int j0 = 2 * jp;
        float v0 = vp[(size_t)(n0 + j0) * 128 + hc + d];
        float v1 = (j0 + 1 < l) ? vp[(size_t)(n0 + j0 + 1) * 128 + hc + d] : 0.f;
        unsigned hi, lo;
        bsplit2(v0, v1, hi, lo);
        Vh[d * VS + jp] = hi; Vl[d * VS + jp] = lo;
    }
    // zero ONLY the V padding columns actually read by the PV mma
    int nctm = (l <= 96) ? 12 : ((l <= 128) ? 16 : 20);
    int jmax = nctm * 4;
    for (int i = tid; i < (jmax - njp) * 32; i += 128) {
        int d = i & 31, jp = njp + (i >> 5);
        Vh[d * VS + jp] = 0u;
        Vl[d * VS + jp] = 0u;
    }
    __syncthreads();

    int lane = tid & 31, wid = tid >> 5;
    int g = lane >> 2, tq = lane & 3;
    int nrt = (l + 15) >> 4;

    for (int rt = wid; rt < nrt; rt += 4) {
        int i0 = rt * 16;
        if (l <= 96)
            attn_rowtile<12>(Qh, Ql, Kh, Kl, Vh, Vl, ctx, n0, hc, l, i0, g, tq);
        else if (l <= 128)
            attn_rowtile<16>(Qh, Ql, Kh, Kl, Vh, Vl, ctx, n0, hc, l, i0, g, tq);
        else
            attn_rowtile<20>(Qh, Ql, Kh, Kl, Vh, Vl, ctx, n0, hc, l, i0, g, tq);
    }
}

// ---------------------------------------------------------------------------
extern "C" void kernel_launch(void* const* d_in, const int* in_sizes, int n_in,
                              void* d_out, int out_size)
{
    const float* POI    = (const float*)d_in[0];
    const float* dde    = (const float*)d_in[1];
    const float* attW   = (const float*)d_in[2];
    const float* a_src  = (const float*)d_in[3];
    const float* a_dst  = (const float*)d_in[4];
    const float* in_w   = (const float*)d_in[5];
    const float* in_b   = (const float*)d_in[6];
    const float* out_w  = (const float*)d_in[7];
    const float* out_b  = (const float*)d_in[8];
    const float* ln2g   = (const float*)d_in[11];
    const float* ln2b   = (const float*)d_in[12];
    const float* ln1g   = (const float*)d_in[9];
    const float* ln1b   = (const float*)d_in[10];
    const float* fw1    = (const float*)d_in[13];
    const float* fb1    = (const float*)d_in[14];
    const float* fw2    = (const float*)d_in[15];
    const float* fb2    = (const float*)d_in[16];
    const int* sess_idx  = (const int*)d_in[17];
    const int* edge_dist = (const int*)d_in[18];
    const int* batch_ids = (const int*)d_in[20];
    const int* node_pos  = (const int*)d_in[21];
    const int* lengths   = (const int*)d_in[22];
    int N = in_sizes[17];
    int E = in_sizes[18];
    int B = in_sizes[22];
    float* outp = (float*)d_out;

    float *b0, *b1, *b2, *b3, *b4;
    unsigned *wh, *wl;
    cudaGetSymbolAddress((void**)&b0, g_buf0);
    cudaGetSymbolAddress((void**)&b1, g_buf1);
    cudaGetSymbolAddress((void**)&b2, g_buf2);
    cudaGetSymbolAddress((void**)&b3, g_buf3);
    cudaGetSymbolAddress((void**)&b4, g_buf4);
    cudaGetSymbolAddress((void**)&wh, d_wh);
    cudaGetSymbolAddress((void**)&wl, d_wl);

    const int gemm_smem = 4 * 128 * PA * (int)sizeof(unsigned);                 // ~136 KB
    const int tail_smem = 4 * 128 * PA * (int)sizeof(unsigned)
                        + 128 * 132 * (int)sizeof(float);                       // ~203 KB
    const int attn_smem = (4 * 160 * QS + 2 * 32 * VS) * (int)sizeof(unsigned); // ~72.7 KB
    cudaFuncSetAttribute(gemm_qkv_kernel, cudaFuncAttributeMaxDynamicSharedMemorySize, gemm_smem);
    cudaFuncSetAttribute(tail_kernel,     cudaFuncAttributeMaxDynamicSharedMemorySize, tail_smem);
    cudaFuncSetAttribute(attn_mma_kernel, cudaFuncAttributeMaxDynamicSharedMemorySize, attn_smem);

    scan_kernel<<<1, BMAXS>>>(lengths, B);
    prep_kernel<<<1, 128>>>(attW, a_src, a_dst);
    wsplit_kernel<<<6, 256>>>(in_w, out_w, fw1, fw2);
    zero_out_kernel<<<(out_size + 255) / 256, 256>>>(outp, out_size);

    int items = N + E;
    logits_kernel<<<(items + 7) / 8, 256>>>(POI, dde, sess_idx, edge_dist, N, E);
    gcn_ln1_kernel<<<(N + 7) / 8, 256>>>(POI, sess_idx, batch_ids, node_pos,
                                         lengths, ln1g, ln1b, N);

    int gblocks = (N + 127) / 128;
    const int WP = 128 * PA;
    gemm_qkv_kernel<<<gblocks, 256, gemm_smem>>>(b1, wh,          wl,          in_b,       b2, N);
    gemm_qkv_kernel<<<gblocks, 256, gemm_smem>>>(b0, wh + WP,     wl + WP,     in_b + 128, b3, N);
    gemm_qkv_kernel<<<gblocks, 256, gemm_smem>>>(b0, wh + 2 * WP, wl + 2 * WP, in_b + 256, b4, N);

    dim3 ag(B, 4);
    attn_mma_kernel<<<ag, 128, attn_smem>>>(b2, b3, b4, b0, lengths);

    tail_kernel<<<gblocks, 256, tail_smem>>>(b0, b1, wh + 3 * WP, wl + 3 * WP,
                                             out_b, fb1, fb2, ln2g, ln2b,
                                             batch_ids, lengths, outp, N);
}

// round 8
// speedup vs baseline: 2.6791x; 1.1348x over previous
#include <cuda_runtime.h>
#include <cuda_bf16.h>
#include <math.h>

// ---------------------------------------------------------------------------
// SeqGraphRepNetwork on GB300 — packed formulation.
// R7: logits fused into gcn (all-local edge logits); QKV+LN1 fused into one
//     kernel; head kernels fused; 5 launches total.
// ---------------------------------------------------------------------------

#define NMAX   163840
#define LMAX   160
#define BMAXS  1024
#define PA     68            // gemm smem row stride (words)
#define WPC    (128 * PA)    // words per weight plane
#define QS     20            // attn Q/K smem row stride (words)
#define VS     84            // attn V^T smem row stride (words)

__device__ float d_vsrc[128];
__device__ float d_vdst[128];
__device__ int   d_starts[BMAXS + 1];
__device__ unsigned d_wh[6 * WPC];           // weight hi-plane, gemm layout
__device__ unsigned d_wl[6 * WPC];           // weight lo-plane
__device__ float g_buf0[(size_t)NMAX * 128]; // Hu, later ctx
__device__ float g_buf1[(size_t)NMAX * 128]; // Qin (LN1 output)
__device__ float g_buf2[(size_t)NMAX * 128]; // q proj
__device__ float g_buf3[(size_t)NMAX * 128]; // k proj
__device__ float g_buf4[(size_t)NMAX * 128]; // v proj

// ---------------------------------------------------------------------------
__device__ __forceinline__ void bsplit2(float a0, float a1,
                                        unsigned &hi, unsigned &lo)
{
    __nv_bfloat162 h = __float22bfloat162_rn(make_float2(a0, a1));
    float r0 = a0 - __low2float(h);
    float r1 = a1 - __high2float(h);
    __nv_bfloat162 l = __float22bfloat162_rn(make_float2(r0, r1));
    hi = *(unsigned*)&h;
    lo = *(unsigned*)&l;
}

#define MMA_BF16(d0,d1,d2,d3, a0,a1,a2,a3, b0,b1)                         \
    asm volatile("mma.sync.aligned.m16n8k16.row.col.f32.bf16.bf16.f32 "   \
                 "{%0,%1,%2,%3}, {%4,%5,%6,%7}, {%8,%9}, {%0,%1,%2,%3};"  \
                 : "+f"(d0), "+f"(d1), "+f"(d2), "+f"(d3)                 \
                 : "r"(a0), "r"(a1), "r"(a2), "r"(a3), "r"(b0), "r"(b1))

// 128x128x128 block mma, 3-term error-compensated split-bf16.
__device__ __forceinline__ void mma_block128(
    const unsigned* __restrict__ Ah, const unsigned* __restrict__ Al,
    const unsigned* __restrict__ Bh, const unsigned* __restrict__ Bl,
    float d[4][4][4], int warpRow, int warpCol, int g, int tq)
{
    #pragma unroll
    for (int i = 0; i < 4; ++i)
        #pragma unroll
        for (int j = 0; j < 4; ++j)
            d[i][j][0] = d[i][j][1] = d[i][j][2] = d[i][j][3] = 0.f;

    #pragma unroll
    for (int kk = 0; kk < 8; ++kk) {
        unsigned ah[4][4], al[4][4], bh[4][2], bl[4][2];
        #pragma unroll
        for (int i = 0; i < 4; ++i) {
            int base = (warpRow + i * 16 + g) * PA + kk * 8 + tq;
            ah[i][0] = Ah[base];            ah[i][1] = Ah[base + 8 * PA];
            ah[i][2] = Ah[base + 4];        ah[i][3] = Ah[base + 8 * PA + 4];
            al[i][0] = Al[base];            al[i][1] = Al[base + 8 * PA];
            al[i][2] = Al[base + 4];        al[i][3] = Al[base + 8 * PA + 4];
        }
        #pragma unroll
        for (int j = 0; j < 4; ++j) {
            int base = (warpCol + j * 8 + g) * PA + kk * 8 + tq;
            bh[j][0] = Bh[base];  bh[j][1] = Bh[base + 4];
            bl[j][0] = Bl[base];  bl[j][1] = Bl[base + 4];
        }
        #pragma unroll
        for (int i = 0; i < 4; ++i)
            #pragma unroll
            for (int j = 0; j < 4; ++j) {
                MMA_BF16(d[i][j][0], d[i][j][1], d[i][j][2], d[i][j][3],
                         ah[i][0], ah[i][1], ah[i][2], ah[i][3],
                         bh[j][0], bh[j][1]);
                MMA_BF16(d[i][j][0], d[i][j][1], d[i][j][2], d[i][j][3],
                         ah[i][0], ah[i][1], ah[i][2], ah[i][3],
                         bl[j][0], bl[j][1]);
                MMA_BF16(d[i][j][0], d[i][j][1], d[i][j][2], d[i][j][3],
                         al[i][0], al[i][1], al[i][2], al[i][3],
                         bh[j][0], bh[j][1]);
            }
    }
}

// ---------------------------------------------------------------------------
// Head: block 0 = scan; block 1 = prep vectors; blocks 2-7 = weight split;
// blocks 8-15 = zero the pool output.
// ---------------------------------------------------------------------------
__global__ void head_kernel(const int* __restrict__ lengths, int B,
                            const float* __restrict__ attW,
                            const float* __restrict__ a_src,
                            const float* __restrict__ a_dst,
                            const float* __restrict__ in_w,
                            const float* __restrict__ out_w,
                            const float* __restrict__ fw1,
                            const float* __restrict__ fw2,
                            float* __restrict__ outp, int out_n)
{
    __shared__ int s[BMAXS];
    int blk = blockIdx.x;
    int t = threadIdx.x;
    if (blk == 0) {
        int v = (t < B) ? lengths[t] : 0;
        s[t] = v;
        __syncthreads();
        for (int o = 1; o < BMAXS; o <<= 1) {
            int add = (t >= o) ? s[t - o] : 0;
            __syncthreads();
            s[t] += add;
            __syncthreads();
        }
        if (t < B) d_starts[t] = s[t] - v;
        if (t == B - 1) d_starts[B] = s[t];
    } else if (blk == 1) {
        if (t < 128) {
            float vs = 0.f, vd = 0.f;
            #pragma unroll 4
            for (int k = 0; k < 128; ++k) {
                float w = attW[k * 128 + t];
                vs += a_src[k] * w;
                vd += a_dst[k] * w;
            }
            d_vsrc[t] = vs;
            d_vdst[t] = vd;
        }
    } else if (blk < 8) {
        int m = blk - 2;
        const float* src = (m < 3) ? (in_w + m * 16384)
                         : (m == 3 ? out_w : (m == 4 ? fw1 : fw2));
        unsigned* wh = d_wh + m * WPC;
        unsigned* wl = d_wl + m * WPC;
        for (int i = t; i < 4096; i += 1024) {
            int r = i >> 5, q = i & 31;
            float4 w = ((const float4*)src)[i];
            unsigned h0, l0, h1, l1;
            bsplit2(w.x, w.y, h0, l0);
            bsplit2(w.z, w.w, h1, l1);
            wh[r * PA + 2 * q]     = h0;  wh[r * PA + 2 * q + 1] = h1;
            wl[r * PA + 2 * q]     = l0;  wl[r * PA + 2 * q + 1] = l1;
        }
    } else {
        for (int i = (blk - 8) * 1024 + t; i < out_n; i += 8 * 1024)
            outp[i] = 0.f;
    }
}

// ---------------------------------------------------------------------------
// GCN: warp per node. Edge logits are node-local:
//   L1 = x_n.vsrc + dde[edge_dist[n-1-b]].vsrc  (fwd msg from n-1, if p>0)
//   L2 = x_n.vdst                                (bwd msg from n+1, if p<l-1)
// 2-way softmax (eps 1e-16), aggregate neighbor POI rows -> Hu.
// ---------------------------------------------------------------------------
__global__ void gcn_kernel(const float* __restrict__ POI,
                           const float* __restrict__ dde,
                           const int*   __restrict__ sess_idx,
                           const int*   __restrict__ edge_dist,
                           const int*   __restrict__ batch_ids,
                           const int*   __restrict__ node_pos,
                           const int*   __restrict__ lengths, int N)
{
    int n = blockIdx.x * 8 + (threadIdx.x >> 5);
    if (n >= N) return;
    int lane = threadIdx.x & 31;
    int b = batch_ids[n];
    int p = node_pos[n];
    int l = lengths[b];
    bool h1 = (p > 0);
    bool h2 = (p < l - 1);

    float4 va = ((const float4*)d_vsrc)[lane];
    float4 vb = ((const float4*)d_vdst)[lane];
    float4 xo = ((const float4*)(POI + (size_t)sess_idx[n] * 128))[lane];
    float p1 = xo.x*va.x + xo.y*va.y + xo.z*va.z + xo.w*va.w;
    float p2 = xo.x*vb.x + xo.y*vb.y + xo.z*vb.z + xo.w*vb.w;
    float qq = 0.f;
    if (h1) {
        float4 xe = ((const float4*)(dde + (size_t)edge_dist[n - 1 - b] * 128))[lane];
        qq = xe.x*va.x + xe.y*va.y + xe.z*va.z + xe.w*va.w;
    }
    #pragma unroll
    for (int o = 16; o; o >>= 1) {
        p1 += __shfl_xor_sync(0xffffffffu, p1, o);
        p2 += __shfl_xor_sync(0xffffffffu, p2, o);
        qq += __shfl_xor_sync(0xffffffffu, qq, o);
    }

    float L1 = h1 ? (p1 + qq) : -1e30f;
    float L2 = h2 ? p2 : -1e30f;
    float m  = fmaxf(L1, L2);
    float e1 = h1 ? expf(L1 - m) : 0.f;
    float e2 = h2 ? expf(L2 - m) : 0.f;
    float inv = 1.f / (e1 + e2 + 1e-16f);
    float a1 = e1 * inv, a2 = e2 * inv;

    float4 hu = make_float4(0.f, 0.f, 0.f, 0.f);
    if (h1) {
        float4 x = ((const float4*)(POI + (size_t)sess_idx[n - 1] * 128))[lane];
        hu.x += a1 * x.x; hu.y += a1 * x.y; hu.z += a1 * x.z; hu.w += a1 * x.w;
    }
    if (h2) {
        float4 x = ((const float4*)(POI + (size_t)sess_idx[n + 1] * 128))[lane];
        hu.x += a2 * x.x; hu.y += a2 * x.y; hu.z += a2 * x.z; hu.w += a2 * x.w;
    }
    ((float4*)g_buf0)[(size_t)n * 32 + lane] = hu;
}

// ---------------------------------------------------------------------------
// Fused LN1 + QKV projections. One block = 128 rows.
// smem: Hu planes (69.6K) + Qin planes (69.6K) + B planes (69.6K, also used
// as fp32 staging for the LN pass before the first B load) = 208.9 KB.
// ---------------------------------------------------------------------------
__global__ void __launch_bounds__(256, 1)
qkv_kernel(const float* __restrict__ Hu,
           const unsigned* __restrict__ Wh3, const unsigned* __restrict__ Wl3,
           const float* __restrict__ in_b,
           const float* __restrict__ g1, const float* __restrict__ b1v,
           float* __restrict__ qout, float* __restrict__ kout,
           float* __restrict__ vout, float* __restrict__ qinout, int nrows)
{
    extern __shared__ unsigned smu[];
    unsigned* AhH = smu;
    unsigned* AlH = AhH + WPC;
    unsigned* AhQ = AlH + WPC;
    unsigned* AlQ = AhQ + WPC;
    unsigned* Bh  = AlQ + WPC;
    unsigned* Bl  = Bh + WPC;
    float* stage  = (float*)Bh;          // fp32 Hu staging [128][132]
    int tid  = threadIdx.x;
    int row0 = blockIdx.x * 128;
    int lane = tid & 31, wid = tid >> 5;
    int g  = lane >> 2, tq = lane & 3;
    int warpRow = (wid & 1) * 64;
    int warpCol = (wid >> 1) * 32;

    // phase 1: load Hu block, split planes + fp32 staging
    for (int i = tid; i < 4096; i += 256) {
        int r = i >> 5, q = i & 31;
        int gr = row0 + r;
        float4 a = (gr < nrows) ? ((const float4*)Hu)[(size_t)gr * 32 + q]
                                : make_float4(0.f, 0.f, 0.f, 0.f);
        unsigned h0, l0, h1, l1;
        bsplit2(a.x, a.y, h0, l0);
        bsplit2(a.z, a.w, h1, l1);
        AhH[r * PA + 2 * q]     = h0;  AhH[r * PA + 2 * q + 1] = h1;
        AlH[r * PA + 2 * q]     = l0;  AlH[r * PA + 2 * q + 1] = l1;
        *(float4*)&stage[r * 132 + q * 4] = a;
    }
    __syncthreads();

    // phase 2: LN1 per row -> Qin gmem + Qin split planes
    {
        float4 gg = ((const float4*)g1)[lane];
        float4 bb = ((const float4*)b1v)[lane];
        for (int r = wid; r < 128; r += 8) {
            float4 v = *(float4*)&stage[r * 132 + lane * 4];
            float s1 = v.x + v.y + v.z + v.w;
            float s2 = v.x*v.x + v.y*v.y + v.z*v.z + v.w*v.w;
            #pragma unroll
            for (int o = 16; o; o >>= 1) {
                s1 += __shfl_xor_sync(0xffffffffu, s1, o);
                s2 += __shfl_xor_sync(0xffffffffu, s2, o);
            }
            float mu   = s1 * (1.f / 128.f);
            float var  = fmaxf(s2 * (1.f / 128.f) - mu * mu, 0.f);
            float rstd = rsqrtf(var + 1e-8f);
            float4 o4;
            o4.x = (v.x - mu) * rstd * gg.x + bb.x;
            o4.y = (v.y - mu) * rstd * gg.y + bb.y;
            o4.z = (v.z - mu) * rstd * gg.z + bb.z;
            o4.w = (v.w - mu) * rstd * gg.w + bb.w;
            int gr = row0 + r;
            if (gr < nrows)
                ((float4*)(qinout + (size_t)gr * 128))[lane] = o4;
            unsigned h0, l0, h1, l1;
            bsplit2(o4.x, o4.y, h0, l0);
            bsplit2(o4.z, o4.w, h1, l1);
            AhQ[r * PA + lane * 2]     = h0;  AhQ[r * PA + lane * 2 + 1] = h1;
            AlQ[r * PA + lane * 2]     = l0;  AlQ[r * PA + lane * 2 + 1] = l1;
        }
    }

    // three projection stages
    float d[4][4][4];
    for (int s = 0; s < 3; ++s) {
        __syncthreads();    // staging reads / prior mma B reads complete
        const uint4* wh4 = (const uint4*)(Wh3 + s * WPC);
        const uint4* wl4 = (const uint4*)(Wl3 + s * WPC);
        for (int i = tid; i < 2176; i += 256) {
            ((uint4*)Bh)[i] = wh4[i];
            ((uint4*)Bl)[i] = wl4[i];
        }
        __syncthreads();
        const unsigned* Ah = (s == 0) ? AhQ : AhH;
        const unsigned* Al = (s == 0) ? AlQ : AlH;
        mma_block128(Ah, Al, Bh, Bl, d, warpRow, warpCol, g, tq);

        float* op = (s == 0) ? qout : ((s == 1) ? kout : vout);
        const float* bias = in_b + s * 128;
        #pragma unroll
        for (int j = 0; j < 4; ++j) {
            int c0 = warpCol + j * 8 + tq * 2;
            float bj0 = bias[c0], bj1 = bias[c0 + 1];
            #pragma unroll
            for (int i = 0; i < 4; ++i) {
                int r0 = warpRow + i * 16 + g;
                int gr = row0 + r0;
                if (gr < nrows)
                    *(float2*)(op + (size_t)gr * 128 + c0) =
                        make_float2(d[i][j][0] + bj0, d[i][j][1] + bj1);
                if (gr + 8 < nrows)
                    *(float2*)(op + (size_t)(gr + 8) * 128 + c0) =
                        make_float2(d[i][j][2] + bj0, d[i][j][3] + bj1);
            }
        }
    }
}

// ---------------------------------------------------------------------------
// Fused tail: out2 = LN2(ctx@Wo^T + bo + Qin); h = relu(out2@W1^T + b1);
// out3 = h@W2^T + b2 + out2; S_u += out3 / l  (atomic pool).
// ---------------------------------------------------------------------------
__global__ void __launch_bounds__(256, 1)
tail_kernel(const float* __restrict__ ctx, const float* __restrict__ Qin,
            const unsigned* __restrict__ Wh3, const unsigned* __restrict__ Wl3,
            const float* __restrict__ out_b, const float* __restrict__ fb1,
            const float* __restrict__ fb2,
            const float* __restrict__ lng, const float* __restrict__ lnb,
            const int* __restrict__ batch_ids, const int* __restrict__ lengths,
            float* __restrict__ pool_out, int nrows)
{
    extern __shared__ unsigned smu[];
    unsigned* Ah = smu;                       // [128][PA]
    unsigned* Al = Ah + WPC;
    unsigned* Bh = Al + WPC;
    unsigned* Bl = Bh + WPC;
    float*    O  = (float*)(Bl + WPC);        // [128][132] fp32 out2
    int tid  = threadIdx.x;
    int row0 = blockIdx.x * 128;
    int lane = tid & 31, wid = tid >> 5;
    int g  = lane >> 2, tq = lane & 3;
    int warpRow = (wid & 1) * 64;
    int warpCol = (wid >> 1) * 32;

    for (int i = tid; i < 4096; i += 256) {
        int r = i >> 5, q = i & 31;
        int gr = row0 + r;
        float4 a = (gr < nrows) ? ((const float4*)ctx)[(size_t)gr * 32 + q]
                                : make_float4(0.f, 0.f, 0.f, 0.f);
        unsigned h0, l0, h1, l1;
        bsplit2(a.x, a.y, h0, l0);
        bsplit2(a.z, a.w, h1, l1);
        Ah[r * PA + 2 * q]     = h0;  Ah[r * PA + 2 * q + 1] = h1;
        Al[r * PA + 2 * q]     = l0;  Al[r * PA + 2 * q + 1] = l1;
    }
    for (int i = tid; i < 2176; i += 256) {
        ((uint4*)Bh)[i] = ((const uint4*)Wh3)[i];
        ((uint4*)Bl)[i] = ((const uint4*)Wl3)[i];
    }
    __syncthreads();

    float d[4][4][4];
    mma_block128(Ah, Al, Bh, Bl, d, warpRow, warpCol, g, tq);
    __syncthreads();

    #pragma unroll
    for (int i = 0; i < 4; ++i) {
        int r0 = warpRow + i * 16 + g;
        #pragma unroll
        for (int j = 0; j < 4; ++j) {
            int c0 = warpCol + j * 8 + tq * 2;
            *(float2*)&O[r0 * 132 + c0]       = make_float2(d[i][j][0], d[i][j][1]);
            *(float2*)&O[(r0 + 8) * 132 + c0] = make_float2(d[i][j][2], d[i][j][3]);
        }
    }
    __syncthreads();

    {
        float4 bo = ((const float4*)out_b)[lane];
        float4 gg = ((const float4*)lng)[lane];
        float4 be = ((const float4*)lnb)[lane];
        for (int r = wid; r < 128; r += 8) {
            int gr = row0 + r;
            float4 v = *(float4*)&O[r * 132 + lane * 4];
            float4 qv = (gr < nrows) ? ((const float4*)(Qin + (size_t)gr * 128))[lane]
                                     : make_float4(0.f, 0.f, 0.f, 0.f);
            v.x += bo.x + qv.x; v.y += bo.y + qv.y;
            v.z += bo.z + qv.z; v.w += bo.w + qv.w;
            float s1 = v.x + v.y + v.z + v.w;
            float s2 = v.x*v.x + v.y*v.y + v.z*v.z + v.w*v.w;
            #pragma unroll
            for (int o = 16; o; o >>= 1) {
                s1 += __shfl_xor_sync(0xffffffffu, s1, o);
                s2 += __shfl_xor_sync(0xffffffffu, s2, o);
            }
            float mu   = s1 * (1.f / 128.f);
            float var  = fmaxf(s2 * (1.f / 128.f) - mu * mu, 0.f);
            float rstd = rsqrtf(var + 1e-8f);
            v.x = (v.x - mu) * rstd * gg.x + be.x;
            v.y = (v.y - mu) * rstd * gg.y + be.y;
            v.z = (v.z - mu) * rstd * gg.z + be.z;
            v.w = (v.w - mu) * rstd * gg.w + be.w;
            *(float4*)&O[r * 132 + lane * 4] = v;
            unsigned h0, l0, h1, l1;
            bsplit2(v.x, v.y, h0, l0);
            bsplit2(v.z, v.w, h1, l1);
            Ah[r * PA + lane * 2]     = h0;  Ah[r * PA + lane * 2 + 1] = h1;
            Al[r * PA + lane * 2]     = l0;  Al[r * PA + lane * 2 + 1] = l1;
        }
    }
    __syncthreads();

    for (int i = tid; i < 2176; i += 256) {
        ((uint4*)Bh)[i] = ((const uint4*)(Wh3 + WPC))[i];
        ((uint4*)Bl)[i] = ((const uint4*)(Wl3 + WPC))[i];
    }
    __syncthreads();
    mma_block128(Ah, Al, Bh, Bl, d, warpRow, warpCol, g, tq);
    __syncthreads();

    #pragma unroll
    for (int i = 0; i < 4; ++i) {
        #pragma unroll
        for (int j = 0; j < 4; ++j) {
            int c0 = warpCol + j * 8 + tq * 2;
            float bx = fb1[c0], by = fb1[c0 + 1];
            int r0 = warpRow + i * 16 + g;
            float v0 = fmaxf(d[i][j][0] + bx, 0.f);
            float v1 = fmaxf(d[i][j][1] + by, 0.f);
            float v2 = fmaxf(d[i][j][2] + bx, 0.f);
            float v3 = fmaxf(d[i][j][3] + by, 0.f);
            unsigned h0, l0, h1, l1;
            bsplit2(v0, v1, h0, l0);
            bsplit2(v2, v3, h1, l1);
            int w0 = r0 * PA + (c0 >> 1);
            int w1 = (r0 + 8) * PA + (c0 >> 1);
            Ah[w0] = h0;  Al[w0] = l0;
            Ah[w1] = h1;  Al[w1] = l1;
        }
    }
    __syncthreads();

    for (int i = tid; i < 2176; i += 256) {
        ((uint4*)Bh)[i] = ((const uint4*)(Wh3 + 2 * WPC))[i];
        ((uint4*)Bl)[i] = ((const uint4*)(Wl3 + 2 * WPC))[i];
    }
    __syncthreads();
    mma_block128(Ah, Al, Bh, Bl, d, warpRow, warpCol, g, tq);

    #pragma unroll
    for (int i = 0; i < 4; ++i) {
        #pragma unroll
        for (int half = 0; half < 2; ++half) {
            int r0 = warpRow + i * 16 + g + half * 8;
            int gr = row0 + r0;
            if (gr >= nrows) continue;
            int bsess = batch_ids[gr];
            float invl = 1.f / (float)lengths[bsess];
            float* outrow = pool_out + (size_t)bsess * 128;
            #pragma unroll
            for (int j = 0; j < 4; ++j) {
                int c0 = warpCol + j * 8 + tq * 2;
                float v0 = d[i][j][2 * half]     + fb2[c0]     + O[r0 * 132 + c0];
                float v1 = d[i][j][2 * half + 1] + fb2[c0 + 1] + O[r0 * 132 + c0 + 1];
                atomicAdd(outrow + c0,     v0 * invl);
                atomicAdd(outrow + c0 + 1, v1 * invl);
            }
        }
    }
}

// ---------------------------------------------------------------------------
// Tensor-core attention per (session, head). 256 threads, 8 warps.
// ---------------------------------------------------------------------------
template<int NCT>
__device__ __forceinline__ void attn_rowtile(
    const unsigned* Qh, const unsigned* Ql,
    const unsigned* Kh, const unsigned* Kl,
    const unsigned* Vh, const unsigned* Vl,
    float* __restrict__ ctx, int n0, int hc, int l, int i0, int g, int tq)
{
    const float scale = 0.17677669529663687f;   // 1/sqrt(32)
    unsigned qah[2][4], qal[2][4];
    #pragma unroll
    for (int kk = 0; kk < 2; ++kk) {
        int base = (i0 + g) * QS + kk * 8 + tq;
        qah[kk][0] = Qh[base];        qah[kk][1] = Qh[base + 8 * QS];
        qah[kk][2] = Qh[base + 4];    qah[kk][3] = Qh[base + 8 * QS + 4];
        qal[kk][0] = Ql[base];        qal[kk][1] = Ql[base + 8 * QS];
        qal[kk][2] = Ql[base + 4];    qal[kk][3] = Ql[base + 8 * QS + 4];
    }
    float sa[NCT][4];
    #pragma unroll
    for (int ct = 0; ct < NCT; ++ct)
        sa[ct][0] = sa[ct][1] = sa[ct][2] = sa[ct][3] = 0.f;

    #pragma unroll
    for (int ct = 0; ct < NCT; ++ct) {
        #pragma unroll
        for (int kk = 0; kk < 2; ++kk) {
            int base = (ct * 8 + g) * QS + kk * 8 + tq;
            unsigned bh0 = Kh[base], bh1 = Kh[base + 4];
            unsigned bl0 = Kl[base], bl1 = Kl[base + 4];
            MMA_BF16(sa[ct][0], sa[ct][1], sa[ct][2], sa[ct][3],
                     qah[kk][0], qah[kk][1], qah[kk][2], qah[kk][3], bh0, bh1);
            MMA_BF16(sa[ct][0], sa[ct][1], sa[ct][2], sa[ct][3],
                     qah[kk][0], qah[kk][1], qah[kk][2], qah[kk][3], bl0, bl1);
            MMA_BF16(sa[ct][0], sa[ct][1], sa[ct][2], sa[ct][3],
                     qal[kk][0], qal[kk][1], qal[kk][2], qal[kk][3], bh0, bh1);
        }
    }

    float m0 = -1e30f, m1 = -1e30f;
    #pragma unroll
    for (int ct = 0; ct < NCT; ++ct) {
        int c0 = ct * 8 + 2 * tq;
        bool v0 = c0 < l, v1 = (c0 + 1) < l;
        sa[ct][0] = v0 ? sa[ct][0] * scale : -1e30f;
        sa[ct][1] = v1 ? sa[ct][1] * scale : -1e30f;
        sa[ct][2] = v0 ? sa[ct][2] * scale : -1e30f;
        sa[ct][3] = v1 ? sa[ct][3] * scale : -1e30f;
        m0 = fmaxf(m0, fmaxf(sa[ct][0], sa[ct][1]));
        m1 = fmaxf(m1, fmaxf(sa[ct][2], sa[ct][3]));
    }
    m0 = fmaxf(m0, __shfl_xor_sync(0xffffffffu, m0, 1));
    m0 = fmaxf(m0, __shfl_xor_sync(0xffffffffu, m0, 2));
    m1 = fmaxf(m1, __shfl_xor_sync(0xffffffffu, m1, 1));
    m1 = fmaxf(m1, __shfl_xor_sync(0xffffffffu, m1, 2));

    float sum0 = 0.f, sum1 = 0.f;
    #pragma unroll
    for (int ct = 0; ct < NCT; ++ct) {
        int c0 = ct * 8 + 2 * tq;
        float e0 = (c0 < l)     ? __expf(sa[ct][0] - m0) : 0.f;
        float e1 = (c0 + 1 < l) ? __expf(sa[ct][1] - m0) : 0.f;
        float e2 = (c0 < l)     ? __expf(sa[ct][2] - m1) : 0.f;
        float e3 = (c0 + 1 < l) ? __expf(sa[ct][3] - m1) : 0.f;
        sa[ct][0] = e0; sa[ct][1] = e1; sa[ct][2] = e2; sa[ct][3] = e3;
        sum0 += e0 + e1; sum1 += e2 + e3;
    }
    sum0 += __shfl_xor_sync(0xffffffffu, sum0, 1);
    sum0 += __shfl_xor_sync(0xffffffffu, sum0, 2);
    sum1 += __shfl_xor_sync(0xffffffffu, sum1, 1);
    sum1 += __shfl_xor_sync(0xffffffffu, sum1, 2);

    float ca[4][4];
    #pragma unroll
    for (int nt = 0; nt < 4; ++nt)
        ca[nt][0] = ca[nt][1] = ca[nt][2] = ca[nt][3] = 0.f;

    #pragma unroll
    for (int kk2 = 0; kk2 < NCT / 2; ++kk2) {
        unsigned pah[4], pal[4];
        bsplit2(sa[2*kk2][0],   sa[2*kk2][1],   pah[0], pal[0]);
        bsplit2(sa[2*kk2][2],   sa[2*kk2][3],   pah[1], pal[1]);
        bsplit2(sa[2*kk2+1][0], sa[2*kk2+1][1], pah[2], pal[2]);
        bsplit2(sa[2*kk2+1][2], sa[2*kk2+1][3], pah[3], pal[3]);
        #pragma unroll
        for (int nt = 0; nt < 4; ++nt) {
            int base = (nt * 8 + g) * VS + kk2 * 8 + tq;
            unsigned bh0 = Vh[base], bh1 = Vh[base + 4];
            unsigned bl0 = Vl[base], bl1 = Vl[base + 4];
            MMA_BF16(ca[nt][0], ca[nt][1], ca[nt][2], ca[nt][3],
                     pah[0], pah[1], pah[2], pah[3], bh0, bh1);
            MMA_BF16(ca[nt][0], ca[nt][1], ca[nt][2], ca[nt][3],
                     pah[0], pah[1], pah[2], pah[3], bl0, bl1);
            MMA_BF16(ca[nt][0], ca[nt][1], ca[nt][2], ca[nt][3],
                     pal[0], pal[1], pal[2], pal[3], bh0, bh1);
        }
    }

    float inv0 = 1.f / sum0;
    float inv1 = 1.f / sum1;
    int r0 = i0 + g, r1 = i0 + 8 + g;
    #pragma unroll
    for (int nt = 0; nt < 4; ++nt) {
        int dcol = nt * 8 + 2 * tq;
        if (r0 < l)
            *(float2*)(ctx + (size_t)(n0 + r0) * 128 + hc + dcol) =
                make_float2(ca[nt][0] * inv0, ca[nt][1] * inv0);
        if (r1 < l)
            *(float2*)(ctx + (size_t)(n0 + r1) * 128 + hc + dcol) =
                make_float2(ca[nt][2] * inv1, ca[nt][3] * inv1);
    }
}

__global__ void __launch_bounds__(256, 1)
attn_mma_kernel(const float* __restrict__ qp, const float* __restrict__ kp,
                const float* __restrict__ vp, float* __restrict__ ctx,
                const int* __restrict__ lengths)
{
    int b = blockIdx.x;
    int h = blockIdx.y;
    int n0 = d_starts[b];
    int l  = lengths[b];
    extern __shared__ unsigned sm[];
    unsigned* Qh = sm;                   // [160][QS]
    unsigned* Ql = Qh + 160 * QS;
    unsigned* Kh = Ql + 160 * QS;
    unsigned* Kl = Kh + 160 * QS;
    unsigned* Vh = Kl + 160 * QS;        // [32][VS]
    unsigned* Vl = Vh + 32 * VS;
    int tid = threadIdx.x;
    int hc  = h * 32;

    for (int i = tid; i < l * 16; i += 256) {
        int s = i >> 4, cp = i & 15;
        size_t gi = (((size_t)(n0 + s) * 128 + hc) >> 1) + cp;
        float2 qv = ((const float2*)qp)[gi];
        unsigned hi, lo;
        bsplit2(qv.x, qv.y, hi, lo);
        Qh[s * QS + cp] = hi; Ql[s * QS + cp] = lo;
        float2 kv = ((const float2*)kp)[gi];
        bsplit2(kv.x, kv.y, hi, lo);
        Kh[s * QS + cp] = hi; Kl[s * QS + cp] = lo;
    }
    int njp = (l + 1) >> 1;
    for (int i = tid; i < njp * 32; i += 256) {
        int jp = i >> 5, d = i & 31;
        int j0 = 2 * jp;
        float v0 = vp[(size_t)(n0 + j0) * 128 + hc + d];
        float v1 = (j0 + 1 < l) ? vp[(size_t)(n0 + j0 + 1) * 128 + hc + d] : 0.f;
        unsigned hi, lo;
        bsplit2(v0, v1, hi, lo);
        Vh[d * VS + jp] = hi; Vl[d * VS + jp] = lo;
    }
    int nctm = (l <= 96) ? 12 : ((l <= 128) ? 16 : 20);
    int jmax = nctm * 4;
    for (int i = tid; i < (jmax - njp) * 32; i += 256) {
        int d = i & 31, jp = njp + (i >> 5);
        Vh[d * VS + jp] = 0u;
        Vl[d * VS + jp] = 0u;
    }
    __syncthreads();

    int lane = tid & 31, wid = tid >> 5;
    int g = lane >> 2, tq = lane & 3;
    int nrt = (l + 15) >> 4;

    for (int rt = wid; rt < nrt; rt += 8) {
        int i0 = rt * 16;
        if (l <= 96)
            attn_rowtile<12>(Qh, Ql, Kh, Kl, Vh, Vl, ctx, n0, hc, l, i0, g, tq);
        else if (l <= 128)
            attn_rowtile<16>(Qh, Ql, Kh, Kl, Vh, Vl, ctx, n0, hc, l, i0, g, tq);
        else
            attn_rowtile<20>(Qh, Ql, Kh, Kl, Vh, Vl, ctx, n0, hc, l, i0, g, tq);
    }
}

// ---------------------------------------------------------------------------
extern "C" void kernel_launch(void* const* d_in, const int* in_sizes, int n_in,
                              void* d_out, int out_size)
{
    const float* POI    = (const float*)d_in[0];
    const float* dde    = (const float*)d_in[1];
    const float* attW   = (const float*)d_in[2];
    const float* a_src  = (const float*)d_in[3];
    const float* a_dst  = (const float*)d_in[4];
    const float* in_w   = (const float*)d_in[5];
    const float* in_b   = (const float*)d_in[6];
    const float* out_w  = (const float*)d_in[7];
    const float* out_b  = (const float*)d_in[8];
    const float* ln1g   = (const float*)d_in[9];
    const float* ln1b   = (const float*)d_in[10];
    const float* ln2g   = (const float*)d_in[11];
    const float* ln2b   = (const float*)d_in[12];
    const float* fw1    = (const float*)d_in[13];
    const float* fb1    = (const float*)d_in[14];
    const float* fw2    = (const float*)d_in[15];
    const float* fb2    = (const float*)d_in[16];
    const int* sess_idx  = (const int*)d_in[17];
    const int* edge_dist = (const int*)d_in[18];
    const int* batch_ids = (const int*)d_in[20];
    const int* node_pos  = (const int*)d_in[21];
    const int* lengths   = (const int*)d_in[22];
    int N = in_sizes[17];
    int B = in_sizes[22];
    float* outp = (float*)d_out;

    float *b0, *b1, *b2, *b3, *b4;
    unsigned *wh, *wl;
    cudaGetSymbolAddress((void**)&b0, g_buf0);
    cudaGetSymbolAddress((void**)&b1, g_buf1);
    cudaGetSymbolAddress((void**)&b2, g_buf2);
    cudaGetSymbolAddress((void**)&b3, g_buf3);
    cudaGetSymbolAddress((void**)&b4, g_buf4);
    cudaGetSymbolAddress((void**)&wh, d_wh);
    cudaGetSymbolAddress((void**)&wl, d_wl);

    const int qkv_smem  = 6 * WPC * (int)sizeof(unsigned);                       // ~208.9 KB
    const int tail_smem = 4 * WPC * (int)sizeof(unsigned)
                        + 128 * 132 * (int)sizeof(float);                        // ~206.8 KB
    const int attn_smem = (4 * 160 * QS + 2 * 32 * VS) * (int)sizeof(unsigned);  // ~72.7 KB
    cudaFuncSetAttribute(qkv_kernel,      cudaFuncAttributeMaxDynamicSharedMemorySize, qkv_smem);
    cudaFuncSetAttribute(tail_kernel,     cudaFuncAttributeMaxDynamicSharedMemorySize, tail_smem);
    cudaFuncSetAttribute(attn_mma_kernel, cudaFuncAttributeMaxDynamicSharedMemorySize, attn_smem);

    head_kernel<<<16, 1024>>>(lengths, B, attW, a_src, a_dst,
                              in_w, out_w, fw1, fw2, outp, out_size);

    gcn_kernel<<<(N + 7) / 8, 256>>>(POI, dde, sess_idx, edge_dist,
                                     batch_ids, node_pos, lengths, N);

    int gblocks = (N + 127) / 128;
    qkv_kernel<<<gblocks, 256, qkv_smem>>>(b0, wh, wl, in_b, ln1g, ln1b,
                                           b2, b3, b4, b1, N);

    dim3 ag(B, 4);
    attn_mma_kernel<<<ag, 256, attn_smem>>>(b2, b3, b4, b0, lengths);

    tail_kernel<<<gblocks, 256, tail_smem>>>(b0, b1, wh + 3 * WPC, wl + 3 * WPC,
                                             out_b, fb1, fb2, ln2g, ln2b,
                                             batch_ids, lengths, outp, N);
}

// round 10
// speedup vs baseline: 3.1059x; 1.1593x over previous
#include <cuda_runtime.h>
#include <cuda_bf16.h>
#include <math.h>

// ---------------------------------------------------------------------------
// SeqGraphRepNetwork on GB300 — packed formulation.
// R9: attention -> online-softmax column chunking (sa[4][4] live instead of
//     sa[20][4]) + __launch_bounds__(256,2): 2 blocks/SM instead of 1.
// ---------------------------------------------------------------------------

#define NMAX   163840
#define LMAX   160
#define BMAXS  1024
#define PA     68            // gemm smem row stride (words)
#define WPC    (128 * PA)    // words per weight plane
#define QS     20            // attn Q/K smem row stride (words)
#define VS     84            // attn V^T smem row stride (words)

__device__ float d_vsrc[128];
__device__ float d_vdst[128];
__device__ int   d_starts[BMAXS + 1];
__device__ unsigned d_wh[6 * WPC];           // weight hi-plane, gemm layout
__device__ unsigned d_wl[6 * WPC];           // weight lo-plane
__device__ float g_buf0[(size_t)NMAX * 128]; // Hu, later ctx
__device__ float g_buf1[(size_t)NMAX * 128]; // Qin (LN1 output)
__device__ float g_buf2[(size_t)NMAX * 128]; // q proj
__device__ float g_buf3[(size_t)NMAX * 128]; // k proj
__device__ float g_buf4[(size_t)NMAX * 128]; // v proj

// ---------------------------------------------------------------------------
__device__ __forceinline__ void bsplit2(float a0, float a1,
                                        unsigned &hi, unsigned &lo)
{
    __nv_bfloat162 h = __float22bfloat162_rn(make_float2(a0, a1));
    float r0 = a0 - __low2float(h);
    float r1 = a1 - __high2float(h);
    __nv_bfloat162 l = __float22bfloat162_rn(make_float2(r0, r1));
    hi = *(unsigned*)&h;
    lo = *(unsigned*)&l;
}

#define MMA_BF16(d0,d1,d2,d3, a0,a1,a2,a3, b0,b1)                         \
    asm volatile("mma.sync.aligned.m16n8k16.row.col.f32.bf16.bf16.f32 "   \
                 "{%0,%1,%2,%3}, {%4,%5,%6,%7}, {%8,%9}, {%0,%1,%2,%3};"  \
                 : "+f"(d0), "+f"(d1), "+f"(d2), "+f"(d3)                 \
                 : "r"(a0), "r"(a1), "r"(a2), "r"(a3), "r"(b0), "r"(b1))

// 128x128x128 block mma, 3-term error-compensated split-bf16.
__device__ __forceinline__ void mma_block128(
    const unsigned* __restrict__ Ah, const unsigned* __restrict__ Al,
    const unsigned* __restrict__ Bh, const unsigned* __restrict__ Bl,
    float d[4][4][4], int warpRow, int warpCol, int g, int tq)
{
    #pragma unroll
    for (int i = 0; i < 4; ++i)
        #pragma unroll
        for (int j = 0; j < 4; ++j)
            d[i][j][0] = d[i][j][1] = d[i][j][2] = d[i][j][3] = 0.f;

    #pragma unroll
    for (int kk = 0; kk < 8; ++kk) {
        unsigned ah[4][4], al[4][4], bh[4][2], bl[4][2];
        #pragma unroll
        for (int i = 0; i < 4; ++i) {
            int base = (warpRow + i * 16 + g) * PA + kk * 8 + tq;
            ah[i][0] = Ah[base];            ah[i][1] = Ah[base + 8 * PA];
            ah[i][2] = Ah[base + 4];        ah[i][3] = Ah[base + 8 * PA + 4];
            al[i][0] = Al[base];            al[i][1] = Al[base + 8 * PA];
            al[i][2] = Al[base + 4];        al[i][3] = Al[base + 8 * PA + 4];
        }
        #pragma unroll
        for (int j = 0; j < 4; ++j) {
            int base = (warpCol + j * 8 + g) * PA + kk * 8 + tq;
            bh[j][0] = Bh[base];  bh[j][1] = Bh[base + 4];
            bl[j][0] = Bl[base];  bl[j][1] = Bl[base + 4];
        }
        #pragma unroll
        for (int i = 0; i < 4; ++i)
            #pragma unroll
            for (int j = 0; j < 4; ++j) {
                MMA_BF16(d[i][j][0], d[i][j][1], d[i][j][2], d[i][j][3],
                         ah[i][0], ah[i][1], ah[i][2], ah[i][3],
                         bh[j][0], bh[j][1]);
                MMA_BF16(d[i][j][0], d[i][j][1], d[i][j][2], d[i][j][3],
                         ah[i][0], ah[i][1], ah[i][2], ah[i][3],
                         bl[j][0], bl[j][1]);
                MMA_BF16(d[i][j][0], d[i][j][1], d[i][j][2], d[i][j][3],
                         al[i][0], al[i][1], al[i][2], al[i][3],
                         bh[j][0], bh[j][1]);
            }
    }
}

// ---------------------------------------------------------------------------
// Head: block 0 = scan; block 1 = prep vectors; blocks 2-7 = weight split;
// blocks 8-15 = zero the pool output.
// ---------------------------------------------------------------------------
__global__ void head_kernel(const int* __restrict__ lengths, int B,
                            const float* __restrict__ attW,
                            const float* __restrict__ a_src,
                            const float* __restrict__ a_dst,
                            const float* __restrict__ in_w,
                            const float* __restrict__ out_w,
                            const float* __restrict__ fw1,
                            const float* __restrict__ fw2,
                            float* __restrict__ outp, int out_n)
{
    __shared__ int s[BMAXS];
    int blk = blockIdx.x;
    int t = threadIdx.x;
    if (blk == 0) {
        int v = (t < B) ? lengths[t] : 0;
        s[t] = v;
        __syncthreads();
        for (int o = 1; o < BMAXS; o <<= 1) {
            int add = (t >= o) ? s[t - o] : 0;
            __syncthreads();
            s[t] += add;
            __syncthreads();
        }
        if (t < B) d_starts[t] = s[t] - v;
        if (t == B - 1) d_starts[B] = s[t];
    } else if (blk == 1) {
        if (t < 128) {
            float vs = 0.f, vd = 0.f;
            #pragma unroll 4
            for (int k = 0; k < 128; ++k) {
                float w = attW[k * 128 + t];
                vs += a_src[k] * w;
                vd += a_dst[k] * w;
            }
            d_vsrc[t] = vs;
            d_vdst[t] = vd;
        }
    } else if (blk < 8) {
        int m = blk - 2;
        const float* src = (m < 3) ? (in_w + m * 16384)
                         : (m == 3 ? out_w : (m == 4 ? fw1 : fw2));
        unsigned* wh = d_wh + m * WPC;
        unsigned* wl = d_wl + m * WPC;
        for (int i = t; i < 4096; i += 1024) {
            int r = i >> 5, q = i & 31;
            float4 w = ((const float4*)src)[i];
            unsigned h0, l0, h1, l1;
            bsplit2(w.x, w.y, h0, l0);
            bsplit2(w.z, w.w, h1, l1);
            wh[r * PA + 2 * q]     = h0;  wh[r * PA + 2 * q + 1] = h1;
            wl[r * PA + 2 * q]     = l0;  wl[r * PA + 2 * q + 1] = l1;
        }
    } else {
        for (int i = (blk - 8) * 1024 + t; i < out_n; i += 8 * 1024)
            outp[i] = 0.f;
    }
}

// ---------------------------------------------------------------------------
// GCN: warp per node; node-local edge logits; 2-way softmax aggregate.
// ---------------------------------------------------------------------------
__global__ void gcn_kernel(const float* __restrict__ POI,
                           const float* __restrict__ dde,
                           const int*   __restrict__ sess_idx,
                           const int*   __restrict__ edge_dist,
                           const int*   __restrict__ batch_ids,
                           const int*   __restrict__ node_pos,
                           const int*   __restrict__ lengths, int N)
{
    int n = blockIdx.x * 8 + (threadIdx.x >> 5);
    if (n >= N) return;
    int lane = threadIdx.x & 31;
    int b = batch_ids[n];
    int p = node_pos[n];
    int l = lengths[b];
    bool h1 = (p > 0);
    bool h2 = (p < l - 1);

    float4 va = ((const float4*)d_vsrc)[lane];
    float4 vb = ((const float4*)d_vdst)[lane];
    float4 xo = ((const float4*)(POI + (size_t)sess_idx[n] * 128))[lane];
    float p1 = xo.x*va.x + xo.y*va.y + xo.z*va.z + xo.w*va.w;
    float p2 = xo.x*vb.x + xo.y*vb.y + xo.z*vb.z + xo.w*vb.w;
    float qq = 0.f;
    if (h1) {
        float4 xe = ((const float4*)(dde + (size_t)edge_dist[n - 1 - b] * 128))[lane];
        qq = xe.x*va.x + xe.y*va.y + xe.z*va.z + xe.w*va.w;
    }
    #pragma unroll
    for (int o = 16; o; o >>= 1) {
        p1 += __shfl_xor_sync(0xffffffffu, p1, o);
        p2 += __shfl_xor_sync(0xffffffffu, p2, o);
        qq += __shfl_xor_sync(0xffffffffu, qq, o);
    }

    float L1 = h1 ? (p1 + qq) : -1e30f;
    float L2 = h2 ? p2 : -1e30f;
    float m  = fmaxf(L1, L2);
    float e1 = h1 ? expf(L1 - m) : 0.f;
    float e2 = h2 ? expf(L2 - m) : 0.f;
    float inv = 1.f / (e1 + e2 + 1e-16f);
    float a1 = e1 * inv, a2 = e2 * inv;

    float4 hu = make_float4(0.f, 0.f, 0.f, 0.f);
    if (h1) {
        float4 x = ((const float4*)(POI + (size_t)sess_idx[n - 1] * 128))[lane];
        hu.x += a1 * x.x; hu.y += a1 * x.y; hu.z += a1 * x.z; hu.w += a1 * x.w;
    }
    if (h2) {
        float4 x = ((const float4*)(POI + (size_t)sess_idx[n + 1] * 128))[lane];
        hu.x += a2 * x.x; hu.y += a2 * x.y; hu.z += a2 * x.z; hu.w += a2 * x.w;
    }
    ((float4*)g_buf0)[(size_t)n * 32 + lane] = hu;
}

// ---------------------------------------------------------------------------
// Fused LN1 + QKV projections. One block = 128 rows.
// ---------------------------------------------------------------------------
__global__ void __launch_bounds__(256, 1)
qkv_kernel(const float* __restrict__ Hu,
           const unsigned* __restrict__ Wh3, const unsigned* __restrict__ Wl3,
           const float* __restrict__ in_b,
           const float* __restrict__ g1, const float* __restrict__ b1v,
           float* __restrict__ qout, float* __restrict__ kout,
           float* __restrict__ vout, float* __restrict__ qinout, int nrows)
{
    extern __shared__ unsigned smu[];
    unsigned* AhH = smu;
    unsigned* AlH = AhH + WPC;
    unsigned* AhQ = AlH + WPC;
    unsigned* AlQ = AhQ + WPC;
    unsigned* Bh  = AlQ + WPC;
    unsigned* Bl  = Bh + WPC;
    float* stage  = (float*)Bh;          // fp32 Hu staging [128][132]
    int tid  = threadIdx.x;
    int row0 = blockIdx.x * 128;
    int lane = tid & 31, wid = tid >> 5;
    int g  = lane >> 2, tq = lane & 3;
    int warpRow = (wid & 1) * 64;
    int warpCol = (wid >> 1) * 32;

    for (int i = tid; i < 4096; i += 256) {
        int r = i >> 5, q = i & 31;
        int gr = row0 + r;
        float4 a = (gr < nrows) ? ((const float4*)Hu)[(size_t)gr * 32 + q]
                                : make_float4(0.f, 0.f, 0.f, 0.f);
        unsigned h0, l0, h1, l1;
        bsplit2(a.x, a.y, h0, l0);
        bsplit2(a.z, a.w, h1, l1);
        AhH[r * PA + 2 * q]     = h0;  AhH[r * PA + 2 * q + 1] = h1;
        AlH[r * PA + 2 * q]     = l0;  AlH[r * PA + 2 * q + 1] = l1;
        *(float4*)&stage[r * 132 + q * 4] = a;
    }
    __syncthreads();

    {
        float4 gg = ((const float4*)g1)[lane];
        float4 bb = ((const float4*)b1v)[lane];
        for (int r = wid; r < 128; r += 8) {
            float4 v = *(float4*)&stage[r * 132 + lane * 4];
            float s1 = v.x + v.y + v.z + v.w;
            float s2 = v.x*v.x + v.y*v.y + v.z*v.z + v.w*v.w;
            #pragma unroll
            for (int o = 16; o; o >>= 1) {
                s1 += __shfl_xor_sync(0xffffffffu, s1, o);
                s2 += __shfl_xor_sync(0xffffffffu, s2, o);
            }
            float mu   = s1 * (1.f / 128.f);
            float var  = fmaxf(s2 * (1.f / 128.f) - mu * mu, 0.f);
            float rstd = rsqrtf(var + 1e-8f);
            float4 o4;
            o4.x = (v.x - mu) * rstd * gg.x + bb.x;
            o4.y = (v.y - mu) * rstd * gg.y + bb.y;
            o4.z = (v.z - mu) * rstd * gg.z + bb.z;
            o4.w = (v.w - mu) * rstd * gg.w + bb.w;
            int gr = row0 + r;
            if (gr < nrows)
                ((float4*)(qinout + (size_t)gr * 128))[lane] = o4;
            unsigned h0, l0, h1, l1;
            bsplit2(o4.x, o4.y, h0, l0);
            bsplit2(o4.z, o4.w, h1, l1);
            AhQ[r * PA + lane * 2]     = h0;  AhQ[r * PA + lane * 2 + 1] = h1;
            AlQ[r * PA + lane * 2]     = l0;  AlQ[r * PA + lane * 2 + 1] = l1;
        }
    }

    float d[4][4][4];
    for (int s = 0; s < 3; ++s) {
        __syncthreads();
        const uint4* wh4 = (const uint4*)(Wh3 + s * WPC);
        const uint4* wl4 = (const uint4*)(Wl3 + s * WPC);
        for (int i = tid; i < 2176; i += 256) {
            ((uint4*)Bh)[i] = wh4[i];
            ((uint4*)Bl)[i] = wl4[i];
        }
        __syncthreads();
        const unsigned* Ah = (s == 0) ? AhQ : AhH;
        const unsigned* Al = (s == 0) ? AlQ : AlH;
        mma_block128(Ah, Al, Bh, Bl, d, warpRow, warpCol, g, tq);

        float* op = (s == 0) ? qout : ((s == 1) ? kout : vout);
        const float* bias = in_b + s * 128;
        #pragma unroll
        for (int j = 0; j < 4; ++j) {
            int c0 = warpCol + j * 8 + tq * 2;
            float bj0 = bias[c0], bj1 = bias[c0 + 1];
            #pragma unroll
            for (int i = 0; i < 4; ++i) {
                int r0 = warpRow + i * 16 + g;
                int gr = row0 + r0;
                if (gr < nrows)
                    *(float2*)(op + (size_t)gr * 128 + c0) =
                        make_float2(d[i][j][0] + bj0, d[i][j][1] + bj1);
                if (gr + 8 < nrows)
                    *(float2*)(op + (size_t)(gr + 8) * 128 + c0) =
                        make_float2(d[i][j][2] + bj0, d[i][j][3] + bj1);
            }
        }
    }
}

// ---------------------------------------------------------------------------
// Fused tail: out2 = LN2(ctx@Wo^T + bo + Qin); h = relu(out2@W1^T + b1);
// out3 = h@W2^T + b2 + out2; S_u += out3 / l  (atomic pool).
// ---------------------------------------------------------------------------
__global__ void __launch_bounds__(256, 1)
tail_kernel(const float* __restrict__ ctx, const float* __restrict__ Qin,
            const unsigned* __restrict__ Wh3, const unsigned* __restrict__ Wl3,
            const float* __restrict__ out_b, const float* __restrict__ fb1,
            const float* __restrict__ fb2,
            const float* __restrict__ lng, const float* __restrict__ lnb,
            const int* __restrict__ batch_ids, const int* __restrict__ lengths,
            float* __restrict__ pool_out, int nrows)
{
    extern __shared__ unsigned smu[];
    unsigned* Ah = smu;                       // [128][PA]
    unsigned* Al = Ah + WPC;
    unsigned* Bh = Al + WPC;
    unsigned* Bl = Bh + WPC;
    float*    O  = (float*)(Bl + WPC);        // [128][132] fp32 out2
    int tid  = threadIdx.x;
    int row0 = blockIdx.x * 128;
    int lane = tid & 31, wid = tid >> 5;
    int g  = lane >> 2, tq = lane & 3;
    int warpRow = (wid & 1) * 64;
    int warpCol = (wid >> 1) * 32;

    for (int i = tid; i < 4096; i += 256) {
        int r = i >> 5, q = i & 31;
        int gr = row0 + r;
        float4 a = (gr < nrows) ? ((const float4*)ctx)[(size_t)gr * 32 + q]
                                : make_float4(0.f, 0.f, 0.f, 0.f);
        unsigned h0, l0, h1, l1;
        bsplit2(a.x, a.y, h0, l0);
        bsplit2(a.z, a.w, h1, l1);
        Ah[r * PA + 2 * q]     = h0;  Ah[r * PA + 2 * q + 1] = h1;
        Al[r * PA + 2 * q]     = l0;  Al[r * PA + 2 * q + 1] = l1;
    }
    for (int i = tid; i < 2176; i += 256) {
        ((uint4*)Bh)[i] = ((const uint4*)Wh3)[i];
        ((uint4*)Bl)[i] = ((const uint4*)Wl3)[i];
    }
    __syncthreads();

    float d[4][4][4];
    mma_block128(Ah, Al, Bh, Bl, d, warpRow, warpCol, g, tq);
    __syncthreads();

    #pragma unroll
    for (int i = 0; i < 4; ++i) {
        int r0 = warpRow + i * 16 + g;
        #pragma unroll
        for (int j = 0; j < 4; ++j) {
            int c0 = warpCol + j * 8 + tq * 2;
            *(float2*)&O[r0 * 132 + c0]       = make_float2(d[i][j][0], d[i][j][1]);
            *(float2*)&O[(r0 + 8) * 132 + c0] = make_float2(d[i][j][2], d[i][j][3]);
        }
    }
    __syncthreads();

    {
        float4 bo = ((const float4*)out_b)[lane];
        float4 gg = ((const float4*)lng)[lane];
        float4 be = ((const float4*)lnb)[lane];
        for (int r = wid; r < 128; r += 8) {
            int gr = row0 + r;
            float4 v = *(float4*)&O[r * 132 + lane * 4];
            float4 qv = (gr < nrows) ? ((const float4*)(Qin + (size_t)gr * 128))[lane]
                                     : make_float4(0.f, 0.f, 0.f, 0.f);
            v.x += bo.x + qv.x; v.y += bo.y + qv.y;
            v.z += bo.z + qv.z; v.w += bo.w + qv.w;
            float s1 = v.x + v.y + v.z + v.w;
            float s2 = v.x*v.x + v.y*v.y + v.z*v.z + v.w*v.w;
            #pragma unroll
            for (int o = 16; o; o >>= 1) {
                s1 += __shfl_xor_sync(0xffffffffu, s1, o);
                s2 += __shfl_xor_sync(0xffffffffu, s2, o);
            }
            float mu   = s1 * (1.f / 128.f);
            float var  = fmaxf(s2 * (1.f / 128.f) - mu * mu, 0.f);
            float rstd = rsqrtf(var + 1e-8f);
            v.x = (v.x - mu) * rstd * gg.x + be.x;
            v.y = (v.y - mu) * rstd * gg.y + be.y;
            v.z = (v.z - mu) * rstd * gg.z + be.z;
            v.w = (v.w - mu) * rstd * gg.w + be.w;
            *(float4*)&O[r * 132 + lane * 4] = v;
            unsigned h0, l0, h1, l1;
            bsplit2(v.x, v.y, h0, l0);
            bsplit2(v.z, v.w, h1, l1);
            Ah[r * PA + lane * 2]     = h0;  Ah[r * PA + lane * 2 + 1] = h1;
            Al[r * PA + lane * 2]     = l0;  Al[r * PA + lane * 2 + 1] = l1;
        }
    }
    __syncthreads();

    for (int i = tid; i < 2176; i += 256) {
        ((uint4*)Bh)[i] = ((const uint4*)(Wh3 + WPC))[i];
        ((uint4*)Bl)[i] = ((const uint4*)(Wl3 + WPC))[i];
    }
    __syncthreads();
    mma_block128(Ah, Al, Bh, Bl, d, warpRow, warpCol, g, tq);
    __syncthreads();

    #pragma unroll
    for (int i = 0; i < 4; ++i) {
        #pragma unroll
        for (int j = 0; j < 4; ++j) {
            int c0 = warpCol + j * 8 + tq * 2;
            float bx = fb1[c0], by = fb1[c0 + 1];
            int r0 = warpRow + i * 16 + g;
            float v0 = fmaxf(d[i][j][0] + bx, 0.f);
            float v1 = fmaxf(d[i][j][1] + by, 0.f);
            float v2 = fmaxf(d[i][j][2] + bx, 0.f);
            float v3 = fmaxf(d[i][j][3] + by, 0.f);
            unsigned h0, l0, h1, l1;
            bsplit2(v0, v1, h0, l0);
            bsplit2(v2, v3, h1, l1);
            int w0 = r0 * PA + (c0 >> 1);
            int w1 = (r0 + 8) * PA + (c0 >> 1);
            Ah[w0] = h0;  Al[w0] = l0;
            Ah[w1] = h1;  Al[w1] = l1;
        }
    }
    __syncthreads();

    for (int i = tid; i < 2176; i += 256) {
        ((uint4*)Bh)[i] = ((const uint4*)(Wh3 + 2 * WPC))[i];
        ((uint4*)Bl)[i] = ((const uint4*)(Wl3 + 2 * WPC))[i];
    }
    __syncthreads();
    mma_block128(Ah, Al, Bh, Bl, d, warpRow, warpCol, g, tq);

    #pragma unroll
    for (int i = 0; i < 4; ++i) {
        #pragma unroll
        for (int half = 0; half < 2; ++half) {
            int r0 = warpRow + i * 16 + g + half * 8;
            int gr = row0 + r0;
            if (gr >= nrows) continue;
            int bsess = batch_ids[gr];
            float invl = 1.f / (float)lengths[bsess];
            float* outrow = pool_out + (size_t)bsess * 128;
            #pragma unroll
            for (int j = 0; j < 4; ++j) {
                int c0 = warpCol + j * 8 + tq * 2;
                float v0 = d[i][j][2 * half]     + fb2[c0]     + O[r0 * 132 + c0];
                float v1 = d[i][j][2 * half + 1] + fb2[c0 + 1] + O[r0 * 132 + c0 + 1];
                atomicAdd(outrow + c0,     v0 * invl);
                atomicAdd(outrow + c0 + 1, v1 * invl);
            }
        }
    }
}

// ---------------------------------------------------------------------------
// Tensor-core attention per (session, head), online-softmax chunked.
// 8 warps, warp per 16-row tile; 32-column chunks; sa[4][4] live.
// ---------------------------------------------------------------------------
__global__ void __launch_bounds__(256, 2)
attn_mma_kernel(const float* __restrict__ qp, const float* __restrict__ kp,
                const float* __restrict__ vp, float* __restrict__ ctx,
                const int* __restrict__ lengths)
{
    int b = blockIdx.x;
    int h = blockIdx.y;
    int n0 = d_starts[b];
    int l  = lengths[b];
    extern __shared__ unsigned sm[];
    unsigned* Qh = sm;                   // [160][QS]
    unsigned* Ql = Qh + 160 * QS;
    unsigned* Kh = Ql + 160 * QS;
    unsigned* Kl = Kh + 160 * QS;
    unsigned* Vh = Kl + 160 * QS;        // [32][VS]
    unsigned* Vl = Vh + 32 * VS;
    int tid = threadIdx.x;
    int hc  = h * 32;

    for (int i = tid; i < l * 16; i += 256) {
        int s = i >> 4, cp = i & 15;
        size_t gi = (((size_t)(n0 + s) * 128 + hc) >> 1) + cp;
        float2 qv = ((const float2*)qp)[gi];
        unsigned hi, lo;
        bsplit2(qv.x, qv.y, hi, lo);
        Qh[s * QS + cp] = hi; Ql[s * QS + cp] = lo;
        float2 kv = ((const float2*)kp)[gi];
        bsplit2(kv.x, kv.y, hi, lo);
        Kh[s * QS + cp] = hi; Kl[s * QS + cp] = lo;
    }
    int njp = (l + 1) >> 1;
    for (int i = tid; i < njp * 32; i += 256) {
        int jp = i >> 5, d = i & 31;
        int j0 = 2 * jp;
        float v0 = vp[(size_t)(n0 + j0) * 128 + hc + d];
        float v1 = (j0 + 1 < l) ? vp[(size_t)(n0 + j0 + 1) * 128 + hc + d] : 0.f;
        unsigned hi, lo;
        bsplit2(v0, v1, hi, lo);
        Vh[d * VS + jp] = hi; Vl[d * VS + jp] = lo;
    }
    int nchunks = (l + 31) >> 5;
    int jmax = nchunks * 16;
    for (int i = tid; i < (jmax - njp) * 32; i += 256) {
        int d = i & 31, jp = njp + (i >> 5);
        Vh[d * VS + jp] = 0u;
        Vl[d * VS + jp] = 0u;
    }
    __syncthreads();

    int lane = tid & 31, wid = tid >> 5;
    int g = lane >> 2, tq = lane & 3;
    int nrt = (l + 15) >> 4;
    const float scale = 0.17677669529663687f;   // 1/sqrt(32)

    for (int rt = wid; rt < nrt; rt += 8) {
        int i0 = rt * 16;
        unsigned qah[2][4], qal[2][4];
        #pragma unroll
        for (int kk = 0; kk < 2; ++kk) {
            int base = (i0 + g) * QS + kk * 8 + tq;
            qah[kk][0] = Qh[base];        qah[kk][1] = Qh[base + 8 * QS];
            qah[kk][2] = Qh[base + 4];    qah[kk][3] = Qh[base + 8 * QS + 4];
            qal[kk][0] = Ql[base];        qal[kk][1] = Ql[base + 8 * QS];
            qal[kk][2] = Ql[base + 4];    qal[kk][3] = Ql[base + 8 * QS + 4];
        }

        float ca[4][4];
        #pragma unroll
        for (int nt = 0; nt < 4; ++nt)
            ca[nt][0] = ca[nt][1] = ca[nt][2] = ca[nt][3] = 0.f;
        float m0 = -1e30f, m1 = -1e30f;   // running max (quad-uniform)
        float sum0 = 0.f, sum1 = 0.f;     // per-lane partial sums

        for (int ch = 0; ch < nchunks; ++ch) {
            float sa[4][4];
            #pragma unroll
            for (int ct = 0; ct < 4; ++ct)
                sa[ct][0] = sa[ct][1] = sa[ct][2] = sa[ct][3] = 0.f;

            #pragma unroll
            for (int ct = 0; ct < 4; ++ct) {
                #pragma unroll
                for (int kk = 0; kk < 2; ++kk) {
                    int base = ((ch * 4 + ct) * 8 + g) * QS + kk * 8 + tq;
                    unsigned bh0 = Kh[base], bh1 = Kh[base + 4];
                    unsigned bl0 = Kl[base], bl1 = Kl[base + 4];
                    MMA_BF16(sa[ct][0], sa[ct][1], sa[ct][2], sa[ct][3],
                             qah[kk][0], qah[kk][1], qah[kk][2], qah[kk][3], bh0, bh1);
                    MMA_BF16(sa[ct][0], sa[ct][1], sa[ct][2], sa[ct][3],
                             qah[kk][0], qah[kk][1], qah[kk][2], qah[kk][3], bl0, bl1);
                    MMA_BF16(sa[ct][0], sa[ct][1], sa[ct][2], sa[ct][3],
                             qal[kk][0], qal[kk][1], qal[kk][2], qal[kk][3], bh0, bh1);
                }
            }

            // mask + scale + chunk max
            float cm0 = -1e30f, cm1 = -1e30f;
            #pragma unroll
            for (int ct = 0; ct < 4; ++ct) {
                int c0 = ch * 32 + ct * 8 + 2 * tq;
                bool v0 = c0 < l, v1 = (c0 + 1) < l;
                sa[ct][0] = v0 ? sa[ct][0] * scale : -1e30f;
                sa[ct][1] = v1 ? sa[ct][1] * scale : -1e30f;
                sa[ct][2] = v0 ? sa[ct][2] * scale : -1e30f;
                sa[ct][3] = v1 ? sa[ct][3] * scale : -1e30f;
                cm0 = fmaxf(cm0, fmaxf(sa[ct][0], sa[ct][1]));
                cm1 = fmaxf(cm1, fmaxf(sa[ct][2], sa[ct][3]));
            }
            cm0 = fmaxf(cm0, __shfl_xor_sync(0xffffffffu, cm0, 1));
            cm0 = fmaxf(cm0, __shfl_xor_sync(0xffffffffu, cm0, 2));
            cm1 = fmaxf(cm1, __shfl_xor_sync(0xffffffffu, cm1, 1));
            cm1 = fmaxf(cm1, __shfl_xor_sync(0xffffffffu, cm1, 2));

            float nm0 = fmaxf(m0, cm0);
            float nm1 = fmaxf(m1, cm1);
            float al0 = __expf(m0 - nm0);
            float al1 = __expf(m1 - nm1);
            m0 = nm0; m1 = nm1;
            sum0 *= al0; sum1 *= al1;
            #pragma unroll
            for (int nt = 0; nt < 4; ++nt) {
                ca[nt][0] *= al0; ca[nt][1] *= al0;
                ca[nt][2] *= al1; ca[nt][3] *= al1;
            }

            // exp
            #pragma unroll
            for (int ct = 0; ct < 4; ++ct) {
                int c0 = ch * 32 + ct * 8 + 2 * tq;
                float e0 = (c0 < l)     ? __expf(sa[ct][0] - m0) : 0.f;
                float e1 = (c0 + 1 < l) ? __expf(sa[ct][1] - m0) : 0.f;
                float e2 = (c0 < l)     ? __expf(sa[ct][2] - m1) : 0.f;
                float e3 = (c0 + 1 < l) ? __expf(sa[ct][3] - m1) : 0.f;
                sa[ct][0] = e0; sa[ct][1] = e1; sa[ct][2] = e2; sa[ct][3] = e3;
                sum0 += e0 + e1; sum1 += e2 + e3;
            }

            // PV for this chunk
            #pragma unroll
            for (int kk2 = 0; kk2 < 2; ++kk2) {
                unsigned pah[4], pal[4];
                bsplit2(sa[2*kk2][0],   sa[2*kk2][1],   pah[0], pal[0]);
                bsplit2(sa[2*kk2][2],   sa[2*kk2][3],   pah[1], pal[1]);
                bsplit2(sa[2*kk2+1][0], sa[2*kk2+1][1], pah[2], pal[2]);
                bsplit2(sa[2*kk2+1][2], sa[2*kk2+1][3], pah[3], pal[3]);
                #pragma unroll
                for (int nt = 0; nt < 4; ++nt) {
                    int base = (nt * 8 + g) * VS + (ch * 2 + kk2) * 8 + tq;
                    unsigned bh0 = Vh[base], bh1 = Vh[base + 4];
                    unsigned bl0 = Vl[base], bl1 = Vl[base + 4];
                    MMA_BF16(ca[nt][0], ca[nt][1], ca[nt][2], ca[nt][3],
                             pah[0], pah[1], pah[2], pah[3], bh0, bh1);
                    MMA_BF16(ca[nt][0], ca[nt][1], ca[nt][2], ca[nt][3],
                             pah[0], pah[1], pah[2], pah[3], bl0, bl1);
                    MMA_BF16(ca[nt][0], ca[nt][1], ca[nt][2], ca[nt][3],
                             pal[0], pal[1], pal[2], pal[3], bh0, bh1);
                }
            }
        }

        sum0 += __shfl_xor_sync(0xffffffffu, sum0, 1);
        sum0 += __shfl_xor_sync(0xffffffffu, sum0, 2);
        sum1 += __shfl_xor_sync(0xffffffffu, sum1, 1);
        sum1 += __shfl_xor_sync(0xffffffffu, sum1, 2);

        float inv0 = 1.f / sum0;
        float inv1 = 1.f / sum1;
        int r0 = i0 + g, r1 = i0 + 8 + g;
        #pragma unroll
        for (int nt = 0; nt < 4; ++nt) {
            int dcol = nt * 8 + 2 * tq;
            if (r0 < l)
                *(float2*)(ctx + (size_t)(n0 + r0) * 128 + hc + dcol) =
                    make_float2(ca[nt][0] * inv0, ca[nt][1] * inv0);
            if (r1 < l)
                *(float2*)(ctx + (size_t)(n0 + r1) * 128 + hc + dcol) =
                    make_float2(ca[nt][2] * inv1, ca[nt][3] * inv1);
        }
    }
}

// ---------------------------------------------------------------------------
extern "C" void kernel_launch(void* const* d_in, const int* in_sizes, int n_in,
                              void* d_out, int out_size)
{
    const float* POI    = (const float*)d_in[0];
    const float* dde    = (const float*)d_in[1];
    const float* attW   = (const float*)d_in[2];
    const float* a_src  = (const float*)d_in[3];
    const float* a_dst  = (const float*)d_in[4];
    const float* in_w   = (const float*)d_in[5];
    const float* in_b   = (const float*)d_in[6];
    const float* out_w  = (const float*)d_in[7];
    const float* out_b  = (const float*)d_in[8];
    const float* ln1g   = (const float*)d_in[9];
    const float* ln1b   = (const float*)d_in[10];
    const float* ln2g   = (const float*)d_in[11];
    const float* ln2b   = (const float*)d_in[12];
    const float* fw1    = (const float*)d_in[13];
    const float* fb1    = (const float*)d_in[14];
    const float* fw2    = (const float*)d_in[15];
    const float* fb2    = (const float*)d_in[16];
    const int* sess_idx  = (const int*)d_in[17];
    const int* edge_dist = (const int*)d_in[18];
    const int* batch_ids = (const int*)d_in[20];
    const int* node_pos  = (const int*)d_in[21];
    const int* lengths   = (const int*)d_in[22];
    int N = in_sizes[17];
    int B = in_sizes[22];
    float* outp = (float*)d_out;

    float *b0, *b1, *b2, *b3, *b4;
    unsigned *wh, *wl;
    cudaGetSymbolAddress((void**)&b0, g_buf0);
    cudaGetSymbolAddress((void**)&b1, g_buf1);
    cudaGetSymbolAddress((void**)&b2, g_buf2);
    cudaGetSymbolAddress((void**)&b3, g_buf3);
    cudaGetSymbolAddress((void**)&b4, g_buf4);
    cudaGetSymbolAddress((void**)&wh, d_wh);
    cudaGetSymbolAddress((void**)&wl, d_wl);

    const int qkv_smem  = 6 * WPC * (int)sizeof(unsigned);                       // ~208.9 KB
    const int tail_smem = 4 * WPC * (int)sizeof(unsigned)
                        + 128 * 132 * (int)sizeof(float);                        // ~206.8 KB
    const int attn_smem = (4 * 160 * QS + 2 * 32 * VS) * (int)sizeof(unsigned);  // ~72.7 KB
    cudaFuncSetAttribute(qkv_kernel,      cudaFuncAttributeMaxDynamicSharedMemorySize, qkv_smem);
    cudaFuncSetAttribute(tail_kernel,     cudaFuncAttributeMaxDynamicSharedMemorySize, tail_smem);
    cudaFuncSetAttribute(attn_mma_kernel, cudaFuncAttributeMaxDynamicSharedMemorySize, attn_smem);

    head_kernel<<<16, 1024>>>(lengths, B, attW, a_src, a_dst,
                              in_w, out_w, fw1, fw2, outp, out_size);

    gcn_kernel<<<(N + 7) / 8, 256>>>(POI, dde, sess_idx, edge_dist,
                                     batch_ids, node_pos, lengths, N);

    int gblocks = (N + 127) / 128;
    qkv_kernel<<<gblocks, 256, qkv_smem>>>(b0, wh, wl, in_b, ln1g, ln1b,
                                           b2, b3, b4, b1, N);

    dim3 ag(B, 4);
    attn_mma_kernel<<<ag, 256, attn_smem>>>(b2, b3, b4, b0, lengths);

    tail_kernel<<<gblocks, 256, tail_smem>>>(b0, b1, wh + 3 * WPC, wl + 3 * WPC,
                                             out_b, fb1, fb2, ln2g, ln2b,
                                             batch_ids, lengths, outp, N);
}

// round 12
// speedup vs baseline: 3.4874x; 1.1228x over previous
#include <cuda_runtime.h>
#include <cuda_bf16.h>
#include <math.h>

// ---------------------------------------------------------------------------
// SeqGraphRepNetwork on GB300 — packed formulation.
// R11: qkv/tail -> 512 threads (16 warps, 64x16 warp tiles) to double
//      per-SM issue parallelism at unchanged smem; attn/gcn/head frozen.
// ---------------------------------------------------------------------------

#define NMAX   163840
#define LMAX   160
#define BMAXS  1024
#define PA     68            // gemm smem row stride (words)
#define WPC    (128 * PA)    // words per weight plane
#define QS     20            // attn Q/K smem row stride (words)
#define VS     84            // attn V^T smem row stride (words)

__device__ float d_vsrc[128];
__device__ float d_vdst[128];
__device__ int   d_starts[BMAXS + 1];
__device__ unsigned d_wh[6 * WPC];           // weight hi-plane, gemm layout
__device__ unsigned d_wl[6 * WPC];           // weight lo-plane
__device__ float g_buf0[(size_t)NMAX * 128]; // Hu, later ctx
__device__ float g_buf1[(size_t)NMAX * 128]; // Qin (LN1 output)
__device__ float g_buf2[(size_t)NMAX * 128]; // q proj
__device__ float g_buf3[(size_t)NMAX * 128]; // k proj
__device__ float g_buf4[(size_t)NMAX * 128]; // v proj

// ---------------------------------------------------------------------------
__device__ __forceinline__ void bsplit2(float a0, float a1,
                                        unsigned &hi, unsigned &lo)
{
    __nv_bfloat162 h = __float22bfloat162_rn(make_float2(a0, a1));
    float r0 = a0 - __low2float(h);
    float r1 = a1 - __high2float(h);
    __nv_bfloat162 l = __float22bfloat162_rn(make_float2(r0, r1));
    hi = *(unsigned*)&h;
    lo = *(unsigned*)&l;
}

#define MMA_BF16(d0,d1,d2,d3, a0,a1,a2,a3, b0,b1)                         \
    asm volatile("mma.sync.aligned.m16n8k16.row.col.f32.bf16.bf16.f32 "   \
                 "{%0,%1,%2,%3}, {%4,%5,%6,%7}, {%8,%9}, {%0,%1,%2,%3};"  \
                 : "+f"(d0), "+f"(d1), "+f"(d2), "+f"(d3)                 \
                 : "r"(a0), "r"(a1), "r"(a2), "r"(a3), "r"(b0), "r"(b1))

// 128-row x (NJ*8)-col warp tile block mma over K=128, 3-term split-bf16.
template<int NJ>
__device__ __forceinline__ void mma_block_t(
    const unsigned* __restrict__ Ah, const unsigned* __restrict__ Al,
    const unsigned* __restrict__ Bh, const unsigned* __restrict__ Bl,
    float d[4][NJ][4], int warpRow, int warpCol, int g, int tq)
{
    #pragma unroll
    for (int i = 0; i < 4; ++i)
        #pragma unroll
        for (int j = 0; j < NJ; ++j)
            d[i][j][0] = d[i][j][1] = d[i][j][2] = d[i][j][3] = 0.f;

    #pragma unroll
    for (int kk = 0; kk < 8; ++kk) {
        unsigned ah[4][4], al[4][4], bh[NJ][2], bl[NJ][2];
        #pragma unroll
        for (int i = 0; i < 4; ++i) {
            int base = (warpRow + i * 16 + g) * PA + kk * 8 + tq;
            ah[i][0] = Ah[base];            ah[i][1] = Ah[base + 8 * PA];
            ah[i][2] = Ah[base + 4];        ah[i][3] = Ah[base + 8 * PA + 4];
            al[i][0] = Al[base];            al[i][1] = Al[base + 8 * PA];
            al[i][2] = Al[base + 4];        al[i][3] = Al[base + 8 * PA + 4];
        }
        #pragma unroll
        for (int j = 0; j < NJ; ++j) {
            int base = (warpCol + j * 8 + g) * PA + kk * 8 + tq;
            bh[j][0] = Bh[base];  bh[j][1] = Bh[base + 4];
            bl[j][0] = Bl[base];  bl[j][1] = Bl[base + 4];
        }
        #pragma unroll
        for (int i = 0; i < 4; ++i)
            #pragma unroll
            for (int j = 0; j < NJ; ++j) {
                MMA_BF16(d[i][j][0], d[i][j][1], d[i][j][2], d[i][j][3],
                         ah[i][0], ah[i][1], ah[i][2], ah[i][3],
                         bh[j][0], bh[j][1]);
                MMA_BF16(d[i][j][0], d[i][j][1], d[i][j][2], d[i][j][3],
                         ah[i][0], ah[i][1], ah[i][2], ah[i][3],
                         bl[j][0], bl[j][1]);
                MMA_BF16(d[i][j][0], d[i][j][1], d[i][j][2], d[i][j][3],
                         al[i][0], al[i][1], al[i][2], al[i][3],
                         bh[j][0], bh[j][1]);
            }
    }
}

// ---------------------------------------------------------------------------
// Head: block 0 = scan; block 1 = prep vectors; blocks 2-7 = weight split;
// blocks 8-15 = zero the pool output.
// ---------------------------------------------------------------------------
__global__ void head_kernel(const int* __restrict__ lengths, int B,
                            const float* __restrict__ attW,
                            const float* __restrict__ a_src,
                            const float* __restrict__ a_dst,
                            const float* __restrict__ in_w,
                            const float* __restrict__ out_w,
                            const float* __restrict__ fw1,
                            const float* __restrict__ fw2,
                            float* __restrict__ outp, int out_n)
{
    __shared__ int s[BMAXS];
    int blk = blockIdx.x;
    int t = threadIdx.x;
    if (blk == 0) {
        int v = (t < B) ? lengths[t] : 0;
        s[t] = v;
        __syncthreads();
        for (int o = 1; o < BMAXS; o <<= 1) {
            int add = (t >= o) ? s[t - o] : 0;
            __syncthreads();
            s[t] += add;
            __syncthreads();
        }
        if (t < B) d_starts[t] = s[t] - v;
        if (t == B - 1) d_starts[B] = s[t];
    } else if (blk == 1) {
        if (t < 128) {
            float vs = 0.f, vd = 0.f;
            #pragma unroll 4
            for (int k = 0; k < 128; ++k) {
                float w = attW[k * 128 + t];
                vs += a_src[k] * w;
                vd += a_dst[k] * w;
            }
            d_vsrc[t] = vs;
            d_vdst[t] = vd;
        }
    } else if (blk < 8) {
        int m = blk - 2;
        const float* src = (m < 3) ? (in_w + m * 16384)
                         : (m == 3 ? out_w : (m == 4 ? fw1 : fw2));
        unsigned* wh = d_wh + m * WPC;
        unsigned* wl = d_wl + m * WPC;
        for (int i = t; i < 4096; i += 1024) {
            int r = i >> 5, q = i & 31;
            float4 w = ((const float4*)src)[i];
            unsigned h0, l0, h1, l1;
            bsplit2(w.x, w.y, h0, l0);
            bsplit2(w.z, w.w, h1, l1);
            wh[r * PA + 2 * q]     = h0;  wh[r * PA + 2 * q + 1] = h1;
            wl[r * PA + 2 * q]     = l0;  wl[r * PA + 2 * q + 1] = l1;
        }
    } else {
        for (int i = (blk - 8) * 1024 + t; i < out_n; i += 8 * 1024)
            outp[i] = 0.f;
    }
}

// ---------------------------------------------------------------------------
// GCN: warp per node; node-local edge logits; 2-way softmax aggregate.
// ---------------------------------------------------------------------------
__global__ void gcn_kernel(const float* __restrict__ POI,
                           const float* __restrict__ dde,
                           const int*   __restrict__ sess_idx,
                           const int*   __restrict__ edge_dist,
                           const int*   __restrict__ batch_ids,
                           const int*   __restrict__ node_pos,
                           const int*   __restrict__ lengths, int N)
{
    int n = blockIdx.x * 8 + (threadIdx.x >> 5);
    if (n >= N) return;
    int lane = threadIdx.x & 31;
    int b = batch_ids[n];
    int p = node_pos[n];
    int l = lengths[b];
    bool h1 = (p > 0);
    bool h2 = (p < l - 1);

    float4 va = ((const float4*)d_vsrc)[lane];
    float4 vb = ((const float4*)d_vdst)[lane];
    float4 xo = ((const float4*)(POI + (size_t)sess_idx[n] * 128))[lane];
    float p1 = xo.x*va.x + xo.y*va.y + xo.z*va.z + xo.w*va.w;
    float p2 = xo.x*vb.x + xo.y*vb.y + xo.z*vb.z + xo.w*vb.w;
    float qq = 0.f;
    if (h1) {
        float4 xe = ((const float4*)(dde + (size_t)edge_dist[n - 1 - b] * 128))[lane];
        qq = xe.x*va.x + xe.y*va.y + xe.z*va.z + xe.w*va.w;
    }
    #pragma unroll
    for (int o = 16; o; o >>= 1) {
        p1 += __shfl_xor_sync(0xffffffffu, p1, o);
        p2 += __shfl_xor_sync(0xffffffffu, p2, o);
        qq += __shfl_xor_sync(0xffffffffu, qq, o);
    }

    float L1 = h1 ? (p1 + qq) : -1e30f;
    float L2 = h2 ? p2 : -1e30f;
    float m  = fmaxf(L1, L2);
    float e1 = h1 ? expf(L1 - m) : 0.f;
    float e2 = h2 ? expf(L2 - m) : 0.f;
    float inv = 1.f / (e1 + e2 + 1e-16f);
    float a1 = e1 * inv, a2 = e2 * inv;

    float4 hu = make_float4(0.f, 0.f, 0.f, 0.f);
    if (h1) {
        float4 x = ((const float4*)(POI + (size_t)sess_idx[n - 1] * 128))[lane];
        hu.x += a1 * x.x; hu.y += a1 * x.y; hu.z += a1 * x.z; hu.w += a1 * x.w;
    }
    if (h2) {
        float4 x = ((const float4*)(POI + (size_t)sess_idx[n + 1] * 128))[lane];
        hu.x += a2 * x.x; hu.y += a2 * x.y; hu.z += a2 * x.z; hu.w += a2 * x.w;
    }
    ((float4*)g_buf0)[(size_t)n * 32 + lane] = hu;
}

// ---------------------------------------------------------------------------
// Fused LN1 + QKV projections. One block = 128 rows, 512 threads (16 warps,
// warp tile 64x16).
// ---------------------------------------------------------------------------
__global__ void __launch_bounds__(512, 1)
qkv_kernel(const float* __restrict__ Hu,
           const unsigned* __restrict__ Wh3, const unsigned* __restrict__ Wl3,
           const float* __restrict__ in_b,
           const float* __restrict__ g1, const float* __restrict__ b1v,
           float* __restrict__ qout, float* __restrict__ kout,
           float* __restrict__ vout, float* __restrict__ qinout, int nrows)
{
    extern __shared__ unsigned smu[];
    unsigned* AhH = smu;
    unsigned* AlH = AhH + WPC;
    unsigned* AhQ = AlH + WPC;
    unsigned* AlQ = AhQ + WPC;
    unsigned* Bh  = AlQ + WPC;
    unsigned* Bl  = Bh + WPC;
    float* stage  = (float*)Bh;          // fp32 Hu staging [128][132]
    int tid  = threadIdx.x;
    int row0 = blockIdx.x * 128;
    int lane = tid & 31, wid = tid >> 5;
    int g  = lane >> 2, tq = lane & 3;
    int warpRow = (wid & 1) * 64;
    int warpCol = (wid >> 1) * 16;

    for (int i = tid; i < 4096; i += 512) {
        int r = i >> 5, q = i & 31;
        int gr = row0 + r;
        float4 a = (gr < nrows) ? ((const float4*)Hu)[(size_t)gr * 32 + q]
                                : make_float4(0.f, 0.f, 0.f, 0.f);
        unsigned h0, l0, h1, l1;
        bsplit2(a.x, a.y, h0, l0);
        bsplit2(a.z, a.w, h1, l1);
        AhH[r * PA + 2 * q]     = h0;  AhH[r * PA + 2 * q + 1] = h1;
        AlH[r * PA + 2 * q]     = l0;  AlH[r * PA + 2 * q + 1] = l1;
        *(float4*)&stage[r * 132 + q * 4] = a;
    }
    __syncthreads();

    {
        float4 gg = ((const float4*)g1)[lane];
        float4 bb = ((const float4*)b1v)[lane];
        for (int r = wid; r < 128; r += 16) {
            float4 v = *(float4*)&stage[r * 132 + lane * 4];
            float s1 = v.x + v.y + v.z + v.w;
            float s2 = v.x*v.x + v.y*v.y + v.z*v.z + v.w*v.w;
            #pragma unroll
            for (int o = 16; o; o >>= 1) {
                s1 += __shfl_xor_sync(0xffffffffu, s1, o);
                s2 += __shfl_xor_sync(0xffffffffu, s2, o);
            }
            float mu   = s1 * (1.f / 128.f);
            float var  = fmaxf(s2 * (1.f / 128.f) - mu * mu, 0.f);
            float rstd = rsqrtf(var + 1e-8f);
            float4 o4;
            o4.x = (v.x - mu) * rstd * gg.x + bb.x;
            o4.y = (v.y - mu) * rstd * gg.y + bb.y;
            o4.z = (v.z - mu) * rstd * gg.z + bb.z;
            o4.w = (v.w - mu) * rstd * gg.w + bb.w;
            int gr = row0 + r;
            if (gr < nrows)
                ((float4*)(qinout + (size_t)gr * 128))[lane] = o4;
            unsigned h0, l0, h1, l1;
            bsplit2(o4.x, o4.y, h0, l0);
            bsplit2(o4.z, o4.w, h1, l1);
            AhQ[r * PA + lane * 2]     = h0;  AhQ[r * PA + lane * 2 + 1] = h1;
            AlQ[r * PA + lane * 2]     = l0;  AlQ[r * PA + lane * 2 + 1] = l1;
        }
    }

    float d[4][2][4];
    for (int s = 0; s < 3; ++s) {
        __syncthreads();
        const uint4* wh4 = (const uint4*)(Wh3 + s * WPC);
        const uint4* wl4 = (const uint4*)(Wl3 + s * WPC);
        for (int i = tid; i < 2176; i += 512) {
            ((uint4*)Bh)[i] = wh4[i];
            ((uint4*)Bl)[i] = wl4[i];
        }
        __syncthreads();
        const unsigned* Ah = (s == 0) ? AhQ : AhH;
        const unsigned* Al = (s == 0) ? AlQ : AlH;
        mma_block_t<2>(Ah, Al, Bh, Bl, d, warpRow, warpCol, g, tq);

        float* op = (s == 0) ? qout : ((s == 1) ? kout : vout);
        const float* bias = in_b + s * 128;
        #pragma unroll
        for (int j = 0; j < 2; ++j) {
            int c0 = warpCol + j * 8 + tq * 2;
            float bj0 = bias[c0], bj1 = bias[c0 + 1];
            #pragma unroll
            for (int i = 0; i < 4; ++i) {
                int r0 = warpRow + i * 16 + g;
                int gr = row0 + r0;
                if (gr < nrows)
                    *(float2*)(op + (size_t)gr * 128 + c0) =
                        make_float2(d[i][j][0] + bj0, d[i][j][1] + bj1);
                if (gr + 8 < nrows)
                    *(float2*)(op + (size_t)(gr + 8) * 128 + c0) =
                        make_float2(d[i][j][2] + bj0, d[i][j][3] + bj1);
            }
        }
    }
}

// ---------------------------------------------------------------------------
// Fused tail: out2 = LN2(ctx@Wo^T + bo + Qin); h = relu(out2@W1^T + b1);
// out3 = h@W2^T + b2 + out2; S_u += out3 / l  (atomic pool).
// 512 threads, 16 warps, warp tile 64x16.
// ---------------------------------------------------------------------------
__global__ void __launch_bounds__(512, 1)
tail_kernel(const float* __restrict__ ctx, const float* __restrict__ Qin,
            const unsigned* __restrict__ Wh3, const unsigned* __restrict__ Wl3,
            const float* __restrict__ out_b, const float* __restrict__ fb1,
            const float* __restrict__ fb2,
            const float* __restrict__ lng, const float* __restrict__ lnb,
            const int* __restrict__ batch_ids, const int* __restrict__ lengths,
            float* __restrict__ pool_out, int nrows)
{
    extern __shared__ unsigned smu[];
    unsigned* Ah = smu;                       // [128][PA]
    unsigned* Al = Ah + WPC;
    unsigned* Bh = Al + WPC;
    unsigned* Bl = Bh + WPC;
    float*    O  = (float*)(Bl + WPC);        // [128][132] fp32 out2
    int tid  = threadIdx.x;
    int row0 = blockIdx.x * 128;
    int lane = tid & 31, wid = tid >> 5;
    int g  = lane >> 2, tq = lane & 3;
    int warpRow = (wid & 1) * 64;
    int warpCol = (wid >> 1) * 16;

    for (int i = tid; i < 4096; i += 512) {
        int r = i >> 5, q = i & 31;
        int gr = row0 + r;
        float4 a = (gr < nrows) ? ((const float4*)ctx)[(size_t)gr * 32 + q]
                                : make_float4(0.f, 0.f, 0.f, 0.f);
        unsigned h0, l0, h1, l1;
        bsplit2(a.x, a.y, h0, l0);
        bsplit2(a.z, a.w, h1, l1);
        Ah[r * PA + 2 * q]     = h0;  Ah[r * PA + 2 * q + 1] = h1;
        Al[r * PA + 2 * q]     = l0;  Al[r * PA + 2 * q + 1] = l1;
    }
    for (int i = tid; i < 2176; i += 512) {
        ((uint4*)Bh)[i] = ((const uint4*)Wh3)[i];
        ((uint4*)Bl)[i] = ((const uint4*)Wl3)[i];
    }
    __syncthreads();

    float d[4][2][4];
    mma_block_t<2>(Ah, Al, Bh, Bl, d, warpRow, warpCol, g, tq);
    __syncthreads();

    #pragma unroll
    for (int i = 0; i < 4; ++i) {
        int r0 = warpRow + i * 16 + g;
        #pragma unroll
        for (int j = 0; j < 2; ++j) {
            int c0 = warpCol + j * 8 + tq * 2;
            *(float2*)&O[r0 * 132 + c0]       = make_float2(d[i][j][0], d[i][j][1]);
            *(float2*)&O[(r0 + 8) * 132 + c0] = make_float2(d[i][j][2], d[i][j][3]);
        }
    }
    __syncthreads();

    {
        float4 bo = ((const float4*)out_b)[lane];
        float4 gg = ((const float4*)lng)[lane];
        float4 be = ((const float4*)lnb)[lane];
        for (int r = wid; r < 128; r += 16) {
            int gr = row0 + r;
            float4 v = *(float4*)&O[r * 132 + lane * 4];
            float4 qv = (gr < nrows) ? ((const float4*)(Qin + (size_t)gr * 128))[lane]
                                     : make_float4(0.f, 0.f, 0.f, 0.f);
            v.x += bo.x + qv.x; v.y += bo.y + qv.y;
            v.z += bo.z + qv.z; v.w += bo.w + qv.w;
            float s1 = v.x + v.y + v.z + v.w;
            float s2 = v.x*v.x + v.y*v.y + v.z*v.z + v.w*v.w;
            #pragma unroll
            for (int o = 16; o; o >>= 1) {
                s1 += __shfl_xor_sync(0xffffffffu, s1, o);
                s2 += __shfl_xor_sync(0xffffffffu, s2, o);
            }
            float mu   = s1 * (1.f / 128.f);
            float var  = fmaxf(s2 * (1.f / 128.f) - mu * mu, 0.f);
            float rstd = rsqrtf(var + 1e-8f);
            v.x = (v.x - mu) * rstd * gg.x + be.x;
            v.y = (v.y - mu) * rstd * gg.y + be.y;
            v.z = (v.z - mu) * rstd * gg.z + be.z;
            v.w = (v.w - mu) * rstd * gg.w + be.w;
            *(float4*)&O[r * 132 + lane * 4] = v;
            unsigned h0, l0, h1, l1;
            bsplit2(v.x, v.y, h0, l0);
            bsplit2(v.z, v.w, h1, l1);
            Ah[r * PA + lane * 2]     = h0;  Ah[r * PA + lane * 2 + 1] = h1;
            Al[r * PA + lane * 2]     = l0;  Al[r * PA + lane * 2 + 1] = l1;
        }
    }
    __syncthreads();

    for (int i = tid; i < 2176; i += 512) {
        ((uint4*)Bh)[i] = ((const uint4*)(Wh3 + WPC))[i];
        ((uint4*)Bl)[i] = ((const uint4*)(Wl3 + WPC))[i];
    }
    __syncthreads();
    mma_block_t<2>(Ah, Al, Bh, Bl, d, warpRow, warpCol, g, tq);
    __syncthreads();

    #pragma unroll
    for (int i = 0; i < 4; ++i) {
        #pragma unroll
        for (int j = 0; j < 2; ++j) {
            int c0 = warpCol + j * 8 + tq * 2;
            float bx = fb1[c0], by = fb1[c0 + 1];
            int r0 = warpRow + i * 16 + g;
            float v0 = fmaxf(d[i][j][0] + bx, 0.f);
            float v1 = fmaxf(d[i][j][1] + by, 0.f);
            float v2 = fmaxf(d[i][j][2] + bx, 0.f);
            float v3 = fmaxf(d[i][j][3] + by, 0.f);
            unsigned h0, l0, h1, l1;
            bsplit2(v0, v1, h0, l0);
            bsplit2(v2, v3, h1, l1);
            int w0 = r0 * PA + (c0 >> 1);
            int w1 = (r0 + 8) * PA + (c0 >> 1);
            Ah[w0] = h0;  Al[w0] = l0;
            Ah[w1] = h1;  Al[w1] = l1;
        }
    }
    __syncthreads();

    for (int i = tid; i < 2176; i += 512) {
        ((uint4*)Bh)[i] = ((const uint4*)(Wh3 + 2 * WPC))[i];
        ((uint4*)Bl)[i] = ((const uint4*)(Wl3 + 2 * WPC))[i];
    }
    __syncthreads();
    mma_block_t<2>(Ah, Al, Bh, Bl, d, warpRow, warpCol, g, tq);

    #pragma unroll
    for (int i = 0; i < 4; ++i) {
        #pragma unroll
        for (int half = 0; half < 2; ++half) {
            int r0 = warpRow + i * 16 + g + half * 8;
            int gr = row0 + r0;
            if (gr >= nrows) continue;
            int bsess = batch_ids[gr];
            float invl = 1.f / (float)lengths[bsess];
            float* outrow = pool_out + (size_t)bsess * 128;
            #pragma unroll
            for (int j = 0; j < 2; ++j) {
                int c0 = warpCol + j * 8 + tq * 2;
                float v0 = d[i][j][2 * half]     + fb2[c0]     + O[r0 * 132 + c0];
                float v1 = d[i][j][2 * half + 1] + fb2[c0 + 1] + O[r0 * 132 + c0 + 1];
                atomicAdd(outrow + c0,     v0 * invl);
                atomicAdd(outrow + c0 + 1, v1 * invl);
            }
        }
    }
}

// ---------------------------------------------------------------------------
// Tensor-core attention per (session, head), online-softmax chunked.
// 8 warps, warp per 16-row tile; 32-column chunks; sa[4][4] live.
// ---------------------------------------------------------------------------
__global__ void __launch_bounds__(256, 2)
attn_mma_kernel(const float* __restrict__ qp, const float* __restrict__ kp,
                const float* __restrict__ vp, float* __restrict__ ctx,
                const int* __restrict__ lengths)
{
    int b = blockIdx.x;
    int h = blockIdx.y;
    int n0 = d_starts[b];
    int l  = lengths[b];
    extern __shared__ unsigned sm[];
    unsigned* Qh = sm;                   // [160][QS]
    unsigned* Ql = Qh + 160 * QS;
    unsigned* Kh = Ql + 160 * QS;
    unsigned* Kl = Kh + 160 * QS;
    unsigned* Vh = Kl + 160 * QS;        // [32][VS]
    unsigned* Vl = Vh + 32 * VS;
    int tid = threadIdx.x;
    int hc  = h * 32;

    for (int i = tid; i < l * 16; i += 256) {
        int s = i >> 4, cp = i & 15;
        size_t gi = (((size_t)(n0 + s) * 128 + hc) >> 1) + cp;
        float2 qv = ((const float2*)qp)[gi];
        unsigned hi, lo;
        bsplit2(qv.x, qv.y, hi, lo);
        Qh[s * QS + cp] = hi; Ql[s * QS + cp] = lo;
        float2 kv = ((const float2*)kp)[gi];
        bsplit2(kv.x, kv.y, hi, lo);
        Kh[s * QS + cp] = hi; Kl[s * QS + cp] = lo;
    }
    int njp = (l + 1) >> 1;
    for (int i = tid; i < njp * 32; i += 256) {
        int jp = i >> 5, d = i & 31;
        int j0 = 2 * jp;
        float v0 = vp[(size_t)(n0 + j0) * 128 + hc + d];
        float v1 = (j0 + 1 < l) ? vp[(size_t)(n0 + j0 + 1) * 128 + hc + d] : 0.f;
        unsigned hi, lo;
        bsplit2(v0, v1, hi, lo);
        Vh[d * VS + jp] = hi; Vl[d * VS + jp] = lo;
    }
    int nchunks = (l + 31) >> 5;
    int jmax = nchunks * 16;
    for (int i = tid; i < (jmax - njp) * 32; i += 256) {
        int d = i & 31, jp = njp + (i >> 5);
        Vh[d * VS + jp] = 0u;
        Vl[d * VS + jp] = 0u;
    }
    __syncthreads();

    int lane = tid & 31, wid = tid >> 5;
    int g = lane >> 2, tq = lane & 3;
    int nrt = (l + 15) >> 4;
    const float scale = 0.17677669529663687f;   // 1/sqrt(32)

    for (int rt = wid; rt < nrt; rt += 8) {
        int i0 = rt * 16;
        unsigned qah[2][4], qal[2][4];
        #pragma unroll
        for (int kk = 0; kk < 2; ++kk) {
            int base = (i0 + g) * QS + kk * 8 + tq;
            qah[kk][0] = Qh[base];        qah[kk][1] = Qh[base + 8 * QS];
            qah[kk][2] = Qh[base + 4];    qah[kk][3] = Qh[base + 8 * QS + 4];
            qal[kk][0] = Ql[base];        qal[kk][1] = Ql[base + 8 * QS];
            qal[kk][2] = Ql[base + 4];    qal[kk][3] = Ql[base + 8 * QS + 4];
        }

        float ca[4][4];
        #pragma unroll
        for (int nt = 0; nt < 4; ++nt)
            ca[nt][0] = ca[nt][1] = ca[nt][2] = ca[nt][3] = 0.f;
        float m0 = -1e30f, m1 = -1e30f;   // running max (quad-uniform)
        float sum0 = 0.f, sum1 = 0.f;     // per-lane partial sums

        for (int ch = 0; ch < nchunks; ++ch) {
            float sa[4][4];
            #pragma unroll
            for (int ct = 0; ct < 4; ++ct)
                sa[ct][0] = sa[ct][1] = sa[ct][2] = sa[ct][3] = 0.f;

            #pragma unroll
            for (int ct = 0; ct < 4; ++ct) {
                #pragma unroll
                for (int kk = 0; kk < 2; ++kk) {
                    int base = ((ch * 4 + ct) * 8 + g) * QS + kk * 8 + tq;
                    unsigned bh0 = Kh[base], bh1 = Kh[base + 4];
                    unsigned bl0 = Kl[base], bl1 = Kl[base + 4];
                    MMA_BF16(sa[ct][0], sa[ct][1], sa[ct][2], sa[ct][3],
                             qah[kk][0], qah[kk][1], qah[kk][2], qah[kk][3], bh0, bh1);
                    MMA_BF16(sa[ct][0], sa[ct][1], sa[ct][2], sa[ct][3],
                             qah[kk][0], qah[kk][1], qah[kk][2], qah[kk][3], bl0, bl1);
                    MMA_BF16(sa[ct][0], sa[ct][1], sa[ct][2], sa[ct][3],
                             qal[kk][0], qal[kk][1], qal[kk][2], qal[kk][3], bh0, bh1);
                }
            }

            float cm0 = -1e30f, cm1 = -1e30f;
            #pragma unroll
            for (int ct = 0; ct < 4; ++ct) {
                int c0 = ch * 32 + ct * 8 + 2 * tq;
                bool v0 = c0 < l, v1 = (c0 + 1) < l;
                sa[ct][0] = v0 ? sa[ct][0] * scale : -1e30f;
                sa[ct][1] = v1 ? sa[ct][1] * scale : -1e30f;
                sa[ct][2] = v0 ? sa[ct][2] * scale : -1e30f;
                sa[ct][3] = v1 ? sa[ct][3] * scale : -1e30f;
                cm0 = fmaxf(cm0, fmaxf(sa[ct][0], sa[ct][1]));
                cm1 = fmaxf(cm1, fmaxf(sa[ct][2], sa[ct][3]));
            }
            cm0 = fmaxf(cm0, __shfl_xor_sync(0xffffffffu, cm0, 1));
            cm0 = fmaxf(cm0, __shfl_xor_sync(0xffffffffu, cm0, 2));
            cm1 = fmaxf(cm1, __shfl_xor_sync(0xffffffffu, cm1, 1));
            cm1 = fmaxf(cm1, __shfl_xor_sync(0xffffffffu, cm1, 2));

            float nm0 = fmaxf(m0, cm0);
            float nm1 = fmaxf(m1, cm1);
            float al0 = __expf(m0 - nm0);
            float al1 = __expf(m1 - nm1);
            m0 = nm0; m1 = nm1;
            sum0 *= al0; sum1 *= al1;
            #pragma unroll
            for (int nt = 0; nt < 4; ++nt) {
                ca[nt][0] *= al0; ca[nt][1] *= al0;
                ca[nt][2] *= al1; ca[nt][3] *= al1;
            }

            #pragma unroll
            for (int ct = 0; ct < 4; ++ct) {
                int c0 = ch * 32 + ct * 8 + 2 * tq;
                float e0 = (c0 < l)     ? __expf(sa[ct][0] - m0) : 0.f;
                float e1 = (c0 + 1 < l) ? __expf(sa[ct][1] - m0) : 0.f;
                float e2 = (c0 < l)     ? __expf(sa[ct][2] - m1) : 0.f;
                float e3 = (c0 + 1 < l) ? __expf(sa[ct][3] - m1) : 0.f;
                sa[ct][0] = e0; sa[ct][1] = e1; sa[ct][2] = e2; sa[ct][3] = e3;
                sum0 += e0 + e1; sum1 += e2 + e3;
            }

            #pragma unroll
            for (int kk2 = 0; kk2 < 2; ++kk2) {
                unsigned pah[4], pal[4];
                bsplit2(sa[2*kk2][0],   sa[2*kk2][1],   pah[0], pal[0]);
                bsplit2(sa[2*kk2][2],   sa[2*kk2][3],   pah[1], pal[1]);
                bsplit2(sa[2*kk2+1][0], sa[2*kk2+1][1], pah[2], pal[2]);
                bsplit2(sa[2*kk2+1][2], sa[2*kk2+1][3], pah[3], pal[3]);
                #pragma unroll
                for (int nt = 0; nt < 4; ++nt) {
                    int base = (nt * 8 + g) * VS + (ch * 2 + kk2) * 8 + tq;
                    unsigned bh0 = Vh[base], bh1 = Vh[base + 4];
                    unsigned bl0 = Vl[base], bl1 = Vl[base + 4];
                    MMA_BF16(ca[nt][0], ca[nt][1], ca[nt][2], ca[nt][3],
                             pah[0], pah[1], pah[2], pah[3], bh0, bh1);
                    MMA_BF16(ca[nt][0], ca[nt][1], ca[nt][2], ca[nt][3],
                             pah[0], pah[1], pah[2], pah[3], bl0, bl1);
                    MMA_BF16(ca[nt][0], ca[nt][1], ca[nt][2], ca[nt][3],
                             pal[0], pal[1], pal[2], pal[3], bh0, bh1);
                }
            }
        }

        sum0 += __shfl_xor_sync(0xffffffffu, sum0, 1);
        sum0 += __shfl_xor_sync(0xffffffffu, sum0, 2);
        sum1 += __shfl_xor_sync(0xffffffffu, sum1, 1);
        sum1 += __shfl_xor_sync(0xffffffffu, sum1, 2);

        float inv0 = 1.f / sum0;
        float inv1 = 1.f / sum1;
        int r0 = i0 + g, r1 = i0 + 8 + g;
        #pragma unroll
        for (int nt = 0; nt < 4; ++nt) {
            int dcol = nt * 8 + 2 * tq;
            if (r0 < l)
                *(float2*)(ctx + (size_t)(n0 + r0) * 128 + hc + dcol) =
                    make_float2(ca[nt][0] * inv0, ca[nt][1] * inv0);
            if (r1 < l)
                *(float2*)(ctx + (size_t)(n0 + r1) * 128 + hc + dcol) =
                    make_float2(ca[nt][2] * inv1, ca[nt][3] * inv1);
        }
    }
}

// ---------------------------------------------------------------------------
extern "C" void kernel_launch(void* const* d_in, const int* in_sizes, int n_in,
                              void* d_out, int out_size)
{
    const float* POI    = (const float*)d_in[0];
    const float* dde    = (const float*)d_in[1];
    const float* attW   = (const float*)d_in[2];
    const float* a_src  = (const float*)d_in[3];
    const float* a_dst  = (const float*)d_in[4];
    const float* in_w   = (const float*)d_in[5];
    const float* in_b   = (const float*)d_in[6];
    const float* out_w  = (const float*)d_in[7];
    const float* out_b  = (const float*)d_in[8];
    const float* ln1g   = (const float*)d_in[9];
    const float* ln1b   = (const float*)d_in[10];
    const float* ln2g   = (const float*)d_in[11];
    const float* ln2b   = (const float*)d_in[12];
    const float* fw1    = (const float*)d_in[13];
    const float* fb1    = (const float*)d_in[14];
    const float* fw2    = (const float*)d_in[15];
    const float* fb2    = (const float*)d_in[16];
    const int* sess_idx  = (const int*)d_in[17];
    const int* edge_dist = (const int*)d_in[18];
    const int* batch_ids = (const int*)d_in[20];
    const int* node_pos  = (const int*)d_in[21];
    const int* lengths   = (const int*)d_in[22];
    int N = in_sizes[17];
    int B = in_sizes[22];
    float* outp = (float*)d_out;

    float *b0, *b1, *b2, *b3, *b4;
    unsigned *wh, *wl;
    cudaGetSymbolAddress((void**)&b0, g_buf0);
    cudaGetSymbolAddress((void**)&b1, g_buf1);
    cudaGetSymbolAddress((void**)&b2, g_buf2);
    cudaGetSymbolAddress((void**)&b3, g_buf3);
    cudaGetSymbolAddress((void**)&b4, g_buf4);
    cudaGetSymbolAddress((void**)&wh, d_wh);
    cudaGetSymbolAddress((void**)&wl, d_wl);

    const int qkv_smem  = 6 * WPC * (int)sizeof(unsigned);                       // ~208.9 KB
    const int tail_smem = 4 * WPC * (int)sizeof(unsigned)
                        + 128 * 132 * (int)sizeof(float);                        // ~206.8 KB
    const int attn_smem = (4 * 160 * QS + 2 * 32 * VS) * (int)sizeof(unsigned);  // ~72.7 KB
    cudaFuncSetAttribute(qkv_kernel,      cudaFuncAttributeMaxDynamicSharedMemorySize, qkv_smem);
    cudaFuncSetAttribute(tail_kernel,     cudaFuncAttributeMaxDynamicSharedMemorySize, tail_smem);
    cudaFuncSetAttribute(attn_mma_kernel, cudaFuncAttributeMaxDynamicSharedMemorySize, attn_smem);

    head_kernel<<<16, 1024>>>(lengths, B, attW, a_src, a_dst,
                              in_w, out_w, fw1, fw2, outp, out_size);

    gcn_kernel<<<(N + 7) / 8, 256>>>(POI, dde, sess_idx, edge_dist,
                                     batch_ids, node_pos, lengths, N);

    int gblocks = (N + 127) / 128;
    qkv_kernel<<<gblocks, 512, qkv_smem>>>(b0, wh, wl, in_b, ln1g, ln1b,
                                           b2, b3, b4, b1, N);

    dim3 ag(B, 4);
    attn_mma_kernel<<<ag, 256, attn_smem>>>(b2, b3, b4, b0, lengths);

    tail_kernel<<<gblocks, 512, tail_smem>>>(b0, b1, wh + 3 * WPC, wl + 3 * WPC,
                                             out_b, fb1, fb2, ln2g, ln2b,
                                             batch_ids, lengths, outp, N);
}

// round 13
// speedup vs baseline: 3.5626x; 1.0216x over previous
#include <cuda_runtime.h>
#include <cuda_bf16.h>
#include <math.h>

// ---------------------------------------------------------------------------
// SeqGraphRepNetwork on GB300 — packed formulation.
// R13: attention — Q fragments loaded directly from gmem (no Q smem),
//      smem 72.7->47KB, __launch_bounds__(256,3) for 3 blocks/SM;
//      length-descending block schedule via counting sort.
// ---------------------------------------------------------------------------

#define NMAX   163840
#define LMAX   160
#define BMAXS  1024
#define PA     68            // gemm smem row stride (words)
#define WPC    (128 * PA)    // words per weight plane
#define QS     20            // attn K smem row stride (words)
#define VS     84            // attn V^T smem row stride (words)

__device__ float d_vsrc[128];
__device__ float d_vdst[128];
__device__ int   d_starts[BMAXS + 1];
__device__ int   d_order[BMAXS];             // sessions sorted by length desc
__device__ unsigned d_wh[6 * WPC];           // weight hi-plane, gemm layout
__device__ unsigned d_wl[6 * WPC];           // weight lo-plane
__device__ float g_buf0[(size_t)NMAX * 128]; // Hu, later ctx
__device__ float g_buf1[(size_t)NMAX * 128]; // Qin (LN1 output)
__device__ float g_buf2[(size_t)NMAX * 128]; // q proj
__device__ float g_buf3[(size_t)NMAX * 128]; // k proj
__device__ float g_buf4[(size_t)NMAX * 128]; // v proj

// ---------------------------------------------------------------------------
__device__ __forceinline__ void bsplit2(float a0, float a1,
                                        unsigned &hi, unsigned &lo)
{
    __nv_bfloat162 h = __float22bfloat162_rn(make_float2(a0, a1));
    float r0 = a0 - __low2float(h);
    float r1 = a1 - __high2float(h);
    __nv_bfloat162 l = __float22bfloat162_rn(make_float2(r0, r1));
    hi = *(unsigned*)&h;
    lo = *(unsigned*)&l;
}

#define MMA_BF16(d0,d1,d2,d3, a0,a1,a2,a3, b0,b1)                         \
    asm volatile("mma.sync.aligned.m16n8k16.row.col.f32.bf16.bf16.f32 "   \
                 "{%0,%1,%2,%3}, {%4,%5,%6,%7}, {%8,%9}, {%0,%1,%2,%3};"  \
                 : "+f"(d0), "+f"(d1), "+f"(d2), "+f"(d3)                 \
                 : "r"(a0), "r"(a1), "r"(a2), "r"(a3), "r"(b0), "r"(b1))

// 128-row x (NJ*8)-col warp tile block mma over K=128, 3-term split-bf16.
template<int NJ>
__device__ __forceinline__ void mma_block_t(
    const unsigned* __restrict__ Ah, const unsigned* __restrict__ Al,
    const unsigned* __restrict__ Bh, const unsigned* __restrict__ Bl,
    float d[4][NJ][4], int warpRow, int warpCol, int g, int tq)
{
    #pragma unroll
    for (int i = 0; i < 4; ++i)
        #pragma unroll
        for (int j = 0; j < NJ; ++j)
            d[i][j][0] = d[i][j][1] = d[i][j][2] = d[i][j][3] = 0.f;

    #pragma unroll
    for (int kk = 0; kk < 8; ++kk) {
        unsigned ah[4][4], al[4][4], bh[NJ][2], bl[NJ][2];
        #pragma unroll
        for (int i = 0; i < 4; ++i) {
            int base = (warpRow + i * 16 + g) * PA + kk * 8 + tq;
            ah[i][0] = Ah[base];            ah[i][1] = Ah[base + 8 * PA];
            ah[i][2] = Ah[base + 4];        ah[i][3] = Ah[base + 8 * PA + 4];
            al[i][0] = Al[base];            al[i][1] = Al[base + 8 * PA];
            al[i][2] = Al[base + 4];        al[i][3] = Al[base + 8 * PA + 4];
        }
        #pragma unroll
        for (int j = 0; j < NJ; ++j) {
            int base = (warpCol + j * 8 + g) * PA + kk * 8 + tq;
            bh[j][0] = Bh[base];  bh[j][1] = Bh[base + 4];
            bl[j][0] = Bl[base];  bl[j][1] = Bl[base + 4];
        }
        #pragma unroll
        for (int i = 0; i < 4; ++i)
            #pragma unroll
            for (int j = 0; j < NJ; ++j) {
                MMA_BF16(d[i][j][0], d[i][j][1], d[i][j][2], d[i][j][3],
                         ah[i][0], ah[i][1], ah[i][2], ah[i][3],
                         bh[j][0], bh[j][1]);
                MMA_BF16(d[i][j][0], d[i][j][1], d[i][j][2], d[i][j][3],
                         ah[i][0], ah[i][1], ah[i][2], ah[i][3],
                         bl[j][0], bl[j][1]);
                MMA_BF16(d[i][j][0], d[i][j][1], d[i][j][2], d[i][j][3],
                         al[i][0], al[i][1], al[i][2], al[i][3],
                         bh[j][0], bh[j][1]);
            }
    }
}

// ---------------------------------------------------------------------------
// Head: block 0 = scan + length-desc counting sort; block 1 = prep vectors;
// blocks 2-7 = weight split; blocks 8-15 = zero the pool output.
// ---------------------------------------------------------------------------
__global__ void head_kernel(const int* __restrict__ lengths, int B,
                            const float* __restrict__ attW,
                            const float* __restrict__ a_src,
                            const float* __restrict__ a_dst,
                            const float* __restrict__ in_w,
                            const float* __restrict__ out_w,
                            const float* __restrict__ fw1,
                            const float* __restrict__ fw2,
                            float* __restrict__ outp, int out_n)
{
    __shared__ int s[BMAXS];
    __shared__ int hist[192];
    int blk = blockIdx.x;
    int t = threadIdx.x;
    if (blk == 0) {
        int v = (t < B) ? lengths[t] : 0;
        s[t] = v;
        __syncthreads();
        for (int o = 1; o < BMAXS; o <<= 1) {
            int add = (t >= o) ? s[t - o] : 0;
            __syncthreads();
            s[t] += add;
            __syncthreads();
        }
        if (t < B) d_starts[t] = s[t] - v;
        if (t == B - 1) d_starts[B] = s[t];
        // counting sort of sessions by length, descending
        if (t < 192) hist[t] = 0;
        __syncthreads();
        int li = 0;
        if (t < B) {
            li = lengths[t];
            if (li > 191) li = 191;
            if (li < 0) li = 0;
            atomicAdd(&hist[li], 1);
        }
        __syncthreads();
        if (t == 0) {
            int acc = 0;
            for (int L = 191; L >= 0; --L) { int c = hist[L]; hist[L] = acc; acc += c; }
        }
        __syncthreads();
        if (t < B) {
            int pos = atomicAdd(&hist[li], 1);
            d_order[pos] = t;
        }
    } else if (blk == 1) {
        if (t < 128) {
            float vs = 0.f, vd = 0.f;
            #pragma unroll 4
            for (int k = 0; k < 128; ++k) {
                float w = attW[k * 128 + t];
                vs += a_src[k] * w;
                vd += a_dst[k] * w;
            }
            d_vsrc[t] = vs;
            d_vdst[t] = vd;
        }
    } else if (blk < 8) {
        int m = blk - 2;
        const float* src = (m < 3) ? (in_w + m * 16384)
                         : (m == 3 ? out_w : (m == 4 ? fw1 : fw2));
        unsigned* wh = d_wh + m * WPC;
        unsigned* wl = d_wl + m * WPC;
        for (int i = t; i < 4096; i += 1024) {
            int r = i >> 5, q = i & 31;
            float4 w = ((const float4*)src)[i];
            unsigned h0, l0, h1, l1;
            bsplit2(w.x, w.y, h0, l0);
            bsplit2(w.z, w.w, h1, l1);
            wh[r * PA + 2 * q]     = h0;  wh[r * PA + 2 * q + 1] = h1;
            wl[r * PA + 2 * q]     = l0;  wl[r * PA + 2 * q + 1] = l1;
        }
    } else {
        for (int i = (blk - 8) * 1024 + t; i < out_n; i += 8 * 1024)
            outp[i] = 0.f;
    }
}

// ---------------------------------------------------------------------------
// GCN: warp per node; node-local edge logits; 2-way softmax aggregate.
// ---------------------------------------------------------------------------
__global__ void gcn_kernel(const float* __restrict__ POI,
                           const float* __restrict__ dde,
                           const int*   __restrict__ sess_idx,
                           const int*   __restrict__ edge_dist,
                           const int*   __restrict__ batch_ids,
                           const int*   __restrict__ node_pos,
                           const int*   __restrict__ lengths, int N)
{
    int n = blockIdx.x * 8 + (threadIdx.x >> 5);
    if (n >= N) return;
    int lane = threadIdx.x & 31;
    int b = batch_ids[n];
    int p = node_pos[n];
    int l = lengths[b];
    bool h1 = (p > 0);
    bool h2 = (p < l - 1);

    float4 va = ((const float4*)d_vsrc)[lane];
    float4 vb = ((const float4*)d_vdst)[lane];
    float4 xo = ((const float4*)(POI + (size_t)sess_idx[n] * 128))[lane];
    float p1 = xo.x*va.x + xo.y*va.y + xo.z*va.z + xo.w*va.w;
    float p2 = xo.x*vb.x + xo.y*vb.y + xo.z*vb.z + xo.w*vb.w;
    float qq = 0.f;
    if (h1) {
        float4 xe = ((const float4*)(dde + (size_t)edge_dist[n - 1 - b] * 128))[lane];
        qq = xe.x*va.x + xe.y*va.y + xe.z*va.z + xe.w*va.w;
    }
    #pragma unroll
    for (int o = 16; o; o >>= 1) {
        p1 += __shfl_xor_sync(0xffffffffu, p1, o);
        p2 += __shfl_xor_sync(0xffffffffu, p2, o);
        qq += __shfl_xor_sync(0xffffffffu, qq, o);
    }

    float L1 = h1 ? (p1 + qq) : -1e30f;
    float L2 = h2 ? p2 : -1e30f;
    float m  = fmaxf(L1, L2);
    float e1 = h1 ? expf(L1 - m) : 0.f;
    float e2 = h2 ? expf(L2 - m) : 0.f;
    float inv = 1.f / (e1 + e2 + 1e-16f);
    float a1 = e1 * inv, a2 = e2 * inv;

    float4 hu = make_float4(0.f, 0.f, 0.f, 0.f);
    if (h1) {
        float4 x = ((const float4*)(POI + (size_t)sess_idx[n - 1] * 128))[lane];
        hu.x += a1 * x.x; hu.y += a1 * x.y; hu.z += a1 * x.z; hu.w += a1 * x.w;
    }
    if (h2) {
        float4 x = ((const float4*)(POI + (size_t)sess_idx[n + 1] * 128))[lane];
        hu.x += a2 * x.x; hu.y += a2 * x.y; hu.z += a2 * x.z; hu.w += a2 * x.w;
    }
    ((float4*)g_buf0)[(size_t)n * 32 + lane] = hu;
}

// ---------------------------------------------------------------------------
// Fused LN1 + QKV projections. One block = 128 rows, 512 threads.
// ---------------------------------------------------------------------------
__global__ void __launch_bounds__(512, 1)
qkv_kernel(const float* __restrict__ Hu,
           const unsigned* __restrict__ Wh3, const unsigned* __restrict__ Wl3,
           const float* __restrict__ in_b,
           const float* __restrict__ g1, const float* __restrict__ b1v,
           float* __restrict__ qout, float* __restrict__ kout,
           float* __restrict__ vout, float* __restrict__ qinout, int nrows)
{
    extern __shared__ unsigned smu[];
    unsigned* AhH = smu;
    unsigned* AlH = AhH + WPC;
    unsigned* AhQ = AlH + WPC;
    unsigned* AlQ = AhQ + WPC;
    unsigned* Bh  = AlQ + WPC;
    unsigned* Bl  = Bh + WPC;
    float* stage  = (float*)Bh;          // fp32 Hu staging [128][132]
    int tid  = threadIdx.x;
    int row0 = blockIdx.x * 128;
    int lane = tid & 31, wid = tid >> 5;
    int g  = lane >> 2, tq = lane & 3;
    int warpRow = (wid & 1) * 64;
    int warpCol = (wid >> 1) * 16;

    for (int i = tid; i < 4096; i += 512) {
        int r = i >> 5, q = i & 31;
        int gr = row0 + r;
        float4 a = (gr < nrows) ? ((const float4*)Hu)[(size_t)gr * 32 + q]
                                : make_float4(0.f, 0.f, 0.f, 0.f);
        unsigned h0, l0, h1, l1;
        bsplit2(a.x, a.y, h0, l0);
        bsplit2(a.z, a.w, h1, l1);
        AhH[r * PA + 2 * q]     = h0;  AhH[r * PA + 2 * q + 1] = h1;
        AlH[r * PA + 2 * q]     = l0;  AlH[r * PA + 2 * q + 1] = l1;
        *(float4*)&stage[r * 132 + q * 4] = a;
    }
    __syncthreads();

    {
        float4 gg = ((const float4*)g1)[lane];
        float4 bb = ((const float4*)b1v)[lane];
        for (int r = wid; r < 128; r += 16) {
            float4 v = *(float4*)&stage[r * 132 + lane * 4];
            float s1 = v.x + v.y + v.z + v.w;
            float s2 = v.x*v.x + v.y*v.y + v.z*v.z + v.w*v.w;
            #pragma unroll
            for (int o = 16; o; o >>= 1) {
                s1 += __shfl_xor_sync(0xffffffffu, s1, o);
                s2 += __shfl_xor_sync(0xffffffffu, s2, o);
            }
            float mu   = s1 * (1.f / 128.f);
            float var  = fmaxf(s2 * (1.f / 128.f) - mu * mu, 0.f);
            float rstd = rsqrtf(var + 1e-8f);
            float4 o4;
            o4.x = (v.x - mu) * rstd * gg.x + bb.x;
            o4.y = (v.y - mu) * rstd * gg.y + bb.y;
            o4.z = (v.z - mu) * rstd * gg.z + bb.z;
            o4.w = (v.w - mu) * rstd * gg.w + bb.w;
            int gr = row0 + r;
            if (gr < nrows)
                ((float4*)(qinout + (size_t)gr * 128))[lane] = o4;
            unsigned h0, l0, h1, l1;
            bsplit2(o4.x, o4.y, h0, l0);
            bsplit2(o4.z, o4.w, h1, l1);
            AhQ[r * PA + lane * 2]     = h0;  AhQ[r * PA + lane * 2 + 1] = h1;
            AlQ[r * PA + lane * 2]     = l0;  AlQ[r * PA + lane * 2 + 1] = l1;
        }
    }

    float d[4][2][4];
    for (int s = 0; s < 3; ++s) {
        __syncthreads();
        const uint4* wh4 = (const uint4*)(Wh3 + s * WPC);
        const uint4* wl4 = (const uint4*)(Wl3 + s * WPC);
        for (int i = tid; i < 2176; i += 512) {
            ((uint4*)Bh)[i] = wh4[i];
            ((uint4*)Bl)[i] = wl4[i];
        }
        __syncthreads();
        const unsigned* Ah = (s == 0) ? AhQ : AhH;
        const unsigned* Al = (s == 0) ? AlQ : AlH;
        mma_block_t<2>(Ah, Al, Bh, Bl, d, warpRow, warpCol, g, tq);

        float* op = (s == 0) ? qout : ((s == 1) ? kout : vout);
        const float* bias = in_b + s * 128;
        #pragma unroll
        for (int j = 0; j < 2; ++j) {
            int c0 = warpCol + j * 8 + tq * 2;
            float bj0 = bias[c0], bj1 = bias[c0 + 1];
            #pragma unroll
            for (int i = 0; i < 4; ++i) {
                int r0 = warpRow + i * 16 + g;
                int gr = row0 + r0;
                if (gr < nrows)
                    *(float2*)(op + (size_t)gr * 128 + c0) =
                        make_float2(d[i][j][0] + bj0, d[i][j][1] + bj1);
                if (gr + 8 < nrows)
                    *(float2*)(op + (size_t)(gr + 8) * 128 + c0) =
                        make_float2(d[i][j][2] + bj0, d[i][j][3] + bj1);
            }
        }
    }
}

// ---------------------------------------------------------------------------
// Fused tail: out2 = LN2(ctx@Wo^T + bo + Qin); h = relu(out2@W1^T + b1);
// out3 = h@W2^T + b2 + out2; S_u += out3 / l.  512 threads.
// ---------------------------------------------------------------------------
__global__ void __launch_bounds__(512, 1)
tail_kernel(const float* __restrict__ ctx, const float* __restrict__ Qin,
            const unsigned* __restrict__ Wh3, const unsigned* __restrict__ Wl3,
            const float* __restrict__ out_b, const float* __restrict__ fb1,
            const float* __restrict__ fb2,
            const float* __restrict__ lng, const float* __restrict__ lnb,
            const int* __restrict__ batch_ids, const int* __restrict__ lengths,
            float* __restrict__ pool_out, int nrows)
{
    extern __shared__ unsigned smu[];
    unsigned* Ah = smu;                       // [128][PA]
    unsigned* Al = Ah + WPC;
    unsigned* Bh = Al + WPC;
    unsigned* Bl = Bh + WPC;
    float*    O  = (float*)(Bl + WPC);        // [128][132] fp32 out2
    int tid  = threadIdx.x;
    int row0 = blockIdx.x * 128;
    int lane = tid & 31, wid = tid >> 5;
    int g  = lane >> 2, tq = lane & 3;
    int warpRow = (wid & 1) * 64;
    int warpCol = (wid >> 1) * 16;

    for (int i = tid; i < 4096; i += 512) {
        int r = i >> 5, q = i & 31;
        int gr = row0 + r;
        float4 a = (gr < nrows) ? ((const float4*)ctx)[(size_t)gr * 32 + q]
                                : make_float4(0.f, 0.f, 0.f, 0.f);
        unsigned h0, l0, h1, l1;
        bsplit2(a.x, a.y, h0, l0);
        bsplit2(a.z, a.w, h1, l1);
        Ah[r * PA + 2 * q]     = h0;  Ah[r * PA + 2 * q + 1] = h1;
        Al[r * PA + 2 * q]     = l0;  Al[r * PA + 2 * q + 1] = l1;
    }
    for (int i = tid; i < 2176; i += 512) {
        ((uint4*)Bh)[i] = ((const uint4*)Wh3)[i];
        ((uint4*)Bl)[i] = ((const uint4*)Wl3)[i];
    }
    __syncthreads();

    float d[4][2][4];
    mma_block_t<2>(Ah, Al, Bh, Bl, d, warpRow, warpCol, g, tq);
    __syncthreads();

    #pragma unroll
    for (int i = 0; i < 4; ++i) {
        int r0 = warpRow + i * 16 + g;
        #pragma unroll
        for (int j = 0; j < 2; ++j) {
            int c0 = warpCol + j * 8 + tq * 2;
            *(float2*)&O[r0 * 132 + c0]       = make_float2(d[i][j][0], d[i][j][1]);
            *(float2*)&O[(r0 + 8) * 132 + c0] = make_float2(d[i][j][2], d[i][j][3]);
        }
    }
    __syncthreads();

    {
        float4 bo = ((const float4*)out_b)[lane];
        float4 gg = ((const float4*)lng)[lane];
        float4 be = ((const float4*)lnb)[lane];
        for (int r = wid; r < 128; r += 16) {
            int gr = row0 + r;
            float4 v = *(float4*)&O[r * 132 + lane * 4];
            float4 qv = (gr < nrows) ? ((const float4*)(Qin + (size_t)gr * 128))[lane]
                                     : make_float4(0.f, 0.f, 0.f, 0.f);
            v.x += bo.x + qv.x; v.y += bo.y + qv.y;
            v.z += bo.z + qv.z; v.w += bo.w + qv.w;
            float s1 = v.x + v.y + v.z + v.w;
            float s2 = v.x*v.x + v.y*v.y + v.z*v.z + v.w*v.w;
            #pragma unroll
            for (int o = 16; o; o >>= 1) {
                s1 += __shfl_xor_sync(0xffffffffu, s1, o);
                s2 += __shfl_xor_sync(0xffffffffu, s2, o);
            }
            float mu   = s1 * (1.f / 128.f);
            float var  = fmaxf(s2 * (1.f / 128.f) - mu * mu, 0.f);
            float rstd = rsqrtf(var + 1e-8f);
            v.x = (v.x - mu) * rstd * gg.x + be.x;
            v.y = (v.y - mu) * rstd * gg.y + be.y;
            v.z = (v.z - mu) * rstd * gg.z + be.z;
            v.w = (v.w - mu) * rstd * gg.w + be.w;
            *(float4*)&O[r * 132 + lane * 4] = v;
            unsigned h0, l0, h1, l1;
            bsplit2(v.x, v.y, h0, l0);
            bsplit2(v.z, v.w, h1, l1);
            Ah[r * PA + lane * 2]     = h0;  Ah[r * PA + lane * 2 + 1] = h1;
            Al[r * PA + lane * 2]     = l0;  Al[r * PA + lane * 2 + 1] = l1;
        }
    }
    __syncthreads();

    for (int i = tid; i < 2176; i += 512) {
        ((uint4*)Bh)[i] = ((const uint4*)(Wh3 + WPC))[i];
        ((uint4*)Bl)[i] = ((const uint4*)(Wl3 + WPC))[i];
    }
    __syncthreads();
    mma_block_t<2>(Ah, Al, Bh, Bl, d, warpRow, warpCol, g, tq);
    __syncthreads();

    #pragma unroll
    for (int i = 0; i < 4; ++i) {
        #pragma unroll
        for (int j = 0; j < 2; ++j) {
            int c0 = warpCol + j * 8 + tq * 2;
            float bx = fb1[c0], by = fb1[c0 + 1];
            int r0 = warpRow + i * 16 + g;
            float v0 = fmaxf(d[i][j][0] + bx, 0.f);
            float v1 = fmaxf(d[i][j][1] + by, 0.f);
            float v2 = fmaxf(d[i][j][2] + bx, 0.f);
            float v3 = fmaxf(d[i][j][3] + by, 0.f);
            unsigned h0, l0, h1, l1;
            bsplit2(v0, v1, h0, l0);
            bsplit2(v2, v3, h1, l1);
            int w0 = r0 * PA + (c0 >> 1);
            int w1 = (r0 + 8) * PA + (c0 >> 1);
            Ah[w0] = h0;  Al[w0] = l0;
            Ah[w1] = h1;  Al[w1] = l1;
        }
    }
    __syncthreads();

    for (int i = tid; i < 2176; i += 512) {
        ((uint4*)Bh)[i] = ((const uint4*)(Wh3 + 2 * WPC))[i];
        ((uint4*)Bl)[i] = ((const uint4*)(Wl3 + 2 * WPC))[i];
    }
    __syncthreads();
    mma_block_t<2>(Ah, Al, Bh, Bl, d, warpRow, warpCol, g, tq);

    #pragma unroll
    for (int i = 0; i < 4; ++i) {
        #pragma unroll
        for (int half = 0; half < 2; ++half) {
            int r0 = warpRow + i * 16 + g + half * 8;
            int gr = row0 + r0;
            if (gr >= nrows) continue;
            int bsess = batch_ids[gr];
            float invl = 1.f / (float)lengths[bsess];
            float* outrow = pool_out + (size_t)bsess * 128;
            #pragma unroll
            for (int j = 0; j < 2; ++j) {
                int c0 = warpCol + j * 8 + tq * 2;
                float v0 = d[i][j][2 * half]     + fb2[c0]     + O[r0 * 132 + c0];
                float v1 = d[i][j][2 * half + 1] + fb2[c0 + 1] + O[r0 * 132 + c0 + 1];
                atomicAdd(outrow + c0,     v0 * invl);
                atomicAdd(outrow + c0 + 1, v1 * invl);
            }
        }
    }
}

// ---------------------------------------------------------------------------
// Tensor-core attention per (session, head), online-softmax chunked.
// Q fragments loaded straight from gmem; K/V split planes in smem (47KB).
// ---------------------------------------------------------------------------
__global__ void __launch_bounds__(256, 3)
attn_mma_kernel(const float* __restrict__ qp, const float* __restrict__ kp,
                const float* __restrict__ vp, float* __restrict__ ctx,
                const int* __restrict__ lengths)
{
    int b = d_order[blockIdx.x];
    int h = blockIdx.y;
    int n0 = d_starts[b];
    int l  = lengths[b];
    extern __shared__ unsigned sm[];
    unsigned* Kh = sm;                   // [160][QS]
    unsigned* Kl = Kh + 160 * QS;
    unsigned* Vh = Kl + 160 * QS;        // [32][VS]
    unsigned* Vl = Vh + 32 * VS;
    int tid = threadIdx.x;
    int hc  = h * 32;

    for (int i = tid; i < l * 16; i += 256) {
        int s = i >> 4, cp = i & 15;
        size_t gi = (((size_t)(n0 + s) * 128 + hc) >> 1) + cp;
        float2 kv = ((const float2*)kp)[gi];
        unsigned hi, lo;
        bsplit2(kv.x, kv.y, hi, lo);
        Kh[s * QS + cp] = hi; Kl[s * QS + cp] = lo;
    }
    int njp = (l + 1) >> 1;
    for (int i = tid; i < njp * 32; i += 256) {
        int jp = i >> 5, d = i & 31;
        int j0 = 2 * jp;
        float v0 = vp[(size_t)(n0 + j0) * 128 + hc + d];
        float v1 = (j0 + 1 < l) ? vp[(size_t)(n0 + j0 + 1) * 128 + hc + d] : 0.f;
        unsigned hi, lo;
        bsplit2(v0, v1, hi, lo);
        Vh[d * VS + jp] = hi; Vl[d * VS + jp] = lo;
    }
    int nchunks = (l + 31) >> 5;
    int jmax = nchunks * 16;
    for (int i = tid; i < (jmax - njp) * 32; i += 256) {
        int d = i & 31, jp = njp + (i >> 5);
        Vh[d * VS + jp] = 0u;
        Vl[d * VS + jp] = 0u;
    }
    __syncthreads();

    int lane = tid & 31, wid = tid >> 5;
    int g = lane >> 2, tq = lane & 3;
    int nrt = (l + 15) >> 4;
    const float scale = 0.17677669529663687f;   // 1/sqrt(32)

    for (int rt = wid; rt < nrt; rt += 8) {
        int i0 = rt * 16;
        // Q fragments direct from gmem (rows beyond l produce unused garbage)
        unsigned qah[2][4], qal[2][4];
        {
            const float2* qr0 = (const float2*)(qp + (size_t)(n0 + i0 + g) * 128 + hc);
            const float2* qr1 = (const float2*)(qp + (size_t)(n0 + i0 + 8 + g) * 128 + hc);
            #pragma unroll
            for (int kk = 0; kk < 2; ++kk) {
                float2 v;
                v = qr0[kk * 8 + tq];     bsplit2(v.x, v.y, qah[kk][0], qal[kk][0]);
                v = qr1[kk * 8 + tq];     bsplit2(v.x, v.y, qah[kk][1], qal[kk][1]);
                v = qr0[kk * 8 + tq + 4]; bsplit2(v.x, v.y, qah[kk][2], qal[kk][2]);
                v = qr1[kk * 8 + tq + 4]; bsplit2(v.x, v.y, qah[kk][3], qal[kk][3]);
            }
        }

        float ca[4][4];
        #pragma unroll
        for (int nt = 0; nt < 4; ++nt)
            ca[nt][0] = ca[nt][1] = ca[nt][2] = ca[nt][3] = 0.f;
        float m0 = -1e30f, m1 = -1e30f;   // running max (quad-uniform)
        float sum0 = 0.f, sum1 = 0.f;     // per-lane partial sums

        for (int ch = 0; ch < nchunks; ++ch) {
            float sa[4][4];
            #pragma unroll
            for (int ct = 0; ct < 4; ++ct)
                sa[ct][0] = sa[ct][1] = sa[ct][2] = sa[ct][3] = 0.f;

            #pragma unroll
            for (int ct = 0; ct < 4; ++ct) {
                #pragma unroll
                for (int kk = 0; kk < 2; ++kk) {
                    int base = ((ch * 4 + ct) * 8 + g) * QS + kk * 8 + tq;
                    unsigned bh0 = Kh[base], bh1 = Kh[base + 4];
                    unsigned bl0 = Kl[base], bl1 = Kl[base + 4];
                    MMA_BF16(sa[ct][0], sa[ct][1], sa[ct][2], sa[ct][3],
                             qah[kk][0], qah[kk][1], qah[kk][2], qah[kk][3], bh0, bh1);
                    MMA_BF16(sa[ct][0], sa[ct][1], sa[ct][2], sa[ct][3],
                             qah[kk][0], qah[kk][1], qah[kk][2], qah[kk][3], bl0, bl1);
                    MMA_BF16(sa[ct][0], sa[ct][1], sa[ct][2], sa[ct][3],
                             qal[kk][0], qal[kk][1], qal[kk][2], qal[kk][3], bh0, bh1);
                }
            }

            float cm0 = -1e30f, cm1 = -1e30f;
            #pragma unroll
            for (int ct = 0; ct < 4; ++ct) {
                int c0 = ch * 32 + ct * 8 + 2 * tq;
                bool v0 = c0 < l, v1 = (c0 + 1) < l;
                sa[ct][0] = v0 ? sa[ct][0] * scale : -1e30f;
                sa[ct][1] = v1 ? sa[ct][1] * scale : -1e30f;
                sa[ct][2] = v0 ? sa[ct][2] * scale : -1e30f;
                sa[ct][3] = v1 ? sa[ct][3] * scale : -1e30f;
                cm0 = fmaxf(cm0, fmaxf(sa[ct][0], sa[ct][1]));
                cm1 = fmaxf(cm1, fmaxf(sa[ct][2], sa[ct][3]));
            }
            cm0 = fmaxf(cm0, __shfl_xor_sync(0xffffffffu, cm0, 1));
            cm0 = fmaxf(cm0, __shfl_xor_sync(0xffffffffu, cm0, 2));
            cm1 = fmaxf(cm1, __shfl_xor_sync(0xffffffffu, cm1, 1));
            cm1 = fmaxf(cm1, __shfl_xor_sync(0xffffffffu, cm1, 2));

            float nm0 = fmaxf(m0, cm0);
            float nm1 = fmaxf(m1, cm1);
            float al0 = __expf(m0 - nm0);
            float al1 = __expf(m1 - nm1);
            m0 = nm0; m1 = nm1;
            sum0 *= al0; sum1 *= al1;
            #pragma unroll
            for (int nt = 0; nt < 4; ++nt) {
                ca[nt][0] *= al0; ca[nt][1] *= al0;
                ca[nt][2] *= al1; ca[nt][3] *= al1;
            }

            #pragma unroll
            for (int ct = 0; ct < 4; ++ct) {
                int c0 = ch * 32 + ct * 8 + 2 * tq;
                float e0 = (c0 < l)     ? __expf(sa[ct][0] - m0) : 0.f;
                float e1 = (c0 + 1 < l) ? __expf(sa[ct][1] - m0) : 0.f;
                float e2 = (c0 < l)     ? __expf(sa[ct][2] - m1) : 0.f;
                float e3 = (c0 + 1 < l) ? __expf(sa[ct][3] - m1) : 0.f;
                sa[ct][0] = e0; sa[ct][1] = e1; sa[ct][2] = e2; sa[ct][3] = e3;
                sum0 += e0 + e1; sum1 += e2 + e3;
            }

            #pragma unroll
            for (int kk2 = 0; kk2 < 2; ++kk2) {
                unsigned pah[4], pal[4];
                bsplit2(sa[2*kk2][0],   sa[2*kk2][1],   pah[0], pal[0]);
                bsplit2(sa[2*kk2][2],   sa[2*kk2][3],   pah[1], pal[1]);
                bsplit2(sa[2*kk2+1][0], sa[2*kk2+1][1], pah[2], pal[2]);
                bsplit2(sa[2*kk2+1][2], sa[2*kk2+1][3], pah[3], pal[3]);
                #pragma unroll
                for (int nt = 0; nt < 4; ++nt) {
                    int base = (nt * 8 + g) * VS + (ch * 2 + kk2) * 8 + tq;
                    unsigned bh0 = Vh[base], bh1 = Vh[base + 4];
                    unsigned bl0 = Vl[base], bl1 = Vl[base + 4];
                    MMA_BF16(ca[nt][0], ca[nt][1], ca[nt][2], ca[nt][3],
                             pah[0], pah[1], pah[2], pah[3], bh0, bh1);
                    MMA_BF16(ca[nt][0], ca[nt][1], ca[nt][2], ca[nt][3],
                             pah[0], pah[1], pah[2], pah[3], bl0, bl1);
                    MMA_BF16(ca[nt][0], ca[nt][1], ca[nt][2], ca[nt][3],
                             pal[0], pal[1], pal[2], pal[3], bh0, bh1);
                }
            }
        }

        sum0 += __shfl_xor_sync(0xffffffffu, sum0, 1);
        sum0 += __shfl_xor_sync(0xffffffffu, sum0, 2);
        sum1 += __shfl_xor_sync(0xffffffffu, sum1, 1);
        sum1 += __shfl_xor_sync(0xffffffffu, sum1, 2);

        float inv0 = 1.f / sum0;
        float inv1 = 1.f / sum1;
        int r0 = i0 + g, r1 = i0 + 8 + g;
        #pragma unroll
        for (int nt = 0; nt < 4; ++nt) {
            int dcol = nt * 8 + 2 * tq;
            if (r0 < l)
                *(float2*)(ctx + (size_t)(n0 + r0) * 128 + hc + dcol) =
                    make_float2(ca[nt][0] * inv0, ca[nt][1] * inv0);
            if (r1 < l)
                *(float2*)(ctx + (size_t)(n0 + r1) * 128 + hc + dcol) =
                    make_float2(ca[nt][2] * inv1, ca[nt][3] * inv1);
        }
    }
}

// ---------------------------------------------------------------------------
extern "C" void kernel_launch(void* const* d_in, const int* in_sizes, int n_in,
                              void* d_out, int out_size)
{
    const float* POI    = (const float*)d_in[0];
    const float* dde    = (const float*)d_in[1];
    const float* attW   = (const float*)d_in[2];
    const float* a_src  = (const float*)d_in[3];
    const float* a_dst  = (const float*)d_in[4];
    const float* in_w   = (const float*)d_in[5];
    const float* in_b   = (const float*)d_in[6];
    const float* out_w  = (const float*)d_in[7];
    const float* out_b  = (const float*)d_in[8];
    const float* ln1g   = (const float*)d_in[9];
    const float* ln1b   = (const float*)d_in[10];
    const float* ln2g   = (const float*)d_in[11];
    const float* ln2b   = (const float*)d_in[12];
    const float* fw1    = (const float*)d_in[13];
    const float* fb1    = (const float*)d_in[14];
    const float* fw2    = (const float*)d_in[15];
    const float* fb2    = (const float*)d_in[16];
    const int* sess_idx  = (const int*)d_in[17];
    const int* edge_dist = (const int*)d_in[18];
    const int* batch_ids = (const int*)d_in[20];
    const int* node_pos  = (const int*)d_in[21];
    const int* lengths   = (const int*)d_in[22];
    int N = in_sizes[17];
    int B = in_sizes[22];
    float* outp = (float*)d_out;

    float *b0, *b1, *b2, *b3, *b4;
    unsigned *wh, *wl;
    cudaGetSymbolAddress((void**)&b0, g_buf0);
    cudaGetSymbolAddress((void**)&b1, g_buf1);
    cudaGetSymbolAddress((void**)&b2, g_buf2);
    cudaGetSymbolAddress((void**)&b3, g_buf3);
    cudaGetSymbolAddress((void**)&b4, g_buf4);
    cudaGetSymbolAddress((void**)&wh, d_wh);
    cudaGetSymbolAddress((void**)&wl, d_wl);

    const int qkv_smem  = 6 * WPC * (int)sizeof(unsigned);                       // ~208.9 KB
    const int tail_smem = 4 * WPC * (int)sizeof(unsigned)
                        + 128 * 132 * (int)sizeof(float);                        // ~206.8 KB
    const int attn_smem = (2 * 160 * QS + 2 * 32 * VS) * (int)sizeof(unsigned);  // ~47.1 KB
    cudaFuncSetAttribute(qkv_kernel,      cudaFuncAttributeMaxDynamicSharedMemorySize, qkv_smem);
    cudaFuncSetAttribute(tail_kernel,     cudaFuncAttributeMaxDynamicSharedMemorySize, tail_smem);
    cudaFuncSetAttribute(attn_mma_kernel, cudaFuncAttributeMaxDynamicSharedMemorySize, attn_smem);

    head_kernel<<<16, 1024>>>(lengths, B, attW, a_src, a_dst,
                              in_w, out_w, fw1, fw2, outp, out_size);

    gcn_kernel<<<(N + 7) / 8, 256>>>(POI, dde, sess_idx, edge_dist,
                                     batch_ids, node_pos, lengths, N);

    int gblocks = (N + 127) / 128;
    qkv_kernel<<<gblocks, 512, qkv_smem>>>(b0, wh, wl, in_b, ln1g, ln1b,
                                           b2, b3, b4, b1, N);

    dim3 ag(B, 4);
    attn_mma_kernel<<<ag, 256, attn_smem>>>(b2, b3, b4, b0, lengths);

    tail_kernel<<<gblocks, 512, tail_smem>>>(b0, b1, wh + 3 * WPC, wl + 3 * WPC,
                                             out_b, fb1, fb2, ln2g, ln2b,
                                             batch_ids, lengths, outp, N);
}

// round 14
// speedup vs baseline: 3.6221x; 1.0167x over previous
#include <cuda_runtime.h>
#include <cuda_bf16.h>
#include <math.h>

// ---------------------------------------------------------------------------
// SeqGraphRepNetwork on GB300 — packed formulation.
// R14: qkv/tail -> 1024 threads (32 warps, 64x8 warp tiles, NJ=1) for 50%
//      occupancy at unchanged smem; attention full-chunk (mask-free) path.
// ---------------------------------------------------------------------------

#define NMAX   163840
#define LMAX   160
#define BMAXS  1024
#define PA     68            // gemm smem row stride (words)
#define WPC    (128 * PA)    // words per weight plane
#define QS     20            // attn K smem row stride (words)
#define VS     84            // attn V^T smem row stride (words)

__device__ float d_vsrc[128];
__device__ float d_vdst[128];
__device__ int   d_starts[BMAXS + 1];
__device__ int   d_order[BMAXS];             // sessions sorted by length desc
__device__ unsigned d_wh[6 * WPC];           // weight hi-plane, gemm layout
__device__ unsigned d_wl[6 * WPC];           // weight lo-plane
__device__ float g_buf0[(size_t)NMAX * 128]; // Hu, later ctx
__device__ float g_buf1[(size_t)NMAX * 128]; // Qin (LN1 output)
__device__ float g_buf2[(size_t)NMAX * 128]; // q proj
__device__ float g_buf3[(size_t)NMAX * 128]; // k proj
__device__ float g_buf4[(size_t)NMAX * 128]; // v proj

// ---------------------------------------------------------------------------
__device__ __forceinline__ void bsplit2(float a0, float a1,
                                        unsigned &hi, unsigned &lo)
{
    __nv_bfloat162 h = __float22bfloat162_rn(make_float2(a0, a1));
    float r0 = a0 - __low2float(h);
    float r1 = a1 - __high2float(h);
    __nv_bfloat162 l = __float22bfloat162_rn(make_float2(r0, r1));
    hi = *(unsigned*)&h;
    lo = *(unsigned*)&l;
}

#define MMA_BF16(d0,d1,d2,d3, a0,a1,a2,a3, b0,b1)                         \
    asm volatile("mma.sync.aligned.m16n8k16.row.col.f32.bf16.bf16.f32 "   \
                 "{%0,%1,%2,%3}, {%4,%5,%6,%7}, {%8,%9}, {%0,%1,%2,%3};"  \
                 : "+f"(d0), "+f"(d1), "+f"(d2), "+f"(d3)                 \
                 : "r"(a0), "r"(a1), "r"(a2), "r"(a3), "r"(b0), "r"(b1))

// 128-row x (NJ*8)-col warp tile block mma over K=128, 3-term split-bf16.
template<int NJ>
__device__ __forceinline__ void mma_block_t(
    const unsigned* __restrict__ Ah, const unsigned* __restrict__ Al,
    const unsigned* __restrict__ Bh, const unsigned* __restrict__ Bl,
    float d[4][NJ][4], int warpRow, int warpCol, int g, int tq)
{
    #pragma unroll
    for (int i = 0; i < 4; ++i)
        #pragma unroll
        for (int j = 0; j < NJ; ++j)
            d[i][j][0] = d[i][j][1] = d[i][j][2] = d[i][j][3] = 0.f;

    #pragma unroll
    for (int kk = 0; kk < 8; ++kk) {
        unsigned ah[4][4], al[4][4], bh[NJ][2], bl[NJ][2];
        #pragma unroll
        for (int i = 0; i < 4; ++i) {
            int base = (warpRow + i * 16 + g) * PA + kk * 8 + tq;
            ah[i][0] = Ah[base];            ah[i][1] = Ah[base + 8 * PA];
            ah[i][2] = Ah[base + 4];        ah[i][3] = Ah[base + 8 * PA + 4];
            al[i][0] = Al[base];            al[i][1] = Al[base + 8 * PA];
            al[i][2] = Al[base + 4];        al[i][3] = Al[base + 8 * PA + 4];
        }
        #pragma unroll
        for (int j = 0; j < NJ; ++j) {
            int base = (warpCol + j * 8 + g) * PA + kk * 8 + tq;
            bh[j][0] = Bh[base];  bh[j][1] = Bh[base + 4];
            bl[j][0] = Bl[base];  bl[j][1] = Bl[base + 4];
        }
        #pragma unroll
        for (int i = 0; i < 4; ++i)
            #pragma unroll
            for (int j = 0; j < NJ; ++j) {
                MMA_BF16(d[i][j][0], d[i][j][1], d[i][j][2], d[i][j][3],
                         ah[i][0], ah[i][1], ah[i][2], ah[i][3],
                         bh[j][0], bh[j][1]);
                MMA_BF16(d[i][j][0], d[i][j][1], d[i][j][2], d[i][j][3],
                         ah[i][0], ah[i][1], ah[i][2], ah[i][3],
                         bl[j][0], bl[j][1]);
                MMA_BF16(d[i][j][0], d[i][j][1], d[i][j][2], d[i][j][3],
                         al[i][0], al[i][1], al[i][2], al[i][3],
                         bh[j][0], bh[j][1]);
            }
    }
}

// ---------------------------------------------------------------------------
// Head: block 0 = scan + length-desc counting sort; block 1 = prep vectors;
// blocks 2-7 = weight split; blocks 8-15 = zero the pool output.
// ---------------------------------------------------------------------------
__global__ void head_kernel(const int* __restrict__ lengths, int B,
                            const float* __restrict__ attW,
                            const float* __restrict__ a_src,
                            const float* __restrict__ a_dst,
                            const float* __restrict__ in_w,
                            const float* __restrict__ out_w,
                            const float* __restrict__ fw1,
                            const float* __restrict__ fw2,
                            float* __restrict__ outp, int out_n)
{
    __shared__ int s[BMAXS];
    __shared__ int hist[192];
    int blk = blockIdx.x;
    int t = threadIdx.x;
    if (blk == 0) {
        int v = (t < B) ? lengths[t] : 0;
        s[t] = v;
        __syncthreads();
        for (int o = 1; o < BMAXS; o <<= 1) {
            int add = (t >= o) ? s[t - o] : 0;
            __syncthreads();
            s[t] += add;
            __syncthreads();
        }
        if (t < B) d_starts[t] = s[t] - v;
        if (t == B - 1) d_starts[B] = s[t];
        if (t < 192) hist[t] = 0;
        __syncthreads();
        int li = 0;
        if (t < B) {
            li = lengths[t];
            if (li > 191) li = 191;
            if (li < 0) li = 0;
            atomicAdd(&hist[li], 1);
        }
        __syncthreads();
        if (t == 0) {
            int acc = 0;
            for (int L = 191; L >= 0; --L) { int c = hist[L]; hist[L] = acc; acc += c; }
        }
        __syncthreads();
        if (t < B) {
            int pos = atomicAdd(&hist[li], 1);
            d_order[pos] = t;
        }
    } else if (blk == 1) {
        if (t < 128) {
            float vs = 0.f, vd = 0.f;
            #pragma unroll 4
            for (int k = 0; k < 128; ++k) {
                float w = attW[k * 128 + t];
                vs += a_src[k] * w;
                vd += a_dst[k] * w;
            }
            d_vsrc[t] = vs;
            d_vdst[t] = vd;
        }
    } else if (blk < 8) {
        int m = blk - 2;
        const float* src = (m < 3) ? (in_w + m * 16384)
                         : (m == 3 ? out_w : (m == 4 ? fw1 : fw2));
        unsigned* wh = d_wh + m * WPC;
        unsigned* wl = d_wl + m * WPC;
        for (int i = t; i < 4096; i += 1024) {
            int r = i >> 5, q = i & 31;
            float4 w = ((const float4*)src)[i];
            unsigned h0, l0, h1, l1;
            bsplit2(w.x, w.y, h0, l0);
            bsplit2(w.z, w.w, h1, l1);
            wh[r * PA + 2 * q]     = h0;  wh[r * PA + 2 * q + 1] = h1;
            wl[r * PA + 2 * q]     = l0;  wl[r * PA + 2 * q + 1] = l1;
        }
    } else {
        for (int i = (blk - 8) * 1024 + t; i < out_n; i += 8 * 1024)
            outp[i] = 0.f;
    }
}

// ---------------------------------------------------------------------------
// GCN: warp per node; node-local edge logits; 2-way softmax aggregate.
// ---------------------------------------------------------------------------
__global__ void gcn_kernel(const float* __restrict__ POI,
                           const float* __restrict__ dde,
                           const int*   __restrict__ sess_idx,
                           const int*   __restrict__ edge_dist,
                           const int*   __restrict__ batch_ids,
                           const int*   __restrict__ node_pos,
                           const int*   __restrict__ lengths, int N)
{
    int n = blockIdx.x * 8 + (threadIdx.x >> 5);
    if (n >= N) return;
    int lane = threadIdx.x & 31;
    int b = batch_ids[n];
    int p = node_pos[n];
    int l = lengths[b];
    bool h1 = (p > 0);
    bool h2 = (p < l - 1);

    float4 va = ((const float4*)d_vsrc)[lane];
    float4 vb = ((const float4*)d_vdst)[lane];
    float4 xo = ((const float4*)(POI + (size_t)sess_idx[n] * 128))[lane];
    float p1 = xo.x*va.x + xo.y*va.y + xo.z*va.z + xo.w*va.w;
    float p2 = xo.x*vb.x + xo.y*vb.y + xo.z*vb.z + xo.w*vb.w;
    float qq = 0.f;
    if (h1) {
        float4 xe = ((const float4*)(dde + (size_t)edge_dist[n - 1 - b] * 128))[lane];
        qq = xe.x*va.x + xe.y*va.y + xe.z*va.z + xe.w*va.w;
    }
    #pragma unroll
    for (int o = 16; o; o >>= 1) {
        p1 += __shfl_xor_sync(0xffffffffu, p1, o);
        p2 += __shfl_xor_sync(0xffffffffu, p2, o);
        qq += __shfl_xor_sync(0xffffffffu, qq, o);
    }

    float L1 = h1 ? (p1 + qq) : -1e30f;
    float L2 = h2 ? p2 : -1e30f;
    float m  = fmaxf(L1, L2);
    float e1 = h1 ? expf(L1 - m) : 0.f;
    float e2 = h2 ? expf(L2 - m) : 0.f;
    float inv = 1.f / (e1 + e2 + 1e-16f);
    float a1 = e1 * inv, a2 = e2 * inv;

    float4 hu = make_float4(0.f, 0.f, 0.f, 0.f);
    if (h1) {
        float4 x = ((const float4*)(POI + (size_t)sess_idx[n - 1] * 128))[lane];
        hu.x += a1 * x.x; hu.y += a1 * x.y; hu.z += a1 * x.z; hu.w += a1 * x.w;
    }
    if (h2) {
        float4 x = ((const float4*)(POI + (size_t)sess_idx[n + 1] * 128))[lane];
        hu.x += a2 * x.x; hu.y += a2 * x.y; hu.z += a2 * x.z; hu.w += a2 * x.w;
    }
    ((float4*)g_buf0)[(size_t)n * 32 + lane] = hu;
}

// ---------------------------------------------------------------------------
// Fused LN1 + QKV projections. One block = 128 rows, 1024 threads (32 warps,
// warp tile 64x8).
// ---------------------------------------------------------------------------
__global__ void __launch_bounds__(1024, 1)
qkv_kernel(const float* __restrict__ Hu,
           const unsigned* __restrict__ Wh3, const unsigned* __restrict__ Wl3,
           const float* __restrict__ in_b,
           const float* __restrict__ g1, const float* __restrict__ b1v,
           float* __restrict__ qout, float* __restrict__ kout,
           float* __restrict__ vout, float* __restrict__ qinout, int nrows)
{
    extern __shared__ unsigned smu[];
    unsigned* AhH = smu;
    unsigned* AlH = AhH + WPC;
    unsigned* AhQ = AlH + WPC;
    unsigned* AlQ = AhQ + WPC;
    unsigned* Bh  = AlQ + WPC;
    unsigned* Bl  = Bh + WPC;
    float* stage  = (float*)Bh;          // fp32 Hu staging [128][132]
    int tid  = threadIdx.x;
    int row0 = blockIdx.x * 128;
    int lane = tid & 31, wid = tid >> 5;
    int g  = lane >> 2, tq = lane & 3;
    int warpRow = (wid & 1) * 64;
    int warpCol = (wid >> 1) * 8;

    for (int i = tid; i < 4096; i += 1024) {
        int r = i >> 5, q = i & 31;
        int gr = row0 + r;
        float4 a = (gr < nrows) ? ((const float4*)Hu)[(size_t)gr * 32 + q]
                                : make_float4(0.f, 0.f, 0.f, 0.f);
        unsigned h0, l0, h1, l1;
        bsplit2(a.x, a.y, h0, l0);
        bsplit2(a.z, a.w, h1, l1);
        AhH[r * PA + 2 * q]     = h0;  AhH[r * PA + 2 * q + 1] = h1;
        AlH[r * PA + 2 * q]     = l0;  AlH[r * PA + 2 * q + 1] = l1;
        *(float4*)&stage[r * 132 + q * 4] = a;
    }
    __syncthreads();

    {
        float4 gg = ((const float4*)g1)[lane];
        float4 bb = ((const float4*)b1v)[lane];
        for (int r = wid; r < 128; r += 32) {
            float4 v = *(float4*)&stage[r * 132 + lane * 4];
            float s1 = v.x + v.y + v.z + v.w;
            float s2 = v.x*v.x + v.y*v.y + v.z*v.z + v.w*v.w;
            #pragma unroll
            for (int o = 16; o; o >>= 1) {
                s1 += __shfl_xor_sync(0xffffffffu, s1, o);
                s2 += __shfl_xor_sync(0xffffffffu, s2, o);
            }
            float mu   = s1 * (1.f / 128.f);
            float var  = fmaxf(s2 * (1.f / 128.f) - mu * mu, 0.f);
            float rstd = rsqrtf(var + 1e-8f);
            float4 o4;
            o4.x = (v.x - mu) * rstd * gg.x + bb.x;
            o4.y = (v.y - mu) * rstd * gg.y + bb.y;
            o4.z = (v.z - mu) * rstd * gg.z + bb.z;
            o4.w = (v.w - mu) * rstd * gg.w + bb.w;
            int gr = row0 + r;
            if (gr < nrows)
                ((float4*)(qinout + (size_t)gr * 128))[lane] = o4;
            unsigned h0, l0, h1, l1;
            bsplit2(o4.x, o4.y, h0, l0);
            bsplit2(o4.z, o4.w, h1, l1);
            AhQ[r * PA + lane * 2]     = h0;  AhQ[r * PA + lane * 2 + 1] = h1;
            AlQ[r * PA + lane * 2]     = l0;  AlQ[r * PA + lane * 2 + 1] = l1;
        }
    }

    float d[4][1][4];
    for (int s = 0; s < 3; ++s) {
        __syncthreads();
        const uint4* wh4 = (const uint4*)(Wh3 + s * WPC);
        const uint4* wl4 = (const uint4*)(Wl3 + s * WPC);
        for (int i = tid; i < 2176; i += 1024) {
            ((uint4*)Bh)[i] = wh4[i];
            ((uint4*)Bl)[i] = wl4[i];
        }
        __syncthreads();
        const unsigned* Ah = (s == 0) ? AhQ : AhH;
        const unsigned* Al = (s == 0) ? AlQ : AlH;
        mma_block_t<1>(Ah, Al, Bh, Bl, d, warpRow, warpCol, g, tq);

        float* op = (s == 0) ? qout : ((s == 1) ? kout : vout);
        const float* bias = in_b + s * 128;
        {
            int c0 = warpCol + tq * 2;
            float bj0 = bias[c0], bj1 = bias[c0 + 1];
            #pragma unroll
            for (int i = 0; i < 4; ++i) {
                int r0 = warpRow + i * 16 + g;
                int gr = row0 + r0;
                if (gr < nrows)
                    *(float2*)(op + (size_t)gr * 128 + c0) =
                        make_float2(d[i][0][0] + bj0, d[i][0][1] + bj1);
                if (gr + 8 < nrows)
                    *(float2*)(op + (size_t)(gr + 8) * 128 + c0) =
                        make_float2(d[i][0][2] + bj0, d[i][0][3] + bj1);
            }
        }
    }
}

// ---------------------------------------------------------------------------
// Fused tail: out2 = LN2(ctx@Wo^T + bo + Qin); h = relu(out2@W1^T + b1);
// out3 = h@W2^T + b2 + out2; S_u += out3 / l.  1024 threads, 32 warps.
// ---------------------------------------------------------------------------
__global__ void __launch_bounds__(1024, 1)
tail_kernel(const float* __restrict__ ctx, const float* __restrict__ Qin,
            const unsigned* __restrict__ Wh3, const unsigned* __restrict__ Wl3,
            const float* __restrict__ out_b, const float* __restrict__ fb1,
            const float* __restrict__ fb2,
            const float* __restrict__ lng, const float* __restrict__ lnb,
            const int* __restrict__ batch_ids, const int* __restrict__ lengths,
            float* __restrict__ pool_out, int nrows)
{
    extern __shared__ unsigned smu[];
    unsigned* Ah = smu;                       // [128][PA]
    unsigned* Al = Ah + WPC;
    unsigned* Bh = Al + WPC;
    unsigned* Bl = Bh + WPC;
    float*    O  = (float*)(Bl + WPC);        // [128][132] fp32 out2
    int tid  = threadIdx.x;
    int row0 = blockIdx.x * 128;
    int lane = tid & 31, wid = tid >> 5;
    int g  = lane >> 2, tq = lane & 3;
    int warpRow = (wid & 1) * 64;
    int warpCol = (wid >> 1) * 8;

    for (int i = tid; i < 4096; i += 1024) {
        int r = i >> 5, q = i & 31;
        int gr = row0 + r;
        float4 a = (gr < nrows) ? ((const float4*)ctx)[(size_t)gr * 32 + q]
                                : make_float4(0.f, 0.f, 0.f, 0.f);
        unsigned h0, l0, h1, l1;
        bsplit2(a.x, a.y, h0, l0);
        bsplit2(a.z, a.w, h1, l1);
        Ah[r * PA + 2 * q]     = h0;  Ah[r * PA + 2 * q + 1] = h1;
        Al[r * PA + 2 * q]     = l0;  Al[r * PA + 2 * q + 1] = l1;
    }
    for (int i = tid; i < 2176; i += 1024) {
        ((uint4*)Bh)[i] = ((const uint4*)Wh3)[i];
        ((uint4*)Bl)[i] = ((const uint4*)Wl3)[i];
    }
    __syncthreads();

    float d[4][1][4];
    mma_block_t<1>(Ah, Al, Bh, Bl, d, warpRow, warpCol, g, tq);
    __syncthreads();

    #pragma unroll
    for (int i = 0; i < 4; ++i) {
        int r0 = warpRow + i * 16 + g;
        int c0 = warpCol + tq * 2;
        *(float2*)&O[r0 * 132 + c0]       = make_float2(d[i][0][0], d[i][0][1]);
        *(float2*)&O[(r0 + 8) * 132 + c0] = make_float2(d[i][0][2], d[i][0][3]);
    }
    __syncthreads();

    {
        float4 bo = ((const float4*)out_b)[lane];
        float4 gg = ((const float4*)lng)[lane];
        float4 be = ((const float4*)lnb)[lane];
        for (int r = wid; r < 128; r += 32) {
            int gr = row0 + r;
            float4 v = *(float4*)&O[r * 132 + lane * 4];
            float4 qv = (gr < nrows) ? ((const float4*)(Qin + (size_t)gr * 128))[lane]
                                     : make_float4(0.f, 0.f, 0.f, 0.f);
            v.x += bo.x + qv.x; v.y += bo.y + qv.y;
            v.z += bo.z + qv.z; v.w += bo.w + qv.w;
            float s1 = v.x + v.y + v.z + v.w;
            float s2 = v.x*v.x + v.y*v.y + v.z*v.z + v.w*v.w;
            #pragma unroll
            for (int o = 16; o; o >>= 1) {
                s1 += __shfl_xor_sync(0xffffffffu, s1, o);
                s2 += __shfl_xor_sync(0xffffffffu, s2, o);
            }
            float mu   = s1 * (1.f / 128.f);
            float var  = fmaxf(s2 * (1.f / 128.f) - mu * mu, 0.f);
            float rstd = rsqrtf(var + 1e-8f);
            v.x = (v.x - mu) * rstd * gg.x + be.x;
            v.y = (v.y - mu) * rstd * gg.y + be.y;
            v.z = (v.z - mu) * rstd * gg.z + be.z;
            v.w = (v.w - mu) * rstd * gg.w + be.w;
            *(float4*)&O[r * 132 + lane * 4] = v;
            unsigned h0, l0, h1, l1;
            bsplit2(v.x, v.y, h0, l0);
            bsplit2(v.z, v.w, h1, l1);
            Ah[r * PA + lane * 2]     = h0;  Ah[r * PA + lane * 2 + 1] = h1;
            Al[r * PA + lane * 2]     = l0;  Al[r * PA + lane * 2 + 1] = l1;
        }
    }
    __syncthreads();

    for (int i = tid; i < 2176; i += 1024) {
        ((uint4*)Bh)[i] = ((const uint4*)(Wh3 + WPC))[i];
        ((uint4*)Bl)[i] = ((const uint4*)(Wl3 + WPC))[i];
    }
    __syncthreads();
    mma_block_t<1>(Ah, Al, Bh, Bl, d, warpRow, warpCol, g, tq);
    __syncthreads();

    #pragma unroll
    for (int i = 0; i < 4; ++i) {
        int c0 = warpCol + tq * 2;
        float bx = fb1[c0], by = fb1[c0 + 1];
        int r0 = warpRow + i * 16 + g;
        float v0 = fmaxf(d[i][0][0] + bx, 0.f);
        float v1 = fmaxf(d[i][0][1] + by, 0.f);
        float v2 = fmaxf(d[i][0][2] + bx, 0.f);
        float v3 = fmaxf(d[i][0][3] + by, 0.f);
        unsigned h0, l0, h1, l1;
        bsplit2(v0, v1, h0, l0);
        bsplit2(v2, v3, h1, l1);
        int w0 = r0 * PA + (c0 >> 1);
        int w1 = (r0 + 8) * PA + (c0 >> 1);
        Ah[w0] = h0;  Al[w0] = l0;
        Ah[w1] = h1;  Al[w1] = l1;
    }
    __syncthreads();

    for (int i = tid; i < 2176; i += 1024) {
        ((uint4*)Bh)[i] = ((const uint4*)(Wh3 + 2 * WPC))[i];
        ((uint4*)Bl)[i] = ((const uint4*)(Wl3 + 2 * WPC))[i];
    }
    __syncthreads();
    mma_block_t<1>(Ah, Al, Bh, Bl, d, warpRow, warpCol, g, tq);

    #pragma unroll
    for (int i = 0; i < 4; ++i) {
        #pragma unroll
        for (int half = 0; half < 2; ++half) {
            int r0 = warpRow + i * 16 + g + half * 8;
            int gr = row0 + r0;
            if (gr >= nrows) continue;
            int bsess = batch_ids[gr];
            float invl = 1.f / (float)lengths[bsess];
            float* outrow = pool_out + (size_t)bsess * 128;
            int c0 = warpCol + tq * 2;
            float v0 = d[i][0][2 * half]     + fb2[c0]     + O[r0 * 132 + c0];
            float v1 = d[i][0][2 * half + 1] + fb2[c0 + 1] + O[r0 * 132 + c0 + 1];
            atomicAdd(outrow + c0,     v0 * invl);
            atomicAdd(outrow + c0 + 1, v1 * invl);
        }
    }
}

// ---------------------------------------------------------------------------
// Tensor-core attention per (session, head), online-softmax chunked.
// Q fragments direct from gmem; full-chunk (mask-free) fast path.
// ---------------------------------------------------------------------------
__global__ void __launch_bounds__(256, 3)
attn_mma_kernel(const float* __restrict__ qp, const float* __restrict__ kp,
                const float* __restrict__ vp, float* __restrict__ ctx,
                const int* __restrict__ lengths)
{
    int b = d_order[blockIdx.x];
    int h = blockIdx.y;
    int n0 = d_starts[b];
    int l  = lengths[b];
    extern __shared__ unsigned sm[];
    unsigned* Kh = sm;                   // [160][QS]
    unsigned* Kl = Kh + 160 * QS;
    unsigned* Vh = Kl + 160 * QS;        // [32][VS]
    unsigned* Vl = Vh + 32 * VS;
    int tid = threadIdx.x;
    int hc  = h * 32;

    for (int i = tid; i < l * 16; i += 256) {
        int s = i >> 4, cp = i & 15;
        size_t gi = (((size_t)(n0 + s) * 128 + hc) >> 1) + cp;
        float2 kv = ((const float2*)kp)[gi];
        unsigned hi, lo;
        bsplit2(kv.x, kv.y, hi, lo);
        Kh[s * QS + cp] = hi; Kl[s * QS + cp] = lo;
    }
    int njp = (l + 1) >> 1;
    for (int i = tid; i < njp * 32; i += 256) {
        int jp = i >> 5, d = i & 31;
        int j0 = 2 * jp;
        float v0 = vp[(size_t)(n0 + j0) * 128 + hc + d];
        float v1 = (j0 + 1 < l) ? vp[(size_t)(n0 + j0 + 1) * 128 + hc + d] : 0.f;
        unsigned hi, lo;
        bsplit2(v0, v1, hi, lo);
        Vh[d * VS + jp] = hi; Vl[d * VS + jp] = lo;
    }
    int nchunks = (l + 31) >> 5;
    int jmax = nchunks * 16;
    for (int i = tid; i < (jmax - njp) * 32; i += 256) {
        int d = i & 31, jp = njp + (i >> 5);
        Vh[d * VS + jp] = 0u;
        Vl[d * VS + jp] = 0u;
    }
    __syncthreads();

    int lane = tid & 31, wid = tid >> 5;
    int g = lane >> 2, tq = lane & 3;
    int nrt = (l + 15) >> 4;
    const float scale = 0.17677669529663687f;   // 1/sqrt(32)

    for (int rt = wid; rt < nrt; rt += 8) {
        int i0 = rt * 16;
        unsigned qah[2][4], qal[2][4];
        {
            const float2* qr0 = (const float2*)(qp + (size_t)(n0 + i0 + g) * 128 + hc);
            const float2* qr1 = (const float2*)(qp + (size_t)(n0 + i0 + 8 + g) * 128 + hc);
            #pragma unroll
            for (int kk = 0; kk < 2; ++kk) {
                float2 v;
                v = qr0[kk * 8 + tq];     bsplit2(v.x, v.y, qah[kk][0], qal[kk][0]);
                v = qr1[kk * 8 + tq];     bsplit2(v.x, v.y, qah[kk][1], qal[kk][1]);
                v = qr0[kk * 8 + tq + 4]; bsplit2(v.x, v.y, qah[kk][2], qal[kk][2]);
                v = qr1[kk * 8 + tq + 4]; bsplit2(v.x, v.y, qah[kk][3], qal[kk][3]);
            }
        }

        float ca[4][4];
        #pragma unroll
        for (int nt = 0; nt < 4; ++nt)
            ca[nt][0] = ca[nt][1] = ca[nt][2] = ca[nt][3] = 0.f;
        float m0 = -1e30f, m1 = -1e30f;
        float sum0 = 0.f, sum1 = 0.f;

        for (int ch = 0; ch < nchunks; ++ch) {
            float sa[4][4];
            #pragma unroll
            for (int ct = 0; ct < 4; ++ct)
                sa[ct][0] = sa[ct][1] = sa[ct][2] = sa[ct][3] = 0.f;

            #pragma unroll
            for (int ct = 0; ct < 4; ++ct) {
                #pragma unroll
                for (int kk = 0; kk < 2; ++kk) {
                    int base = ((ch * 4 + ct) * 8 + g) * QS + kk * 8 + tq;
                    unsigned bh0 = Kh[base], bh1 = Kh[base + 4];
                    unsigned bl0 = Kl[base], bl1 = Kl[base + 4];
                    MMA_BF16(sa[ct][0], sa[ct][1], sa[ct][2], sa[ct][3],
                             qah[kk][0], qah[kk][1], qah[kk][2], qah[kk][3], bh0, bh1);
                    MMA_BF16(sa[ct][0], sa[ct][1], sa[ct][2], sa[ct][3],
                             qah[kk][0], qah[kk][1], qah[kk][2], qah[kk][3], bl0, bl1);
                    MMA_BF16(sa[ct][0], sa[ct][1], sa[ct][2], sa[ct][3],
                             qal[kk][0], qal[kk][1], qal[kk][2], qal[kk][3], bh0, bh1);
                }
            }

            bool full = ((ch + 1) << 5) <= l;   // uniform across block
            float cm0 = -1e30f, cm1 = -1e30f;
            if (full) {
                #pragma unroll
                for (int ct = 0; ct < 4; ++ct) {
                    sa[ct][0] *= scale; sa[ct][1] *= scale;
                    sa[ct][2] *= scale; sa[ct][3] *= scale;
                    cm0 = fmaxf(cm0, fmaxf(sa[ct][0], sa[ct][1]));
                    cm1 = fmaxf(cm1, fmaxf(sa[ct][2], sa[ct][3]));
                }
            } else {
                #pragma unroll
                for (int ct = 0; ct < 4; ++ct) {
                    int c0 = ch * 32 + ct * 8 + 2 * tq;
                    bool v0 = c0 < l, v1 = (c0 + 1) < l;
                    sa[ct][0] = v0 ? sa[ct][0] * scale : -1e30f;
                    sa[ct][1] = v1 ? sa[ct][1] * scale : -1e30f;
                    sa[ct][2] = v0 ? sa[ct][2] * scale : -1e30f;
                    sa[ct][3] = v1 ? sa[ct][3] * scale : -1e30f;
                    cm0 = fmaxf(cm0, fmaxf(sa[ct][0], sa[ct][1]));
                    cm1 = fmaxf(cm1, fmaxf(sa[ct][2], sa[ct][3]));
                }
            }
            cm0 = fmaxf(cm0, __shfl_xor_sync(0xffffffffu, cm0, 1));
            cm0 = fmaxf(cm0, __shfl_xor_sync(0xffffffffu, cm0, 2));
            cm1 = fmaxf(cm1, __shfl_xor_sync(0xffffffffu, cm1, 1));
            cm1 = fmaxf(cm1, __shfl_xor_sync(0xffffffffu, cm1, 2));

            float nm0 = fmaxf(m0, cm0);
            float nm1 = fmaxf(m1, cm1);
            float al0 = __expf(m0 - nm0);
            float al1 = __expf(m1 - nm1);
            m0 = nm0; m1 = nm1;
            sum0 *= al0; sum1 *= al1;
            #pragma unroll
            for (int nt = 0; nt < 4; ++nt) {
                ca[nt][0] *= al0; ca[nt][1] *= al0;
                ca[nt][2] *= al1; ca[nt][3] *= al1;
            }

            if (full) {
                #pragma unroll
                for (int ct = 0; ct < 4; ++ct) {
                    float e0 = __expf(sa[ct][0] - m0);
                    float e1 = __expf(sa[ct][1] - m0);
                    float e2 = __expf(sa[ct][2] - m1);
                    float e3 = __expf(sa[ct][3] - m1);
                    sa[ct][0] = e0; sa[ct][1] = e1; sa[ct][2] = e2; sa[ct][3] = e3;
                    sum0 += e0 + e1; sum1 += e2 + e3;
                }
            } else {
                #pragma unroll
                for (int ct = 0; ct < 4; ++ct) {
                    int c0 = ch * 32 + ct * 8 + 2 * tq;
                    float e0 = (c0 < l)     ? __expf(sa[ct][0] - m0) : 0.f;
                    float e1 = (c0 + 1 < l) ? __expf(sa[ct][1] - m0) : 0.f;
                    float e2 = (c0 < l)     ? __expf(sa[ct][2] - m1) : 0.f;
                    float e3 = (c0 + 1 < l) ? __expf(sa[ct][3] - m1) : 0.f;
                    sa[ct][0] = e0; sa[ct][1] = e1; sa[ct][2] = e2; sa[ct][3] = e3;
                    sum0 += e0 + e1; sum1 += e2 + e3;
                }
            }

            #pragma unroll
            for (int kk2 = 0; kk2 < 2; ++kk2) {
                unsigned pah[4], pal[4];
                bsplit2(sa[2*kk2][0],   sa[2*kk2][1],   pah[0], pal[0]);
                bsplit2(sa[2*kk2][2],   sa[2*kk2][3],   pah[1], pal[1]);
                bsplit2(sa[2*kk2+1][0], sa[2*kk2+1][1], pah[2], pal[2]);
                bsplit2(sa[2*kk2+1][2], sa[2*kk2+1][3], pah[3], pal[3]);
                #pragma unroll
                for (int nt = 0; nt < 4; ++nt) {
                    int base = (nt * 8 + g) * VS + (ch * 2 + kk2) * 8 + tq;
                    unsigned bh0 = Vh[base], bh1 = Vh[base + 4];
                    unsigned bl0 = Vl[base], bl1 = Vl[base + 4];
                    MMA_BF16(ca[nt][0], ca[nt][1], ca[nt][2], ca[nt][3],
                             pah[0], pah[1], pah[2], pah[3], bh0, bh1);
                    MMA_BF16(ca[nt][0], ca[nt][1], ca[nt][2], ca[nt][3],
                             pah[0], pah[1], pah[2], pah[3], bl0, bl1);
                    MMA_BF16(ca[nt][0], ca[nt][1], ca[nt][2], ca[nt][3],
                             pal[0], pal[1], pal[2], pal[3], bh0, bh1);
                }
            }
        }

        sum0 += __shfl_xor_sync(0xffffffffu, sum0, 1);
        sum0 += __shfl_xor_sync(0xffffffffu, sum0, 2);
        sum1 += __shfl_xor_sync(0xffffffffu, sum1, 1);
        sum1 += __shfl_xor_sync(0xffffffffu, sum1, 2);

        float inv0 = 1.f / sum0;
        float inv1 = 1.f / sum1;
        int r0 = i0 + g, r1 = i0 + 8 + g;
        #pragma unroll
        for (int nt = 0; nt < 4; ++nt) {
            int dcol = nt * 8 + 2 * tq;
            if (r0 < l)
                *(float2*)(ctx + (size_t)(n0 + r0) * 128 + hc + dcol) =
                    make_float2(ca[nt][0] * inv0, ca[nt][1] * inv0);
            if (r1 < l)
                *(float2*)(ctx + (size_t)(n0 + r1) * 128 + hc + dcol) =
                    make_float2(ca[nt][2] * inv1, ca[nt][3] * inv1);
        }
    }
}

// ---------------------------------------------------------------------------
extern "C" void kernel_launch(void* const* d_in, const int* in_sizes, int n_in,
                              void* d_out, int out_size)
{
    const float* POI    = (const float*)d_in[0];
    const float* dde    = (const float*)d_in[1];
    const float* attW   = (const float*)d_in[2];
    const float* a_src  = (const float*)d_in[3];
    const float* a_dst  = (const float*)d_in[4];
    const float* in_w   = (const float*)d_in[5];
    const float* in_b   = (const float*)d_in[6];
    const float* out_w  = (const float*)d_in[7];
    const float* out_b  = (const float*)d_in[8];
    const float* ln1g   = (const float*)d_in[9];
    const float* ln1b   = (const float*)d_in[10];
    const float* ln2g   = (const float*)d_in[11];
    const float* ln2b   = (const float*)d_in[12];
    const float* fw1    = (const float*)d_in[13];
    const float* fb1    = (const float*)d_in[14];
    const float* fw2    = (const float*)d_in[15];
    const float* fb2    = (const float*)d_in[16];
    const int* sess_idx  = (const int*)d_in[17];
    const int* edge_dist = (const int*)d_in[18];
    const int* batch_ids = (const int*)d_in[20];
    const int* node_pos  = (const int*)d_in[21];
    const int* lengths   = (const int*)d_in[22];
    int N = in_sizes[17];
    int B = in_sizes[22];
    float* outp = (float*)d_out;

    float *b0, *b1, *b2, *b3, *b4;
    unsigned *wh, *wl;
    cudaGetSymbolAddress((void**)&b0, g_buf0);
    cudaGetSymbolAddress((void**)&b1, g_buf1);
    cudaGetSymbolAddress((void**)&b2, g_buf2);
    cudaGetSymbolAddress((void**)&b3, g_buf3);
    cudaGetSymbolAddress((void**)&b4, g_buf4);
    cudaGetSymbolAddress((void**)&wh, d_wh);
    cudaGetSymbolAddress((void**)&wl, d_wl);

    const int qkv_smem  = 6 * WPC * (int)sizeof(unsigned);                       // ~208.9 KB
    const int tail_smem = 4 * WPC * (int)sizeof(unsigned)
                        + 128 * 132 * (int)sizeof(float);                        // ~206.8 KB
    const int attn_smem = (2 * 160 * QS + 2 * 32 * VS) * (int)sizeof(unsigned);  // ~47.1 KB
    cudaFuncSetAttribute(qkv_kernel,      cudaFuncAttributeMaxDynamicSharedMemorySize, qkv_smem);
    cudaFuncSetAttribute(tail_kernel,     cudaFuncAttributeMaxDynamicSharedMemorySize, tail_smem);
    cudaFuncSetAttribute(attn_mma_kernel, cudaFuncAttributeMaxDynamicSharedMemorySize, attn_smem);

    head_kernel<<<16, 1024>>>(lengths, B, attW, a_src, a_dst,
                              in_w, out_w, fw1, fw2, outp, out_size);

    gcn_kernel<<<(N + 7) / 8, 256>>>(POI, dde, sess_idx, edge_dist,
                                     batch_ids, node_pos, lengths, N);

    int gblocks = (N + 127) / 128;
    qkv_kernel<<<gblocks, 1024, qkv_smem>>>(b0, wh, wl, in_b, ln1g, ln1b,
                                            b2, b3, b4, b1, N);

    dim3 ag(B, 4);
    attn_mma_kernel<<<ag, 256, attn_smem>>>(b2, b3, b4, b0, lengths);

    tail_kernel<<<gblocks, 1024, tail_smem>>>(b0, b1, wh + 3 * WPC, wl + 3 * WPC,
                                              out_b, fb1, fb2, ln2g, ln2b,
                                              batch_ids, lengths, outp, N);
}